// round 1
// baseline (speedup 1.0000x reference)
#include <cuda_runtime.h>

// Problem constants
#define SEQ   4096
#define HID   2048
#define NH    16
#define NKV   8
#define HD    128
#define QDIM  (NH*HD)    // 2048
#define KVDIM (NKV*HD)   // 1024

// Scratch (static device allocations are allowed)
__device__ float g_q[SEQ * QDIM];     // projected Q, then normed+roped in place
__device__ float g_k[SEQ * KVDIM];    // projected K, then normed+roped in place
__device__ float g_v[SEQ * KVDIM];    // projected V
__device__ float g_attn[SEQ * QDIM];  // attention output, [s, h*D+d]

// ---------------------------------------------------------------------------
// SGEMM: C[M,N] = A[M,K] * B[N,K]^T   (both A and B row-major, K contiguous)
// 128x128 block tile, BK=8, 256 threads, 8x8 per-thread micro-tile.
// All dims are multiples of 128 / 8 in this problem -> no bounds checks.
// ---------------------------------------------------------------------------
__global__ __launch_bounds__(256, 2)
void gemm_nt(float* __restrict__ C, const float* __restrict__ A,
             const float* __restrict__ B, int M, int N, int K)
{
    __shared__ float As[8 * 128];   // transposed: As[k][m]
    __shared__ float Bs[8 * 128];   // transposed: Bs[k][n]

    const int tid  = threadIdx.x;
    const int bm   = blockIdx.y * 128;
    const int bn   = blockIdx.x * 128;
    const int trow = tid >> 4;      // 0..15
    const int tcol = tid & 15;      // 0..15

    const int lRow = tid >> 1;          // 0..127
    const int lCol = (tid & 1) * 4;     // 0 or 4

    const float* Ag = A + (size_t)(bm + lRow) * K + lCol;
    const float* Bg = B + (size_t)(bn + lRow) * K + lCol;

    float acc[8][8];
#pragma unroll
    for (int i = 0; i < 8; i++)
#pragma unroll
        for (int j = 0; j < 8; j++) acc[i][j] = 0.f;

    for (int k0 = 0; k0 < K; k0 += 8) {
        float4 a = *(const float4*)(Ag + k0);
        float4 b = *(const float4*)(Bg + k0);
        As[(lCol + 0) * 128 + lRow] = a.x;
        As[(lCol + 1) * 128 + lRow] = a.y;
        As[(lCol + 2) * 128 + lRow] = a.z;
        As[(lCol + 3) * 128 + lRow] = a.w;
        Bs[(lCol + 0) * 128 + lRow] = b.x;
        Bs[(lCol + 1) * 128 + lRow] = b.y;
        Bs[(lCol + 2) * 128 + lRow] = b.z;
        Bs[(lCol + 3) * 128 + lRow] = b.w;
        __syncthreads();

#pragma unroll
        for (int kk = 0; kk < 8; kk++) {
            float4 a0 = ((const float4*)As)[kk * 32 + trow * 2];
            float4 a1 = ((const float4*)As)[kk * 32 + trow * 2 + 1];
            float4 b0 = ((const float4*)Bs)[kk * 32 + tcol * 2];
            float4 b1 = ((const float4*)Bs)[kk * 32 + tcol * 2 + 1];
            float av[8] = {a0.x, a0.y, a0.z, a0.w, a1.x, a1.y, a1.z, a1.w};
            float bv[8] = {b0.x, b0.y, b0.z, b0.w, b1.x, b1.y, b1.z, b1.w};
#pragma unroll
            for (int i = 0; i < 8; i++)
#pragma unroll
                for (int j = 0; j < 8; j++)
                    acc[i][j] += av[i] * bv[j];
        }
        __syncthreads();
    }

#pragma unroll
    for (int i = 0; i < 8; i++) {
        float* Cr = C + (size_t)(bm + trow * 8 + i) * N + bn + tcol * 8;
        *(float4*)(Cr)     = make_float4(acc[i][0], acc[i][1], acc[i][2], acc[i][3]);
        *(float4*)(Cr + 4) = make_float4(acc[i][4], acc[i][5], acc[i][6], acc[i][7]);
    }
}

// ---------------------------------------------------------------------------
// In-place per-head RMSNorm + RoPE. grid (SEQ, nheads), block 128.
// x layout: [SEQ, nheads*128]
// ---------------------------------------------------------------------------
__global__ __launch_bounds__(128)
void norm_rope(float* __restrict__ x, const float* __restrict__ cs,
               const float* __restrict__ sn, const float* __restrict__ w,
               int nheads)
{
    const int s = blockIdx.x;
    const int h = blockIdx.y;
    const int d = threadIdx.x;
    const size_t idx = (size_t)s * nheads * HD + (size_t)h * HD + d;

    float v = x[idx];
    float ss = v * v;
#pragma unroll
    for (int o = 16; o; o >>= 1) ss += __shfl_xor_sync(0xffffffffu, ss, o);

    __shared__ float red[4];
    __shared__ float sh[128];
    const int lane = d & 31, wid = d >> 5;
    if (lane == 0) red[wid] = ss;
    __syncthreads();
    float tot = red[0] + red[1] + red[2] + red[3];
    float r = rsqrtf(tot * (1.0f / 128.0f) + 1e-6f);
    float xn = v * r * w[d];
    sh[d] = xn;
    __syncthreads();
    float partner = sh[d ^ 64];
    float c  = cs[s * HD + d];
    float si = sn[s * HD + d];
    float out = xn * c + (d < 64 ? -partner : partner) * si;
    x[idx] = out;
}

// ---------------------------------------------------------------------------
// Flash attention (fp32, causal, GQA). grid (SEQ/64, NH), 256 threads (16x16).
// Q tile 64x128 (scaled by 1/sqrt(D) at load), K/V tiles 64x128.
// Thread (tr,tc) owns S[4tr..+3][4tc..+3] and O[4tr..+3][8tc..+7].
// Dynamic smem: Qs 32KB (d-major) + Ks 32KB (d-major) + Vs 32KB + Ps 16KB.
// ---------------------------------------------------------------------------
#define PST 64
__global__ __launch_bounds__(256, 2)
void flash_attn()
{
    extern __shared__ float smem[];
    float* Qs = smem;            // [128][64]
    float* Ks = smem + 8192;     // [128][64]
    float* Vs = smem + 16384;    // [64][128]
    float* Ps = smem + 24576;    // [64][64]

    const int tid = threadIdx.x;
    const int qb  = blockIdx.x;
    const int h   = blockIdx.y;
    const int kvh = h >> 1;             // groups = H/KV = 2
    const int tr  = tid >> 4;
    const int tc  = tid & 15;
    const float scale = 0.0883883476483184f;  // 1/sqrt(128)

    // Load Q tile (scaled), transpose to [d][token]
    {
        const float* Qg = g_q + (size_t)(qb * 64) * QDIM + h * HD;
        for (int i = tid; i < 2048; i += 256) {
            int t = i >> 5, d4 = (i & 31) * 4;
            float4 q4 = *(const float4*)(Qg + (size_t)t * QDIM + d4);
            Qs[(d4 + 0) * 64 + t] = q4.x * scale;
            Qs[(d4 + 1) * 64 + t] = q4.y * scale;
            Qs[(d4 + 2) * 64 + t] = q4.z * scale;
            Qs[(d4 + 3) * 64 + t] = q4.w * scale;
        }
    }

    float m[4], l[4], acc[4][8];
#pragma unroll
    for (int i = 0; i < 4; i++) {
        m[i] = -1e30f; l[i] = 0.f;
#pragma unroll
        for (int j = 0; j < 8; j++) acc[i][j] = 0.f;
    }

    for (int jb = 0; jb <= qb; jb++) {
        __syncthreads();   // previous PV done before overwriting Ks/Vs/Ps
        {
            const float* Kg = g_k + (size_t)(jb * 64) * KVDIM + kvh * HD;
            const float* Vg = g_v + (size_t)(jb * 64) * KVDIM + kvh * HD;
            for (int i = tid; i < 2048; i += 256) {
                int t = i >> 5, d4 = (i & 31) * 4;
                float4 k4 = *(const float4*)(Kg + (size_t)t * KVDIM + d4);
                Ks[(d4 + 0) * 64 + t] = k4.x;
                Ks[(d4 + 1) * 64 + t] = k4.y;
                Ks[(d4 + 2) * 64 + t] = k4.z;
                Ks[(d4 + 3) * 64 + t] = k4.w;
                float4 v4 = *(const float4*)(Vg + (size_t)t * KVDIM + d4);
                *(float4*)(Vs + t * 128 + d4) = v4;
            }
        }
        __syncthreads();

        // S = Q K^T  (Q pre-scaled)
        float sv[4][4];
#pragma unroll
        for (int i = 0; i < 4; i++)
#pragma unroll
            for (int j = 0; j < 4; j++) sv[i][j] = 0.f;

#pragma unroll 4
        for (int d = 0; d < 128; d++) {
            float4 qa = ((const float4*)Qs)[d * 16 + tr];
            float4 kb = ((const float4*)Ks)[d * 16 + tc];
            float qv[4] = {qa.x, qa.y, qa.z, qa.w};
            float kv[4] = {kb.x, kb.y, kb.z, kb.w};
#pragma unroll
            for (int i = 0; i < 4; i++)
#pragma unroll
                for (int j = 0; j < 4; j++)
                    sv[i][j] += qv[i] * kv[j];
        }

        if (jb == qb) {
#pragma unroll
            for (int i = 0; i < 4; i++)
#pragma unroll
                for (int j = 0; j < 4; j++)
                    if (4 * tc + j > 4 * tr + i) sv[i][j] = -1e30f;
        }

        // online softmax
#pragma unroll
        for (int i = 0; i < 4; i++) {
            float mx = fmaxf(fmaxf(sv[i][0], sv[i][1]), fmaxf(sv[i][2], sv[i][3]));
#pragma unroll
            for (int o = 1; o < 16; o <<= 1)
                mx = fmaxf(mx, __shfl_xor_sync(0xffffffffu, mx, o));
            float mn = fmaxf(m[i], mx);
            float cf = __expf(m[i] - mn);
            m[i] = mn;
            float rs = 0.f;
#pragma unroll
            for (int j = 0; j < 4; j++) {
                float p = __expf(sv[i][j] - mn);
                rs += p;
                Ps[(4 * tr + i) * PST + 4 * tc + j] = p;
            }
#pragma unroll
            for (int o = 1; o < 16; o <<= 1)
                rs += __shfl_xor_sync(0xffffffffu, rs, o);
            l[i] = l[i] * cf + rs;
#pragma unroll
            for (int j = 0; j < 8; j++) acc[i][j] *= cf;
        }
        __syncthreads();

        // O += P V
#pragma unroll 2
        for (int c = 0; c < 64; c++) {
            float4 v0 = ((const float4*)Vs)[c * 32 + tc * 2];
            float4 v1 = ((const float4*)Vs)[c * 32 + tc * 2 + 1];
#pragma unroll
            for (int i = 0; i < 4; i++) {
                float p = Ps[(4 * tr + i) * PST + c];
                acc[i][0] += p * v0.x;
                acc[i][1] += p * v0.y;
                acc[i][2] += p * v0.z;
                acc[i][3] += p * v0.w;
                acc[i][4] += p * v1.x;
                acc[i][5] += p * v1.y;
                acc[i][6] += p * v1.z;
                acc[i][7] += p * v1.w;
            }
        }
    }

    // epilogue: O /= l, write [s, h*D+d]
#pragma unroll
    for (int i = 0; i < 4; i++) {
        float inv = 1.0f / l[i];
        float* Orow = g_attn + (size_t)(qb * 64 + 4 * tr + i) * QDIM + h * HD + tc * 8;
        *(float4*)(Orow)     = make_float4(acc[i][0] * inv, acc[i][1] * inv,
                                           acc[i][2] * inv, acc[i][3] * inv);
        *(float4*)(Orow + 4) = make_float4(acc[i][4] * inv, acc[i][5] * inv,
                                           acc[i][6] * inv, acc[i][7] * inv);
    }
}

// ---------------------------------------------------------------------------
extern "C" void kernel_launch(void* const* d_in, const int* in_sizes, int n_in,
                              void* d_out, int out_size)
{
    const float* hid  = (const float*)d_in[0];
    const float* cosp = (const float*)d_in[1];
    const float* sinp = (const float*)d_in[2];
    const float* wq   = (const float*)d_in[3];
    const float* wk   = (const float*)d_in[4];
    const float* wv   = (const float*)d_in[5];
    const float* wo   = (const float*)d_in[6];
    const float* qw   = (const float*)d_in[7];
    const float* kw   = (const float*)d_in[8];
    float* out = (float*)d_out;

    float *qb, *kb, *vb, *ab;
    cudaGetSymbolAddress((void**)&qb, g_q);
    cudaGetSymbolAddress((void**)&kb, g_k);
    cudaGetSymbolAddress((void**)&vb, g_v);
    cudaGetSymbolAddress((void**)&ab, g_attn);

    const int FLASH_SMEM = 28672 * 4;  // 114688 B
    cudaFuncSetAttribute(flash_attn, cudaFuncAttributeMaxDynamicSharedMemorySize,
                         FLASH_SMEM);

    // QKV projections
    gemm_nt<<<dim3(QDIM / 128, SEQ / 128), 256>>>(qb, hid, wq, SEQ, QDIM, HID);
    gemm_nt<<<dim3(KVDIM / 128, SEQ / 128), 256>>>(kb, hid, wk, SEQ, KVDIM, HID);
    gemm_nt<<<dim3(KVDIM / 128, SEQ / 128), 256>>>(vb, hid, wv, SEQ, KVDIM, HID);

    // per-head RMSNorm + RoPE (in place)
    norm_rope<<<dim3(SEQ, NH), 128>>>(qb, cosp, sinp, qw, NH);
    norm_rope<<<dim3(SEQ, NKV), 128>>>(kb, cosp, sinp, kw, NKV);

    // causal GQA flash attention
    flash_attn<<<dim3(SEQ / 64, NH), 256, FLASH_SMEM>>>();

    // output projection
    gemm_nt<<<dim3(HID / 128, SEQ / 128), 256>>>(out, ab, wo, SEQ, HID, QDIM);
}

// round 2
// speedup vs baseline: 3.7177x; 3.7177x over previous
#include <cuda_runtime.h>

#define SEQ   4096
#define HID   2048
#define NH    16
#define NKV   8
#define HD    128
#define QDIM  (NH*HD)    // 2048
#define KVDIM (NKV*HD)   // 1024

__device__ float g_q[SEQ * QDIM];
__device__ float g_k[SEQ * KVDIM];
__device__ float g_v[SEQ * KVDIM];
__device__ float g_attn[SEQ * QDIM];

__device__ __forceinline__ unsigned f2tf32(float x) {
    unsigned u; asm("cvt.rna.tf32.f32 %0, %1;" : "=r"(u) : "f"(x)); return u;
}

__device__ __forceinline__ void mma_tf32(float* d,
    unsigned a0, unsigned a1, unsigned a2, unsigned a3,
    unsigned b0, unsigned b1)
{
    asm volatile(
        "mma.sync.aligned.m16n8k8.row.col.f32.tf32.tf32.f32 "
        "{%0,%1,%2,%3}, {%4,%5,%6,%7}, {%8,%9}, {%0,%1,%2,%3};\n"
        : "+f"(d[0]), "+f"(d[1]), "+f"(d[2]), "+f"(d[3])
        : "r"(a0), "r"(a1), "r"(a2), "r"(a3), "r"(b0), "r"(b1));
}

// ---------------------------------------------------------------------------
// tf32 tensor-core SGEMM: C[M,N] = A[M,K] * B[N,K]^T  (fp32 in/out)
// 128x128 block tile, BK=32, 256 threads = 8 warps (2x4), warp tile 64x32.
// Double-buffered smem, XOR swizzle k^(4*(row&7)) -> conflict-free LDS/STS.
// ---------------------------------------------------------------------------
__global__ __launch_bounds__(256)
void gemm_tf32(float* __restrict__ C, const float* __restrict__ A,
               const float* __restrict__ B, int M, int N, int K)
{
    extern __shared__ unsigned smg[];
    unsigned* As = smg;           // [2][128*32]
    unsigned* Bs = smg + 8192;    // [2][128*32]

    const int tid  = threadIdx.x, lane = tid & 31;
    const int warp = tid >> 5, wm = warp >> 2, wn = warp & 3;
    const int bm = blockIdx.y * 128, bn = blockIdx.x * 128;
    const int lr = tid >> 3;            // 0..31
    const int lk = (tid & 7) * 4;       // 0..28

    const float* Ag = A + (size_t)(bm + lr) * K + lk;
    const float* Bg = B + (size_t)(bn + lr) * K + lk;

    float acc[4][4][4];
#pragma unroll
    for (int i = 0; i < 4; i++)
#pragma unroll
        for (int j = 0; j < 4; j++)
#pragma unroll
            for (int r = 0; r < 4; r++) acc[i][j][r] = 0.f;

    float4 av[4], bv[4];
#pragma unroll
    for (int r = 0; r < 4; r++) {
        av[r] = *(const float4*)(Ag + (size_t)r * 32 * K);
        bv[r] = *(const float4*)(Bg + (size_t)r * 32 * K);
    }
#pragma unroll
    for (int r = 0; r < 4; r++) {
        int row = lr + r * 32;
        int off = row * 32 + (lk ^ ((row & 7) * 4));
        *(uint4*)(As + off) = make_uint4(f2tf32(av[r].x), f2tf32(av[r].y),
                                         f2tf32(av[r].z), f2tf32(av[r].w));
        *(uint4*)(Bs + off) = make_uint4(f2tf32(bv[r].x), f2tf32(bv[r].y),
                                         f2tf32(bv[r].z), f2tf32(bv[r].w));
    }

    const int sw  = (lane >> 2) * 4;
    const int mb0 = (wm * 64 + (lane >> 2)) * 32;
    const int nb0 = (wn * 32 + (lane >> 2)) * 32;
    const int nk  = K >> 5;
    int buf = 0;

    for (int kt = 0; kt < nk; kt++) {
        if (kt + 1 < nk) {
            const float* Ag2 = Ag + (kt + 1) * 32;
            const float* Bg2 = Bg + (kt + 1) * 32;
#pragma unroll
            for (int r = 0; r < 4; r++) {
                av[r] = *(const float4*)(Ag2 + (size_t)r * 32 * K);
                bv[r] = *(const float4*)(Bg2 + (size_t)r * 32 * K);
            }
        }
        __syncthreads();
        const unsigned* as = As + buf * 4096;
        const unsigned* bs = Bs + buf * 4096;
#pragma unroll
        for (int kk = 0; kk < 4; kk++) {
            int k0 = kk * 8 + (lane & 3);
            int ka = k0 ^ sw, kb = (k0 + 4) ^ sw;
            unsigned af[4][4];
#pragma unroll
            for (int mi = 0; mi < 4; mi++) {
                int mb = mb0 + mi * 16 * 32;
                af[mi][0] = as[mb + ka];       af[mi][1] = as[mb + 256 + ka];
                af[mi][2] = as[mb + kb];       af[mi][3] = as[mb + 256 + kb];
            }
#pragma unroll
            for (int ni = 0; ni < 4; ni++) {
                int nb = nb0 + ni * 8 * 32;
                unsigned b0 = bs[nb + ka], b1 = bs[nb + kb];
#pragma unroll
                for (int mi = 0; mi < 4; mi++)
                    mma_tf32(acc[mi][ni], af[mi][0], af[mi][1], af[mi][2], af[mi][3], b0, b1);
            }
        }
        if (kt + 1 < nk) {
            unsigned* ad = As + (buf ^ 1) * 4096;
            unsigned* bd = Bs + (buf ^ 1) * 4096;
#pragma unroll
            for (int r = 0; r < 4; r++) {
                int row = lr + r * 32;
                int off = row * 32 + (lk ^ ((row & 7) * 4));
                *(uint4*)(ad + off) = make_uint4(f2tf32(av[r].x), f2tf32(av[r].y),
                                                 f2tf32(av[r].z), f2tf32(av[r].w));
                *(uint4*)(bd + off) = make_uint4(f2tf32(bv[r].x), f2tf32(bv[r].y),
                                                 f2tf32(bv[r].z), f2tf32(bv[r].w));
            }
        }
        buf ^= 1;
    }

#pragma unroll
    for (int mi = 0; mi < 4; mi++) {
        int row = bm + wm * 64 + mi * 16 + (lane >> 2);
#pragma unroll
        for (int ni = 0; ni < 4; ni++) {
            int col = bn + wn * 32 + ni * 8 + (lane & 3) * 2;
            *(float2*)(C + (size_t)row * N + col)       = make_float2(acc[mi][ni][0], acc[mi][ni][1]);
            *(float2*)(C + (size_t)(row + 8) * N + col) = make_float2(acc[mi][ni][2], acc[mi][ni][3]);
        }
    }
}

// ---------------------------------------------------------------------------
// In-place per-head RMSNorm + RoPE, folds in `scale`, writes tf32-rounded bits.
// grid (SEQ, nheads), block 128.
// ---------------------------------------------------------------------------
__global__ __launch_bounds__(128)
void norm_rope(float* __restrict__ x, const float* __restrict__ cs,
               const float* __restrict__ sn, const float* __restrict__ w,
               int nheads, float scale)
{
    const int s = blockIdx.x;
    const int h = blockIdx.y;
    const int d = threadIdx.x;
    const size_t idx = (size_t)s * nheads * HD + (size_t)h * HD + d;

    float v = x[idx];
    float ss = v * v;
#pragma unroll
    for (int o = 16; o; o >>= 1) ss += __shfl_xor_sync(0xffffffffu, ss, o);

    __shared__ float red[4];
    __shared__ float sh[128];
    const int lane = d & 31, wid = d >> 5;
    if (lane == 0) red[wid] = ss;
    __syncthreads();
    float tot = red[0] + red[1] + red[2] + red[3];
    float r = rsqrtf(tot * (1.0f / 128.0f) + 1e-6f);
    float xn = v * r * w[d];
    sh[d] = xn;
    __syncthreads();
    float partner = sh[d ^ 64];
    float c  = cs[s * HD + d];
    float si = sn[s * HD + d];
    float out = (xn * c + (d < 64 ? -partner : partner) * si) * scale;
    x[idx] = __uint_as_float(f2tf32(out));
}

// in-place fp32 -> tf32 rounding (for V)
__global__ __launch_bounds__(256)
void cvt_tf32(float* __restrict__ x, int n4)
{
    int i = blockIdx.x * 256 + threadIdx.x;
    if (i < n4) {
        float4 v = ((const float4*)x)[i];
        ((uint4*)x)[i] = make_uint4(f2tf32(v.x), f2tf32(v.y), f2tf32(v.z), f2tf32(v.w));
    }
}

// ---------------------------------------------------------------------------
// tf32 tensor-core flash attention (causal, GQA). grid (SEQ/64, NH),
// 128 threads = 4 warps; warp owns 16 query rows. P kept in registers,
// C-frag -> A-frag via quad shuffles. smem: Q/K/V tiles 32KB each (96KB).
// ---------------------------------------------------------------------------
__global__ __launch_bounds__(128)
void flash_tf32()
{
    extern __shared__ unsigned smf[];
    unsigned* Qs = smf;           // [64][128] swizzled d^(4*(t&7))
    unsigned* Ks = smf + 8192;    // [64][128] swizzled d^(4*(t&7))
    unsigned* Vs = smf + 16384;   // [64][128] swizzled d^(8*(t&3))

    const int tid = threadIdx.x, lane = tid & 31, warp = tid >> 5;
    const int qb = blockIdx.x, h = blockIdx.y, kvh = h >> 1;
    const int q2 = lane & 3, u = lane >> 2;

    const unsigned* Qg = (const unsigned*)g_q + (size_t)(qb * 64) * QDIM + h * HD;
#pragma unroll
    for (int i = 0; i < 16; i++) {
        int t4 = tid + i * 128;
        int row = t4 >> 5, d0 = (t4 & 31) * 4;
        *(uint4*)(Qs + row * 128 + (d0 ^ ((row & 7) * 4))) =
            *(const uint4*)(Qg + (size_t)row * QDIM + d0);
    }

    float o[16][4];
#pragma unroll
    for (int i = 0; i < 16; i++)
#pragma unroll
        for (int r = 0; r < 4; r++) o[i][r] = 0.f;
    float m0 = -1e30f, m1 = -1e30f, l0 = 0.f, l1 = 0.f;

    const int sw = u * 4;
    const int mb = (warp * 16 + u) * 128;
    const int srcA = (lane & ~3) | (q2 >> 1);
    const int srcB = srcA | 2;
    const bool od = q2 & 1;

    for (int jb = 0; jb <= qb; jb++) {
        __syncthreads();
        const unsigned* Kg = (const unsigned*)g_k + (size_t)(jb * 64) * KVDIM + kvh * HD;
        const unsigned* Vg = (const unsigned*)g_v + (size_t)(jb * 64) * KVDIM + kvh * HD;
#pragma unroll
        for (int i = 0; i < 16; i++) {
            int t4 = tid + i * 128;
            int row = t4 >> 5, d0 = (t4 & 31) * 4;
            *(uint4*)(Ks + row * 128 + (d0 ^ ((row & 7) * 4))) =
                *(const uint4*)(Kg + (size_t)row * KVDIM + d0);
            *(uint4*)(Vs + row * 128 + (d0 ^ ((row & 3) * 8))) =
                *(const uint4*)(Vg + (size_t)row * KVDIM + d0);
        }
        __syncthreads();

        // S = Q K^T
        float s[8][4];
#pragma unroll
        for (int nt = 0; nt < 8; nt++)
#pragma unroll
            for (int r = 0; r < 4; r++) s[nt][r] = 0.f;

#pragma unroll
        for (int kk = 0; kk < 16; kk++) {
            int k0 = kk * 8 + q2;
            int ka = k0 ^ sw, kb = (k0 + 4) ^ sw;
            unsigned a0 = Qs[mb + ka],        a1 = Qs[mb + 1024 + ka];
            unsigned a2 = Qs[mb + kb],        a3 = Qs[mb + 1024 + kb];
#pragma unroll
            for (int nt = 0; nt < 8; nt++) {
                int nb = (nt * 8 + u) * 128;
                mma_tf32(s[nt], a0, a1, a2, a3, Ks[nb + ka], Ks[nb + kb]);
            }
        }

        if (jb == qb) {
            int r0 = warp * 16 + u;
#pragma unroll
            for (int nt = 0; nt < 8; nt++) {
                int c = nt * 8 + q2 * 2;
                if (c     > r0)     s[nt][0] = -1e30f;
                if (c + 1 > r0)     s[nt][1] = -1e30f;
                if (c     > r0 + 8) s[nt][2] = -1e30f;
                if (c + 1 > r0 + 8) s[nt][3] = -1e30f;
            }
        }

        // online softmax
        float mx0 = -1e30f, mx1 = -1e30f;
#pragma unroll
        for (int nt = 0; nt < 8; nt++) {
            mx0 = fmaxf(mx0, fmaxf(s[nt][0], s[nt][1]));
            mx1 = fmaxf(mx1, fmaxf(s[nt][2], s[nt][3]));
        }
        mx0 = fmaxf(mx0, __shfl_xor_sync(0xffffffffu, mx0, 1));
        mx0 = fmaxf(mx0, __shfl_xor_sync(0xffffffffu, mx0, 2));
        mx1 = fmaxf(mx1, __shfl_xor_sync(0xffffffffu, mx1, 1));
        mx1 = fmaxf(mx1, __shfl_xor_sync(0xffffffffu, mx1, 2));
        float mn0 = fmaxf(m0, mx0), mn1 = fmaxf(m1, mx1);
        float cf0 = __expf(m0 - mn0), cf1 = __expf(m1 - mn1);
        m0 = mn0; m1 = mn1;

        float rs0 = 0.f, rs1 = 0.f;
        unsigned p[8][4];
#pragma unroll
        for (int nt = 0; nt < 8; nt++) {
            float p0 = __expf(s[nt][0] - mn0), p1 = __expf(s[nt][1] - mn0);
            float p2 = __expf(s[nt][2] - mn1), p3 = __expf(s[nt][3] - mn1);
            rs0 += p0 + p1; rs1 += p2 + p3;
            p[nt][0] = f2tf32(p0); p[nt][1] = f2tf32(p1);
            p[nt][2] = f2tf32(p2); p[nt][3] = f2tf32(p3);
        }
        rs0 += __shfl_xor_sync(0xffffffffu, rs0, 1);
        rs0 += __shfl_xor_sync(0xffffffffu, rs0, 2);
        rs1 += __shfl_xor_sync(0xffffffffu, rs1, 1);
        rs1 += __shfl_xor_sync(0xffffffffu, rs1, 2);
        l0 = l0 * cf0 + rs0;
        l1 = l1 * cf1 + rs1;
#pragma unroll
        for (int nt2 = 0; nt2 < 16; nt2++) {
            o[nt2][0] *= cf0; o[nt2][1] *= cf0;
            o[nt2][2] *= cf1; o[nt2][3] *= cf1;
        }

        // C-frag -> A-frag conversion of P (quad shuffles)
#pragma unroll
        for (int kt = 0; kt < 8; kt++) {
            unsigned x0 = __shfl_sync(0xffffffffu, p[kt][0], srcA);
            unsigned x1 = __shfl_sync(0xffffffffu, p[kt][1], srcA);
            unsigned y0 = __shfl_sync(0xffffffffu, p[kt][0], srcB);
            unsigned y1 = __shfl_sync(0xffffffffu, p[kt][1], srcB);
            unsigned z0 = __shfl_sync(0xffffffffu, p[kt][2], srcA);
            unsigned z1 = __shfl_sync(0xffffffffu, p[kt][3], srcA);
            unsigned w0 = __shfl_sync(0xffffffffu, p[kt][2], srcB);
            unsigned w1 = __shfl_sync(0xffffffffu, p[kt][3], srcB);
            p[kt][0] = od ? x1 : x0;   // a0: [row][k]
            p[kt][1] = od ? z1 : z0;   // a1: [row+8][k]
            p[kt][2] = od ? y1 : y0;   // a2: [row][k+4]
            p[kt][3] = od ? w1 : w0;   // a3: [row+8][k+4]
        }

        // O += P V
#pragma unroll
        for (int kt = 0; kt < 8; kt++) {
            int vb0 = (kt * 8 + q2) * 128;
            int vb1 = vb0 + 512;
            int swv = q2 * 8;
#pragma unroll
            for (int nt2 = 0; nt2 < 16; nt2++) {
                int pd = (nt2 * 8 + u) ^ swv;
                mma_tf32(o[nt2], p[kt][0], p[kt][1], p[kt][2], p[kt][3],
                         Vs[vb0 + pd], Vs[vb1 + pd]);
            }
        }
    }

    float r0i = 1.f / l0, r1i = 1.f / l1;
    int grow = qb * 64 + warp * 16 + u;
#pragma unroll
    for (int nt2 = 0; nt2 < 16; nt2++) {
        int col = h * HD + nt2 * 8 + q2 * 2;
        *(float2*)(g_attn + (size_t)grow * QDIM + col) =
            make_float2(o[nt2][0] * r0i, o[nt2][1] * r0i);
        *(float2*)(g_attn + (size_t)(grow + 8) * QDIM + col) =
            make_float2(o[nt2][2] * r1i, o[nt2][3] * r1i);
    }
}

// ---------------------------------------------------------------------------
extern "C" void kernel_launch(void* const* d_in, const int* in_sizes, int n_in,
                              void* d_out, int out_size)
{
    const float* hid  = (const float*)d_in[0];
    const float* cosp = (const float*)d_in[1];
    const float* sinp = (const float*)d_in[2];
    const float* wq   = (const float*)d_in[3];
    const float* wk   = (const float*)d_in[4];
    const float* wv   = (const float*)d_in[5];
    const float* wo   = (const float*)d_in[6];
    const float* qw   = (const float*)d_in[7];
    const float* kw   = (const float*)d_in[8];
    float* out = (float*)d_out;

    float *qb, *kb, *vb, *ab;
    cudaGetSymbolAddress((void**)&qb, g_q);
    cudaGetSymbolAddress((void**)&kb, g_k);
    cudaGetSymbolAddress((void**)&vb, g_v);
    cudaGetSymbolAddress((void**)&ab, g_attn);

    const int GEMM_SMEM  = 16384 * 4;   // 64KB
    const int FLASH_SMEM = 24576 * 4;   // 96KB
    cudaFuncSetAttribute(gemm_tf32, cudaFuncAttributeMaxDynamicSharedMemorySize, GEMM_SMEM);
    cudaFuncSetAttribute(flash_tf32, cudaFuncAttributeMaxDynamicSharedMemorySize, FLASH_SMEM);

    // QKV projections (fp32 in, fp32 out, tf32 tensor-core math)
    gemm_tf32<<<dim3(QDIM / 128, SEQ / 128), 256, GEMM_SMEM>>>(qb, hid, wq, SEQ, QDIM, HID);
    gemm_tf32<<<dim3(KVDIM / 128, SEQ / 128), 256, GEMM_SMEM>>>(kb, hid, wk, SEQ, KVDIM, HID);
    gemm_tf32<<<dim3(KVDIM / 128, SEQ / 128), 256, GEMM_SMEM>>>(vb, hid, wv, SEQ, KVDIM, HID);

    // RMSNorm + RoPE (+scale for Q), outputs tf32-rounded bits in place
    norm_rope<<<dim3(SEQ, NH), 128>>>(qb, cosp, sinp, qw, NH, 0.08838834764831845f);
    norm_rope<<<dim3(SEQ, NKV), 128>>>(kb, cosp, sinp, kw, NKV, 1.0f);
    cvt_tf32<<<(SEQ * KVDIM / 4 + 255) / 256, 256>>>(vb, SEQ * KVDIM / 4);

    // causal GQA flash attention (tensor core)
    flash_tf32<<<dim3(SEQ / 64, NH), 128, FLASH_SMEM>>>();

    // output projection
    gemm_tf32<<<dim3(HID / 128, SEQ / 128), 256, GEMM_SMEM>>>(out, ab, wo, SEQ, HID, QDIM);
}

// round 5
// speedup vs baseline: 4.7283x; 1.2718x over previous
#include <cuda_runtime.h>
#include <cstdint>

#define SEQ   4096
#define HID   2048
#define NH    16
#define NKV   8
#define HD    128
#define QDIM  (NH*HD)    // 2048
#define KVDIM (NKV*HD)   // 1024
#define KDIM  2048       // K for every GEMM here
#define KC    (KDIM/64)  // 32 k-chunks of 64

// fp32 intermediates
__device__ float g_q[SEQ * QDIM];
__device__ float g_k[SEQ * KVDIM];
__device__ float g_v[SEQ * KVDIM];
__device__ float g_attn[SEQ * QDIM];

// int8 2-term packed operands (tile-packed + swizzled) + per-row scales
// tile = 128 rows x 64 k, row = 128B: [8 granules of 16B, g0..3 = q1, g4..7 = q2],
// granule position swizzled: pos = (g ^ (row&7)).
__device__ uint8_t g_pa[(size_t)SEQ * KDIM * 2];
__device__ uint8_t g_pwq[(size_t)QDIM * KDIM * 2];
__device__ uint8_t g_pwk[(size_t)KVDIM * KDIM * 2];
__device__ uint8_t g_pwv[(size_t)KVDIM * KDIM * 2];
__device__ uint8_t g_pwo[(size_t)HID * KDIM * 2];
__device__ float g_sa[SEQ];
__device__ float g_swq[QDIM], g_swk[KVDIM], g_swv[KVDIM], g_swo[HID];

__device__ __forceinline__ unsigned f2tf32(float x) {
    unsigned u; asm("cvt.rna.tf32.f32 %0, %1;" : "=r"(u) : "f"(x)); return u;
}
__device__ __forceinline__ void mma_tf32(float* d,
    unsigned a0, unsigned a1, unsigned a2, unsigned a3, unsigned b0, unsigned b1)
{
    asm volatile(
        "mma.sync.aligned.m16n8k8.row.col.f32.tf32.tf32.f32 "
        "{%0,%1,%2,%3}, {%4,%5,%6,%7}, {%8,%9}, {%0,%1,%2,%3};\n"
        : "+f"(d[0]), "+f"(d[1]), "+f"(d[2]), "+f"(d[3])
        : "r"(a0), "r"(a1), "r"(a2), "r"(a3), "r"(b0), "r"(b1));
}
__device__ __forceinline__ void mma_i8(int* d,
    const uint32_t* a, uint32_t b0, uint32_t b1)
{
    asm volatile(
        "mma.sync.aligned.m16n8k32.row.col.s32.s8.s8.s32 "
        "{%0,%1,%2,%3}, {%4,%5,%6,%7}, {%8,%9}, {%0,%1,%2,%3};\n"
        : "+r"(d[0]), "+r"(d[1]), "+r"(d[2]), "+r"(d[3])
        : "r"(a[0]), "r"(a[1]), "r"(a[2]), "r"(a[3]), "r"(b0), "r"(b1));
}
__device__ __forceinline__ void ldsm4(uint32_t* r, uint32_t addr) {
    asm volatile("ldmatrix.sync.aligned.m8n8.x4.shared.b16 {%0,%1,%2,%3}, [%4];"
                 : "=r"(r[0]), "=r"(r[1]), "=r"(r[2]), "=r"(r[3]) : "r"(addr));
}
__device__ __forceinline__ uint32_t smem_u32(const void* p) {
    uint32_t a;
    asm("{ .reg .u64 t; cvta.to.shared.u64 t, %1; cvt.u32.u64 %0, t; }" : "=r"(a) : "l"(p));
    return a;
}
__device__ __forceinline__ void cp16(uint32_t d, const void* g) {
    asm volatile("cp.async.cg.shared.global [%0], [%1], 16;" :: "r"(d), "l"(g));
}
#define CP_COMMIT() asm volatile("cp.async.commit_group;")
#define CP_WAIT1()  asm volatile("cp.async.wait_group 1;")

// ===========================================================================
// pack_quant: fp32 [rows, 2048] -> per-row 2-term int8, tile-packed+swizzled.
// One warp per row; block = 8 rows.
// x ~= q1*s1 + q2*(s1/128), |q2| <= 64, recon err <= s1/256.
// ===========================================================================
__global__ __launch_bounds__(256)
void pack_quant(const float* __restrict__ src, uint8_t* __restrict__ dst,
                float* __restrict__ scl)
{
    const int warp = threadIdx.x >> 5, lane = threadIdx.x & 31;
    const int row = blockIdx.x * 8 + warp;
    const float* s = src + (size_t)row * KDIM;

    float4 v[16];
    float mx = 0.f;
#pragma unroll
    for (int j = 0; j < 16; j++) {
        v[j] = *(const float4*)(s + lane * 4 + j * 128);
        mx = fmaxf(mx, fmaxf(fmaxf(fabsf(v[j].x), fabsf(v[j].y)),
                             fmaxf(fabsf(v[j].z), fabsf(v[j].w))));
    }
#pragma unroll
    for (int o = 16; o; o >>= 1) mx = fmaxf(mx, __shfl_xor_sync(0xffffffffu, mx, o));

    const float s1   = mx * (1.f / 127.f);
    const float inv1 = mx > 0.f ? 127.f / mx : 0.f;
    const float inv2 = inv1 * 128.f;
    if (lane == 0) scl[row] = s1;

    const int rt = row >> 7, rr = row & 127, sw = rr & 7;
    uint8_t* tbase0 = dst + ((size_t)rt * KC) * 16384 + rr * 128;

#pragma unroll
    for (int j = 0; j < 16; j++) {
        int k = lane * 4 + j * 128;
        int c = k >> 6, w16 = (k >> 4) & 3, bin = k & 15;
        float4 x = v[j];
        int q0 = __float2int_rn(x.x * inv1), q1 = __float2int_rn(x.y * inv1);
        int q2 = __float2int_rn(x.z * inv1), q3 = __float2int_rn(x.w * inv1);
        int r0 = __float2int_rn((x.x - q0 * s1) * inv2);
        int r1 = __float2int_rn((x.y - q1 * s1) * inv2);
        int r2 = __float2int_rn((x.z - q2 * s1) * inv2);
        int r3 = __float2int_rn((x.w - q3 * s1) * inv2);
        uint8_t* tb = tbase0 + c * 16384;
        *(char4*)(tb + (((w16     ^ sw) << 4) + bin)) =
            make_char4((char)q0, (char)q1, (char)q2, (char)q3);
        *(char4*)(tb + ((((w16+4) ^ sw) << 4) + bin)) =
            make_char4((char)r0, (char)r1, (char)r2, (char)r3);
    }
}

// ===========================================================================
// gemm_i8: C[M,N] = A[M,K]*B[N,K]^T via 3-term int8 mma (q1q1, q1q2, q2q1).
// 128x128 block tile, k-chunk 64, cp.async double buffer (64KB smem),
// 256 thr = 8 warps (2x4), warp tile 64x32, ldmatrix.x4 fragments.
// C = sA[row]*sB[col]*(acc1 + acc2/128).
// ===========================================================================
__global__ __launch_bounds__(256)
void gemm_i8(const uint8_t* __restrict__ Ap, const uint8_t* __restrict__ Bp,
             const float* __restrict__ sA, const float* __restrict__ sB,
             float* __restrict__ C, int N)
{
    extern __shared__ uint8_t smi[];   // [2][A 16KB | B 16KB]
    const uint32_t sb0 = smem_u32(smi);
    const int tid = threadIdx.x, lane = tid & 31, warp = tid >> 5;
    const int wm = warp >> 2, wn = warp & 3;
    const int bn = blockIdx.x, bm = blockIdx.y;

    const uint8_t* Asrc = Ap + (size_t)bm * KC * 16384 + tid * 16;
    const uint8_t* Bsrc = Bp + (size_t)bn * KC * 16384 + tid * 16;

    int acc1[4][4][4] = {}, acc2[4][4][4] = {};

    // ldmatrix lane addressing (row&7 invariant across mi/nj since steps are 16)
    const int arow = wm * 64 + (lane & 7) + ((lane >> 3) & 1) * 8;  // + mi*16
    const int akh  = lane >> 4;
    const int aw   = arow & 7;
    const int brow = wn * 32 + (lane & 7) + (lane >> 4) * 8;        // + nj*16
    const int bkh  = (lane >> 3) & 1;
    const int bw   = brow & 7;

#pragma unroll
    for (int pre = 0; pre < 2; pre++) {
        uint32_t d = sb0 + pre * 32768 + tid * 16;
#pragma unroll
        for (int i = 0; i < 4; i++) cp16(d + i * 4096,         Asrc + (size_t)pre * 16384 + i * 4096);
#pragma unroll
        for (int i = 0; i < 4; i++) cp16(d + 16384 + i * 4096, Bsrc + (size_t)pre * 16384 + i * 4096);
        CP_COMMIT();
    }

    for (int kc = 0; kc < KC; kc++) {
        CP_WAIT1();
        __syncthreads();
        const uint32_t stA = sb0 + (kc & 1) * 32768, stB = stA + 16384;

#pragma unroll
        for (int s = 0; s < 2; s++) {
            uint32_t a1f[4][4], a2f[4][4];
            const int ga = 2 * s + akh;
#pragma unroll
            for (int mi = 0; mi < 4; mi++) {
                uint32_t ad = stA + (uint32_t)(arow + mi * 16) * 128;
                ldsm4(a1f[mi], ad + (uint32_t)(((ga     ^ aw) << 4)));
                ldsm4(a2f[mi], ad + (uint32_t)((((ga+4) ^ aw) << 4)));
            }
            const int gb = 2 * s + bkh;
#pragma unroll
            for (int nj = 0; nj < 2; nj++) {
                uint32_t bd = stB + (uint32_t)(brow + nj * 16) * 128;
                uint32_t b1f[4], b2f[4];
                ldsm4(b1f, bd + (uint32_t)(((gb     ^ bw) << 4)));
                ldsm4(b2f, bd + (uint32_t)((((gb+4) ^ bw) << 4)));
#pragma unroll
                for (int mi = 0; mi < 4; mi++) {
                    mma_i8(acc1[mi][2*nj],   a1f[mi], b1f[0], b1f[1]);
                    mma_i8(acc1[mi][2*nj+1], a1f[mi], b1f[2], b1f[3]);
                    mma_i8(acc2[mi][2*nj],   a1f[mi], b2f[0], b2f[1]);
                    mma_i8(acc2[mi][2*nj+1], a1f[mi], b2f[2], b2f[3]);
                    mma_i8(acc2[mi][2*nj],   a2f[mi], b1f[0], b1f[1]);
                    mma_i8(acc2[mi][2*nj+1], a2f[mi], b1f[2], b1f[3]);
                }
            }
        }
        __syncthreads();
        if (kc + 2 < KC) {
            uint32_t d = sb0 + (kc & 1) * 32768 + tid * 16;
#pragma unroll
            for (int i = 0; i < 4; i++) cp16(d + i * 4096,         Asrc + (size_t)(kc + 2) * 16384 + i * 4096);
#pragma unroll
            for (int i = 0; i < 4; i++) cp16(d + 16384 + i * 4096, Bsrc + (size_t)(kc + 2) * 16384 + i * 4096);
        }
        CP_COMMIT();
    }

    const int u = lane >> 2, qq = (lane & 3) * 2;
    const float k2 = 0.0078125f;   // 1/128
#pragma unroll
    for (int mi = 0; mi < 4; mi++) {
        int r0 = bm * 128 + wm * 64 + mi * 16 + u;
        float sa0 = sA[r0], sa1 = sA[r0 + 8];
#pragma unroll
        for (int nt = 0; nt < 4; nt++) {
            int c0 = bn * 128 + wn * 32 + nt * 8 + qq;
            float sb0v = sB[c0], sb1v = sB[c0 + 1];
            float d0 = (float)acc1[mi][nt][0] + (float)acc2[mi][nt][0] * k2;
            float d1 = (float)acc1[mi][nt][1] + (float)acc2[mi][nt][1] * k2;
            float d2 = (float)acc1[mi][nt][2] + (float)acc2[mi][nt][2] * k2;
            float d3 = (float)acc1[mi][nt][3] + (float)acc2[mi][nt][3] * k2;
            *(float2*)(C + (size_t)r0 * N + c0)       = make_float2(sa0 * sb0v * d0, sa0 * sb1v * d1);
            *(float2*)(C + (size_t)(r0 + 8) * N + c0) = make_float2(sa1 * sb0v * d2, sa1 * sb1v * d3);
        }
    }
}

// ===========================================================================
// In-place per-head RMSNorm + RoPE (+scale), writes tf32-rounded bits.
// ===========================================================================
__global__ __launch_bounds__(128)
void norm_rope(float* __restrict__ x, const float* __restrict__ cs,
               const float* __restrict__ sn, const float* __restrict__ w,
               int nheads, float scale)
{
    const int s = blockIdx.x, h = blockIdx.y, d = threadIdx.x;
    const size_t idx = (size_t)s * nheads * HD + (size_t)h * HD + d;

    float v = x[idx];
    float ss = v * v;
#pragma unroll
    for (int o = 16; o; o >>= 1) ss += __shfl_xor_sync(0xffffffffu, ss, o);

    __shared__ float red[4];
    __shared__ float sh[128];
    const int lane = d & 31, wid = d >> 5;
    if (lane == 0) red[wid] = ss;
    __syncthreads();
    float tot = red[0] + red[1] + red[2] + red[3];
    float r = rsqrtf(tot * (1.0f / 128.0f) + 1e-6f);
    float xn = v * r * w[d];
    sh[d] = xn;
    __syncthreads();
    float partner = sh[d ^ 64];
    float c  = cs[s * HD + d];
    float si = sn[s * HD + d];
    float out = (xn * c + (d < 64 ? -partner : partner) * si) * scale;
    x[idx] = __uint_as_float(f2tf32(out));
}

__global__ __launch_bounds__(256)
void cvt_tf32(float* __restrict__ x, int n4)
{
    int i = blockIdx.x * 256 + threadIdx.x;
    if (i < n4) {
        float4 v = ((const float4*)x)[i];
        ((uint4*)x)[i] = make_uint4(f2tf32(v.x), f2tf32(v.y), f2tf32(v.z), f2tf32(v.w));
    }
}

// ===========================================================================
// tf32 mma.sync flash attention (causal, GQA) — unchanged from R2 (passing).
// ===========================================================================
__global__ __launch_bounds__(128)
void flash_tf32()
{
    extern __shared__ unsigned smf[];
    unsigned* Qs = smf;
    unsigned* Ks = smf + 8192;
    unsigned* Vs = smf + 16384;

    const int tid = threadIdx.x, lane = tid & 31, warp = tid >> 5;
    const int qb = blockIdx.x, h = blockIdx.y, kvh = h >> 1;
    const int q2 = lane & 3, u = lane >> 2;

    const unsigned* Qg = (const unsigned*)g_q + (size_t)(qb * 64) * QDIM + h * HD;
#pragma unroll
    for (int i = 0; i < 16; i++) {
        int t4 = tid + i * 128;
        int row = t4 >> 5, d0 = (t4 & 31) * 4;
        *(uint4*)(Qs + row * 128 + (d0 ^ ((row & 7) * 4))) =
            *(const uint4*)(Qg + (size_t)row * QDIM + d0);
    }

    float o[16][4];
#pragma unroll
    for (int i = 0; i < 16; i++)
#pragma unroll
        for (int r = 0; r < 4; r++) o[i][r] = 0.f;
    float m0 = -1e30f, m1 = -1e30f, l0 = 0.f, l1 = 0.f;

    const int sw = u * 4;
    const int mb = (warp * 16 + u) * 128;
    const int srcA = (lane & ~3) | (q2 >> 1);
    const int srcB = srcA | 2;
    const bool od = q2 & 1;

    for (int jb = 0; jb <= qb; jb++) {
        __syncthreads();
        const unsigned* Kg = (const unsigned*)g_k + (size_t)(jb * 64) * KVDIM + kvh * HD;
        const unsigned* Vg = (const unsigned*)g_v + (size_t)(jb * 64) * KVDIM + kvh * HD;
#pragma unroll
        for (int i = 0; i < 16; i++) {
            int t4 = tid + i * 128;
            int row = t4 >> 5, d0 = (t4 & 31) * 4;
            *(uint4*)(Ks + row * 128 + (d0 ^ ((row & 7) * 4))) =
                *(const uint4*)(Kg + (size_t)row * KVDIM + d0);
            *(uint4*)(Vs + row * 128 + (d0 ^ ((row & 3) * 8))) =
                *(const uint4*)(Vg + (size_t)row * KVDIM + d0);
        }
        __syncthreads();

        float s[8][4];
#pragma unroll
        for (int nt = 0; nt < 8; nt++)
#pragma unroll
            for (int r = 0; r < 4; r++) s[nt][r] = 0.f;

#pragma unroll
        for (int kk = 0; kk < 16; kk++) {
            int k0 = kk * 8 + q2;
            int ka = k0 ^ sw, kb = (k0 + 4) ^ sw;
            unsigned a0 = Qs[mb + ka], a1 = Qs[mb + 1024 + ka];
            unsigned a2 = Qs[mb + kb], a3 = Qs[mb + 1024 + kb];
#pragma unroll
            for (int nt = 0; nt < 8; nt++) {
                int nb = (nt * 8 + u) * 128;
                mma_tf32(s[nt], a0, a1, a2, a3, Ks[nb + ka], Ks[nb + kb]);
            }
        }

        if (jb == qb) {
            int r0 = warp * 16 + u;
#pragma unroll
            for (int nt = 0; nt < 8; nt++) {
                int c = nt * 8 + q2 * 2;
                if (c     > r0)     s[nt][0] = -1e30f;
                if (c + 1 > r0)     s[nt][1] = -1e30f;
                if (c     > r0 + 8) s[nt][2] = -1e30f;
                if (c + 1 > r0 + 8) s[nt][3] = -1e30f;
            }
        }

        float mx0 = -1e30f, mx1 = -1e30f;
#pragma unroll
        for (int nt = 0; nt < 8; nt++) {
            mx0 = fmaxf(mx0, fmaxf(s[nt][0], s[nt][1]));
            mx1 = fmaxf(mx1, fmaxf(s[nt][2], s[nt][3]));
        }
        mx0 = fmaxf(mx0, __shfl_xor_sync(0xffffffffu, mx0, 1));
        mx0 = fmaxf(mx0, __shfl_xor_sync(0xffffffffu, mx0, 2));
        mx1 = fmaxf(mx1, __shfl_xor_sync(0xffffffffu, mx1, 1));
        mx1 = fmaxf(mx1, __shfl_xor_sync(0xffffffffu, mx1, 2));
        float mn0 = fmaxf(m0, mx0), mn1 = fmaxf(m1, mx1);
        float cf0 = __expf(m0 - mn0), cf1 = __expf(m1 - mn1);
        m0 = mn0; m1 = mn1;

        float rs0 = 0.f, rs1 = 0.f;
        unsigned p[8][4];
#pragma unroll
        for (int nt = 0; nt < 8; nt++) {
            float p0 = __expf(s[nt][0] - mn0), p1 = __expf(s[nt][1] - mn0);
            float p2 = __expf(s[nt][2] - mn1), p3 = __expf(s[nt][3] - mn1);
            rs0 += p0 + p1; rs1 += p2 + p3;
            p[nt][0] = f2tf32(p0); p[nt][1] = f2tf32(p1);
            p[nt][2] = f2tf32(p2); p[nt][3] = f2tf32(p3);
        }
        rs0 += __shfl_xor_sync(0xffffffffu, rs0, 1);
        rs0 += __shfl_xor_sync(0xffffffffu, rs0, 2);
        rs1 += __shfl_xor_sync(0xffffffffu, rs1, 1);
        rs1 += __shfl_xor_sync(0xffffffffu, rs1, 2);
        l0 = l0 * cf0 + rs0;
        l1 = l1 * cf1 + rs1;
#pragma unroll
        for (int nt2 = 0; nt2 < 16; nt2++) {
            o[nt2][0] *= cf0; o[nt2][1] *= cf0;
            o[nt2][2] *= cf1; o[nt2][3] *= cf1;
        }

#pragma unroll
        for (int kt = 0; kt < 8; kt++) {
            unsigned x0 = __shfl_sync(0xffffffffu, p[kt][0], srcA);
            unsigned x1 = __shfl_sync(0xffffffffu, p[kt][1], srcA);
            unsigned y0 = __shfl_sync(0xffffffffu, p[kt][0], srcB);
            unsigned y1 = __shfl_sync(0xffffffffu, p[kt][1], srcB);
            unsigned z0 = __shfl_sync(0xffffffffu, p[kt][2], srcA);
            unsigned z1 = __shfl_sync(0xffffffffu, p[kt][3], srcA);
            unsigned w0 = __shfl_sync(0xffffffffu, p[kt][2], srcB);
            unsigned w1 = __shfl_sync(0xffffffffu, p[kt][3], srcB);
            p[kt][0] = od ? x1 : x0;
            p[kt][1] = od ? z1 : z0;
            p[kt][2] = od ? y1 : y0;
            p[kt][3] = od ? w1 : w0;
        }

#pragma unroll
        for (int kt = 0; kt < 8; kt++) {
            int vb0 = (kt * 8 + q2) * 128;
            int vb1 = vb0 + 512;
            int swv = q2 * 8;
#pragma unroll
            for (int nt2 = 0; nt2 < 16; nt2++) {
                int pd = (nt2 * 8 + u) ^ swv;
                mma_tf32(o[nt2], p[kt][0], p[kt][1], p[kt][2], p[kt][3],
                         Vs[vb0 + pd], Vs[vb1 + pd]);
            }
        }
    }

    float r0i = 1.f / l0, r1i = 1.f / l1;
    int grow = qb * 64 + warp * 16 + u;
#pragma unroll
    for (int nt2 = 0; nt2 < 16; nt2++) {
        int col = h * HD + nt2 * 8 + q2 * 2;
        *(float2*)(g_attn + (size_t)grow * QDIM + col) =
            make_float2(o[nt2][0] * r0i, o[nt2][1] * r0i);
        *(float2*)(g_attn + (size_t)(grow + 8) * QDIM + col) =
            make_float2(o[nt2][2] * r1i, o[nt2][3] * r1i);
    }
}

// ===========================================================================
extern "C" void kernel_launch(void* const* d_in, const int* in_sizes, int n_in,
                              void* d_out, int out_size)
{
    const float* hid  = (const float*)d_in[0];
    const float* cosp = (const float*)d_in[1];
    const float* sinp = (const float*)d_in[2];
    const float* wq   = (const float*)d_in[3];
    const float* wk   = (const float*)d_in[4];
    const float* wv   = (const float*)d_in[5];
    const float* wo   = (const float*)d_in[6];
    const float* qw   = (const float*)d_in[7];
    const float* kw   = (const float*)d_in[8];
    float* out = (float*)d_out;

    float *qb, *kb, *vb, *ab;
    cudaGetSymbolAddress((void**)&qb, g_q);
    cudaGetSymbolAddress((void**)&kb, g_k);
    cudaGetSymbolAddress((void**)&vb, g_v);
    cudaGetSymbolAddress((void**)&ab, g_attn);
    uint8_t *pa, *pwq, *pwk, *pwv, *pwo;
    cudaGetSymbolAddress((void**)&pa,  g_pa);
    cudaGetSymbolAddress((void**)&pwq, g_pwq);
    cudaGetSymbolAddress((void**)&pwk, g_pwk);
    cudaGetSymbolAddress((void**)&pwv, g_pwv);
    cudaGetSymbolAddress((void**)&pwo, g_pwo);
    float *sa, *swq, *swk, *swv, *swo;
    cudaGetSymbolAddress((void**)&sa,  g_sa);
    cudaGetSymbolAddress((void**)&swq, g_swq);
    cudaGetSymbolAddress((void**)&swk, g_swk);
    cudaGetSymbolAddress((void**)&swv, g_swv);
    cudaGetSymbolAddress((void**)&swo, g_swo);

    const int GEMM_SMEM  = 65536;
    const int FLASH_SMEM = 24576 * 4;   // 96KB
    cudaFuncSetAttribute(gemm_i8, cudaFuncAttributeMaxDynamicSharedMemorySize, GEMM_SMEM);
    cudaFuncSetAttribute(flash_tf32, cudaFuncAttributeMaxDynamicSharedMemorySize, FLASH_SMEM);

    // pack activations + weights into 2-term int8 (tile-packed + swizzled)
    pack_quant<<<SEQ / 8, 256>>>(hid, pa, sa);
    pack_quant<<<QDIM / 8, 256>>>(wq, pwq, swq);
    pack_quant<<<KVDIM / 8, 256>>>(wk, pwk, swk);
    pack_quant<<<KVDIM / 8, 256>>>(wv, pwv, swv);
    pack_quant<<<HID / 8, 256>>>(wo, pwo, swo);

    // QKV projections (int8 3-term tensor core)   [launch #6 = ncu capture slot]
    gemm_i8<<<dim3(QDIM / 128, SEQ / 128), 256, GEMM_SMEM>>>(pa, pwq, sa, swq, qb, QDIM);
    gemm_i8<<<dim3(KVDIM / 128, SEQ / 128), 256, GEMM_SMEM>>>(pa, pwk, sa, swk, kb, KVDIM);
    gemm_i8<<<dim3(KVDIM / 128, SEQ / 128), 256, GEMM_SMEM>>>(pa, pwv, sa, swv, vb, KVDIM);

    // RMSNorm + RoPE (+scale for Q), tf32-rounded in place; V -> tf32 bits
    norm_rope<<<dim3(SEQ, NH), 128>>>(qb, cosp, sinp, qw, NH, 0.08838834764831845f);
    norm_rope<<<dim3(SEQ, NKV), 128>>>(kb, cosp, sinp, kw, NKV, 1.0f);
    cvt_tf32<<<(SEQ * KVDIM / 4 + 255) / 256, 256>>>(vb, SEQ * KVDIM / 4);

    // causal GQA flash attention (mma.sync tf32)
    flash_tf32<<<dim3(SEQ / 64, NH), 128, FLASH_SMEM>>>();

    // output projection (reuses activation scratch)
    pack_quant<<<SEQ / 8, 256>>>(ab, pa, sa);
    gemm_i8<<<dim3(HID / 128, SEQ / 128), 256, GEMM_SMEM>>>(pa, pwo, sa, swo, out, HID);
}

// round 6
// speedup vs baseline: 7.5524x; 1.5973x over previous
#include <cuda_runtime.h>
#include <cuda_fp16.h>
#include <cstdint>

#define SEQ   4096
#define HID   2048
#define NH    16
#define NKV   8
#define HD    128
#define QDIM  (NH*HD)    // 2048
#define KVDIM (NKV*HD)   // 1024
#define KDIM  2048
#define KC    (KDIM/64)  // 32

// fp32 intermediates
__device__ float g_q[SEQ * QDIM];
__device__ float g_k[SEQ * KVDIM];
__device__ float g_v[SEQ * KVDIM];
__device__ float g_attn[SEQ * QDIM];

// fp16 flash operands
__device__ __half g_qh[SEQ * QDIM];
__device__ __half g_kh[SEQ * KVDIM];
__device__ __half g_vh[SEQ * KVDIM];

// int8 2-term packed operands + per-row scales
__device__ uint8_t g_pa[(size_t)SEQ * KDIM * 2];
__device__ uint8_t g_pwq[(size_t)QDIM * KDIM * 2];
__device__ uint8_t g_pwk[(size_t)KVDIM * KDIM * 2];
__device__ uint8_t g_pwv[(size_t)KVDIM * KDIM * 2];
__device__ uint8_t g_pwo[(size_t)HID * KDIM * 2];
__device__ float g_sa[SEQ];
__device__ float g_swq[QDIM], g_swk[KVDIM], g_swv[KVDIM], g_swo[HID];

__device__ __forceinline__ void mma_i8(int* d,
    const uint32_t* a, uint32_t b0, uint32_t b1)
{
    asm volatile(
        "mma.sync.aligned.m16n8k32.row.col.s32.s8.s8.s32 "
        "{%0,%1,%2,%3}, {%4,%5,%6,%7}, {%8,%9}, {%0,%1,%2,%3};\n"
        : "+r"(d[0]), "+r"(d[1]), "+r"(d[2]), "+r"(d[3])
        : "r"(a[0]), "r"(a[1]), "r"(a[2]), "r"(a[3]), "r"(b0), "r"(b1));
}
__device__ __forceinline__ void mma_f16(float* d,
    const uint32_t* a, uint32_t b0, uint32_t b1)
{
    asm volatile(
        "mma.sync.aligned.m16n8k16.row.col.f32.f16.f16.f32 "
        "{%0,%1,%2,%3}, {%4,%5,%6,%7}, {%8,%9}, {%0,%1,%2,%3};\n"
        : "+f"(d[0]), "+f"(d[1]), "+f"(d[2]), "+f"(d[3])
        : "r"(a[0]), "r"(a[1]), "r"(a[2]), "r"(a[3]), "r"(b0), "r"(b1));
}
__device__ __forceinline__ void ldsm4(uint32_t* r, uint32_t addr) {
    asm volatile("ldmatrix.sync.aligned.m8n8.x4.shared.b16 {%0,%1,%2,%3}, [%4];"
                 : "=r"(r[0]), "=r"(r[1]), "=r"(r[2]), "=r"(r[3]) : "r"(addr));
}
__device__ __forceinline__ void ldsm4t(uint32_t* r, uint32_t addr) {
    asm volatile("ldmatrix.sync.aligned.m8n8.x4.trans.shared.b16 {%0,%1,%2,%3}, [%4];"
                 : "=r"(r[0]), "=r"(r[1]), "=r"(r[2]), "=r"(r[3]) : "r"(addr));
}
__device__ __forceinline__ uint32_t smem_u32(const void* p) {
    uint32_t a;
    asm("{ .reg .u64 t; cvta.to.shared.u64 t, %1; cvt.u32.u64 %0, t; }" : "=r"(a) : "l"(p));
    return a;
}
__device__ __forceinline__ void cp16(uint32_t d, const void* g) {
    asm volatile("cp.async.cg.shared.global [%0], [%1], 16;" :: "r"(d), "l"(g));
}
#define CP_COMMIT() asm volatile("cp.async.commit_group;")
#define CP_WAIT1()  asm volatile("cp.async.wait_group 1;")
#define CP_WAIT0()  asm volatile("cp.async.wait_group 0;")

__device__ __forceinline__ uint32_t pk2(float lo, float hi) {
    __half2 t = __floats2half2_rn(lo, hi);
    return *(uint32_t*)&t;
}

// ===========================================================================
// pack_quant: fp32 [rows, 2048] -> per-row 2-term int8, tile-packed+swizzled.
// ===========================================================================
__global__ __launch_bounds__(256)
void pack_quant(const float* __restrict__ src, uint8_t* __restrict__ dst,
                float* __restrict__ scl)
{
    const int warp = threadIdx.x >> 5, lane = threadIdx.x & 31;
    const int row = blockIdx.x * 8 + warp;
    const float* s = src + (size_t)row * KDIM;

    float4 v[16];
    float mx = 0.f;
#pragma unroll
    for (int j = 0; j < 16; j++) {
        v[j] = *(const float4*)(s + lane * 4 + j * 128);
        mx = fmaxf(mx, fmaxf(fmaxf(fabsf(v[j].x), fabsf(v[j].y)),
                             fmaxf(fabsf(v[j].z), fabsf(v[j].w))));
    }
#pragma unroll
    for (int o = 16; o; o >>= 1) mx = fmaxf(mx, __shfl_xor_sync(0xffffffffu, mx, o));

    const float s1   = mx * (1.f / 127.f);
    const float inv1 = mx > 0.f ? 127.f / mx : 0.f;
    const float inv2 = inv1 * 128.f;
    if (lane == 0) scl[row] = s1;

    const int rt = row >> 7, rr = row & 127, sw = rr & 7;
    uint8_t* tbase0 = dst + ((size_t)rt * KC) * 16384 + rr * 128;

#pragma unroll
    for (int j = 0; j < 16; j++) {
        int k = lane * 4 + j * 128;
        int c = k >> 6, w16 = (k >> 4) & 3, bin = k & 15;
        float4 x = v[j];
        int q0 = __float2int_rn(x.x * inv1), q1 = __float2int_rn(x.y * inv1);
        int q2 = __float2int_rn(x.z * inv1), q3 = __float2int_rn(x.w * inv1);
        int r0 = __float2int_rn((x.x - q0 * s1) * inv2);
        int r1 = __float2int_rn((x.y - q1 * s1) * inv2);
        int r2 = __float2int_rn((x.z - q2 * s1) * inv2);
        int r3 = __float2int_rn((x.w - q3 * s1) * inv2);
        uint8_t* tb = tbase0 + c * 16384;
        *(char4*)(tb + (((w16     ^ sw) << 4) + bin)) =
            make_char4((char)q0, (char)q1, (char)q2, (char)q3);
        *(char4*)(tb + ((((w16+4) ^ sw) << 4) + bin)) =
            make_char4((char)r0, (char)r1, (char)r2, (char)r3);
    }
}

// ===========================================================================
// gemm_i8 (unchanged from R5, passing): 3-term int8 mma, 128x128 tile.
// ===========================================================================
__global__ __launch_bounds__(256)
void gemm_i8(const uint8_t* __restrict__ Ap, const uint8_t* __restrict__ Bp,
             const float* __restrict__ sA, const float* __restrict__ sB,
             float* __restrict__ C, int N)
{
    extern __shared__ uint8_t smi[];
    const uint32_t sb0 = smem_u32(smi);
    const int tid = threadIdx.x, lane = tid & 31, warp = tid >> 5;
    const int wm = warp >> 2, wn = warp & 3;
    const int bn = blockIdx.x, bm = blockIdx.y;

    const uint8_t* Asrc = Ap + (size_t)bm * KC * 16384 + tid * 16;
    const uint8_t* Bsrc = Bp + (size_t)bn * KC * 16384 + tid * 16;

    int acc1[4][4][4] = {}, acc2[4][4][4] = {};

    const int arow = wm * 64 + (lane & 7) + ((lane >> 3) & 1) * 8;
    const int akh  = lane >> 4;
    const int aw   = arow & 7;
    const int brow = wn * 32 + (lane & 7) + (lane >> 4) * 8;
    const int bkh  = (lane >> 3) & 1;
    const int bw   = brow & 7;

#pragma unroll
    for (int pre = 0; pre < 2; pre++) {
        uint32_t d = sb0 + pre * 32768 + tid * 16;
#pragma unroll
        for (int i = 0; i < 4; i++) cp16(d + i * 4096,         Asrc + (size_t)pre * 16384 + i * 4096);
#pragma unroll
        for (int i = 0; i < 4; i++) cp16(d + 16384 + i * 4096, Bsrc + (size_t)pre * 16384 + i * 4096);
        CP_COMMIT();
    }

    for (int kc = 0; kc < KC; kc++) {
        CP_WAIT1();
        __syncthreads();
        const uint32_t stA = sb0 + (kc & 1) * 32768, stB = stA + 16384;

#pragma unroll
        for (int s = 0; s < 2; s++) {
            uint32_t a1f[4][4], a2f[4][4];
            const int ga = 2 * s + akh;
#pragma unroll
            for (int mi = 0; mi < 4; mi++) {
                uint32_t ad = stA + (uint32_t)(arow + mi * 16) * 128;
                ldsm4(a1f[mi], ad + (uint32_t)(((ga     ^ aw) << 4)));
                ldsm4(a2f[mi], ad + (uint32_t)((((ga+4) ^ aw) << 4)));
            }
            const int gb = 2 * s + bkh;
#pragma unroll
            for (int nj = 0; nj < 2; nj++) {
                uint32_t bd = stB + (uint32_t)(brow + nj * 16) * 128;
                uint32_t b1f[4], b2f[4];
                ldsm4(b1f, bd + (uint32_t)(((gb     ^ bw) << 4)));
                ldsm4(b2f, bd + (uint32_t)((((gb+4) ^ bw) << 4)));
#pragma unroll
                for (int mi = 0; mi < 4; mi++) {
                    mma_i8(acc1[mi][2*nj],   a1f[mi], b1f[0], b1f[1]);
                    mma_i8(acc1[mi][2*nj+1], a1f[mi], b1f[2], b1f[3]);
                    mma_i8(acc2[mi][2*nj],   a1f[mi], b2f[0], b2f[1]);
                    mma_i8(acc2[mi][2*nj+1], a1f[mi], b2f[2], b2f[3]);
                    mma_i8(acc2[mi][2*nj],   a2f[mi], b1f[0], b1f[1]);
                    mma_i8(acc2[mi][2*nj+1], a2f[mi], b1f[2], b1f[3]);
                }
            }
        }
        __syncthreads();
        if (kc + 2 < KC) {
            uint32_t d = sb0 + (kc & 1) * 32768 + tid * 16;
#pragma unroll
            for (int i = 0; i < 4; i++) cp16(d + i * 4096,         Asrc + (size_t)(kc + 2) * 16384 + i * 4096);
#pragma unroll
            for (int i = 0; i < 4; i++) cp16(d + 16384 + i * 4096, Bsrc + (size_t)(kc + 2) * 16384 + i * 4096);
        }
        CP_COMMIT();
    }

    const int u = lane >> 2, qq = (lane & 3) * 2;
    const float k2 = 0.0078125f;
#pragma unroll
    for (int mi = 0; mi < 4; mi++) {
        int r0 = bm * 128 + wm * 64 + mi * 16 + u;
        float sa0 = sA[r0], sa1 = sA[r0 + 8];
#pragma unroll
        for (int nt = 0; nt < 4; nt++) {
            int c0 = bn * 128 + wn * 32 + nt * 8 + qq;
            float sb0v = sB[c0], sb1v = sB[c0 + 1];
            float d0 = (float)acc1[mi][nt][0] + (float)acc2[mi][nt][0] * k2;
            float d1 = (float)acc1[mi][nt][1] + (float)acc2[mi][nt][1] * k2;
            float d2 = (float)acc1[mi][nt][2] + (float)acc2[mi][nt][2] * k2;
            float d3 = (float)acc1[mi][nt][3] + (float)acc2[mi][nt][3] * k2;
            *(float2*)(C + (size_t)r0 * N + c0)       = make_float2(sa0 * sb0v * d0, sa0 * sb1v * d1);
            *(float2*)(C + (size_t)(r0 + 8) * N + c0) = make_float2(sa1 * sb0v * d2, sa1 * sb1v * d3);
        }
    }
}

// ===========================================================================
// RMSNorm + RoPE (+scale), fp32 in -> fp16 out. grid (SEQ, nheads), block 128.
// ===========================================================================
__global__ __launch_bounds__(128)
void norm_rope(const float* __restrict__ x, __half* __restrict__ xo,
               const float* __restrict__ cs, const float* __restrict__ sn,
               const float* __restrict__ w, int nheads, float scale)
{
    const int s = blockIdx.x, h = blockIdx.y, d = threadIdx.x;
    const size_t idx = (size_t)s * nheads * HD + (size_t)h * HD + d;

    float v = x[idx];
    float ss = v * v;
#pragma unroll
    for (int o = 16; o; o >>= 1) ss += __shfl_xor_sync(0xffffffffu, ss, o);

    __shared__ float red[4];
    __shared__ float sh[128];
    const int lane = d & 31, wid = d >> 5;
    if (lane == 0) red[wid] = ss;
    __syncthreads();
    float tot = red[0] + red[1] + red[2] + red[3];
    float r = rsqrtf(tot * (1.0f / 128.0f) + 1e-6f);
    float xn = v * r * w[d];
    sh[d] = xn;
    __syncthreads();
    float partner = sh[d ^ 64];
    float c  = cs[s * HD + d];
    float si = sn[s * HD + d];
    float out = (xn * c + (d < 64 ? -partner : partner) * si) * scale;
    xo[idx] = __float2half_rn(out);
}

// fp32 -> fp16 bulk convert (for V)
__global__ __launch_bounds__(256)
void cvt_f16(const float* __restrict__ x, __half* __restrict__ y, int n4)
{
    int i = blockIdx.x * 256 + threadIdx.x;
    if (i < n4) {
        float4 v = ((const float4*)x)[i];
        uint2 p;
        p.x = pk2(v.x, v.y);
        p.y = pk2(v.z, v.w);
        ((uint2*)y)[i] = p;
    }
}

// ===========================================================================
// fp16 flash attention (causal, GQA). grid (SEQ/64, NH), 128 thr = 4 warps.
// Q a-frags register-resident (32 regs, loaded once). K/V via ldmatrix.x4
// (trans for V) from granule-XOR-swizzled smem. P->A-frag is pure cvt (no
// shuffles: fp16 a-frag k-pair == S c-frag col-pair). smem 48KB.
// ===========================================================================
__global__ __launch_bounds__(128)
void flash_f16()
{
    extern __shared__ uint8_t smf[];
    const uint32_t sQ = smem_u32(smf);      // 64 rows x 256B
    const uint32_t sK = sQ + 16384;
    const uint32_t sV = sQ + 32768;

    const int tid = threadIdx.x, lane = tid & 31, warp = tid >> 5;
    const int qb = blockIdx.x, h = blockIdx.y, kvh = h >> 1;
    const int q2 = lane & 3, u = lane >> 2;

    // fill Q tile (swizzled granules)
    {
        const uint8_t* Qg = (const uint8_t*)(g_qh + ((size_t)(qb * 64) * NH + h) * HD);
#pragma unroll
        for (int j = 0; j < 8; j++) {
            int idx = tid + j * 128;
            int row = idx >> 4, g = idx & 15;
            cp16(sQ + row * 256 + ((g ^ (row & 7)) << 4),
                 Qg + (size_t)row * NH * HD * 2 + g * 16);
        }
        CP_COMMIT();
    }
    CP_WAIT0();
    __syncthreads();

    // preload Q a-frags: qf[ks][0..3], ks = 0..7 (k16 steps)
    uint32_t qf[8][4];
    {
        int row = warp * 16 + (lane & 7) + ((lane >> 3) & 1) * 8;
        int go  = lane >> 4;
        uint32_t rb = sQ + row * 256;
        int rw = (row & 7);
#pragma unroll
        for (int ks = 0; ks < 8; ks++)
            ldsm4(qf[ks], rb + (((2 * ks + go) ^ rw) << 4));
    }

    float o[16][4];
#pragma unroll
    for (int i = 0; i < 16; i++)
#pragma unroll
        for (int r = 0; r < 4; r++) o[i][r] = 0.f;
    float m0 = -1e30f, m1 = -1e30f, l0 = 0.f, l1 = 0.f;

    // lane addressing for K (non-trans) and V (trans) ldsm
    const int kkey = lane & 7;            // + 8*nt ; matrix = granule
    const int kgo  = lane >> 3;           // 0..3
    const int vkey = (lane & 7) + ((lane >> 3) & 1) * 8;   // + 16*ks
    const int vgo  = lane >> 4;           // 0/1

    for (int jb = 0; jb <= qb; jb++) {
        __syncthreads();
        {
            const uint8_t* Kg = (const uint8_t*)(g_kh + ((size_t)(jb * 64) * NKV + kvh) * HD);
            const uint8_t* Vg = (const uint8_t*)(g_vh + ((size_t)(jb * 64) * NKV + kvh) * HD);
#pragma unroll
            for (int j = 0; j < 8; j++) {
                int idx = tid + j * 128;
                int row = idx >> 4, g = idx & 15;
                uint32_t off = row * 256 + ((g ^ (row & 7)) << 4);
                size_t gsrc = (size_t)row * NKV * HD * 2 + g * 16;
                cp16(sK + off, Kg + gsrc);
                cp16(sV + off, Vg + gsrc);
            }
            CP_COMMIT();
        }
        CP_WAIT0();
        __syncthreads();

        // S = Q K^T
        float s[8][4];
#pragma unroll
        for (int nt = 0; nt < 8; nt++)
#pragma unroll
            for (int r = 0; r < 4; r++) s[nt][r] = 0.f;

#pragma unroll
        for (int g2 = 0; g2 < 4; g2++) {
#pragma unroll
            for (int nt = 0; nt < 8; nt++) {
                int key = 8 * nt + kkey;
                uint32_t bf[4];
                ldsm4(bf, sK + key * 256 + (((4 * g2 + kgo) ^ (key & 7)) << 4));
                mma_f16(s[nt], qf[2 * g2],     bf[0], bf[1]);
                mma_f16(s[nt], qf[2 * g2 + 1], bf[2], bf[3]);
            }
        }

        if (jb == qb) {
            int r0 = warp * 16 + u;
#pragma unroll
            for (int nt = 0; nt < 8; nt++) {
                int c = nt * 8 + q2 * 2;
                if (c     > r0)     s[nt][0] = -1e30f;
                if (c + 1 > r0)     s[nt][1] = -1e30f;
                if (c     > r0 + 8) s[nt][2] = -1e30f;
                if (c + 1 > r0 + 8) s[nt][3] = -1e30f;
            }
        }

        // online softmax
        float mx0 = -1e30f, mx1 = -1e30f;
#pragma unroll
        for (int nt = 0; nt < 8; nt++) {
            mx0 = fmaxf(mx0, fmaxf(s[nt][0], s[nt][1]));
            mx1 = fmaxf(mx1, fmaxf(s[nt][2], s[nt][3]));
        }
        mx0 = fmaxf(mx0, __shfl_xor_sync(0xffffffffu, mx0, 1));
        mx0 = fmaxf(mx0, __shfl_xor_sync(0xffffffffu, mx0, 2));
        mx1 = fmaxf(mx1, __shfl_xor_sync(0xffffffffu, mx1, 1));
        mx1 = fmaxf(mx1, __shfl_xor_sync(0xffffffffu, mx1, 2));
        float mn0 = fmaxf(m0, mx0), mn1 = fmaxf(m1, mx1);
        float cf0 = __expf(m0 - mn0), cf1 = __expf(m1 - mn1);
        m0 = mn0; m1 = mn1;

        float rs0 = 0.f, rs1 = 0.f;
        uint32_t pf[4][4];
#pragma unroll
        for (int kt = 0; kt < 4; kt++) {
            float e00 = __expf(s[2*kt][0]   - mn0), e01 = __expf(s[2*kt][1]   - mn0);
            float e02 = __expf(s[2*kt][2]   - mn1), e03 = __expf(s[2*kt][3]   - mn1);
            float e10 = __expf(s[2*kt+1][0] - mn0), e11 = __expf(s[2*kt+1][1] - mn0);
            float e12 = __expf(s[2*kt+1][2] - mn1), e13 = __expf(s[2*kt+1][3] - mn1);
            rs0 += e00 + e01 + e10 + e11;
            rs1 += e02 + e03 + e12 + e13;
            pf[kt][0] = pk2(e00, e01);   // rows lo, keys lo
            pf[kt][1] = pk2(e02, e03);   // rows hi, keys lo
            pf[kt][2] = pk2(e10, e11);   // rows lo, keys hi
            pf[kt][3] = pk2(e12, e13);   // rows hi, keys hi
        }
        rs0 += __shfl_xor_sync(0xffffffffu, rs0, 1);
        rs0 += __shfl_xor_sync(0xffffffffu, rs0, 2);
        rs1 += __shfl_xor_sync(0xffffffffu, rs1, 1);
        rs1 += __shfl_xor_sync(0xffffffffu, rs1, 2);
        l0 = l0 * cf0 + rs0;
        l1 = l1 * cf1 + rs1;
#pragma unroll
        for (int nt2 = 0; nt2 < 16; nt2++) {
            o[nt2][0] *= cf0; o[nt2][1] *= cf0;
            o[nt2][2] *= cf1; o[nt2][3] *= cf1;
        }

        // O += P V  (V b-frags via ldmatrix.trans)
#pragma unroll
        for (int ks = 0; ks < 4; ks++) {
#pragma unroll
            for (int np = 0; np < 8; np++) {
                int key = 16 * ks + vkey;
                uint32_t vf[4];
                ldsm4t(vf, sV + key * 256 + (((2 * np + vgo) ^ (key & 7)) << 4));
                mma_f16(o[2 * np],     pf[ks], vf[0], vf[1]);
                mma_f16(o[2 * np + 1], pf[ks], vf[2], vf[3]);
            }
        }
    }

    float r0i = 1.f / l0, r1i = 1.f / l1;
    int grow = qb * 64 + warp * 16 + u;
#pragma unroll
    for (int nt2 = 0; nt2 < 16; nt2++) {
        int col = h * HD + nt2 * 8 + q2 * 2;
        *(float2*)(g_attn + (size_t)grow * QDIM + col) =
            make_float2(o[nt2][0] * r0i, o[nt2][1] * r0i);
        *(float2*)(g_attn + (size_t)(grow + 8) * QDIM + col) =
            make_float2(o[nt2][2] * r1i, o[nt2][3] * r1i);
    }
}

// ===========================================================================
extern "C" void kernel_launch(void* const* d_in, const int* in_sizes, int n_in,
                              void* d_out, int out_size)
{
    const float* hid  = (const float*)d_in[0];
    const float* cosp = (const float*)d_in[1];
    const float* sinp = (const float*)d_in[2];
    const float* wq   = (const float*)d_in[3];
    const float* wk   = (const float*)d_in[4];
    const float* wv   = (const float*)d_in[5];
    const float* wo   = (const float*)d_in[6];
    const float* qw   = (const float*)d_in[7];
    const float* kw   = (const float*)d_in[8];
    float* out = (float*)d_out;

    float *qb, *kb, *vb, *ab;
    cudaGetSymbolAddress((void**)&qb, g_q);
    cudaGetSymbolAddress((void**)&kb, g_k);
    cudaGetSymbolAddress((void**)&vb, g_v);
    cudaGetSymbolAddress((void**)&ab, g_attn);
    __half *qh, *kh, *vh;
    cudaGetSymbolAddress((void**)&qh, g_qh);
    cudaGetSymbolAddress((void**)&kh, g_kh);
    cudaGetSymbolAddress((void**)&vh, g_vh);
    uint8_t *pa, *pwq, *pwk, *pwv, *pwo;
    cudaGetSymbolAddress((void**)&pa,  g_pa);
    cudaGetSymbolAddress((void**)&pwq, g_pwq);
    cudaGetSymbolAddress((void**)&pwk, g_pwk);
    cudaGetSymbolAddress((void**)&pwv, g_pwv);
    cudaGetSymbolAddress((void**)&pwo, g_pwo);
    float *sa, *swq, *swk, *swv, *swo;
    cudaGetSymbolAddress((void**)&sa,  g_sa);
    cudaGetSymbolAddress((void**)&swq, g_swq);
    cudaGetSymbolAddress((void**)&swk, g_swk);
    cudaGetSymbolAddress((void**)&swv, g_swv);
    cudaGetSymbolAddress((void**)&swo, g_swo);

    const int GEMM_SMEM  = 65536;
    const int FLASH_SMEM = 49152;
    cudaFuncSetAttribute(gemm_i8, cudaFuncAttributeMaxDynamicSharedMemorySize, GEMM_SMEM);
    cudaFuncSetAttribute(flash_f16, cudaFuncAttributeMaxDynamicSharedMemorySize, FLASH_SMEM);

    // pack activations + weights into 2-term int8
    pack_quant<<<SEQ / 8, 256>>>(hid, pa, sa);
    pack_quant<<<QDIM / 8, 256>>>(wq, pwq, swq);
    pack_quant<<<KVDIM / 8, 256>>>(wk, pwk, swk);
    pack_quant<<<KVDIM / 8, 256>>>(wv, pwv, swv);
    pack_quant<<<HID / 8, 256>>>(wo, pwo, swo);

    // QKV projections (int8 3-term tensor core)
    gemm_i8<<<dim3(QDIM / 128, SEQ / 128), 256, GEMM_SMEM>>>(pa, pwq, sa, swq, qb, QDIM);
    gemm_i8<<<dim3(KVDIM / 128, SEQ / 128), 256, GEMM_SMEM>>>(pa, pwk, sa, swk, kb, KVDIM);
    gemm_i8<<<dim3(KVDIM / 128, SEQ / 128), 256, GEMM_SMEM>>>(pa, pwv, sa, swv, vb, KVDIM);

    // RMSNorm + RoPE -> fp16 (scale folded into Q); V -> fp16
    norm_rope<<<dim3(SEQ, NH), 128>>>(qb, qh, cosp, sinp, qw, NH, 0.08838834764831845f);
    norm_rope<<<dim3(SEQ, NKV), 128>>>(kb, kh, cosp, sinp, kw, NKV, 1.0f);
    cvt_f16<<<(SEQ * KVDIM / 4 + 255) / 256, 256>>>(vb, vh, SEQ * KVDIM / 4);

    // causal GQA flash attention (fp16 tensor core)
    flash_f16<<<dim3(SEQ / 64, NH), 128, FLASH_SMEM>>>();

    // output projection
    pack_quant<<<SEQ / 8, 256>>>(ab, pa, sa);
    gemm_i8<<<dim3(HID / 128, SEQ / 128), 256, GEMM_SMEM>>>(pa, pwo, sa, swo, out, HID);
}

// round 7
// speedup vs baseline: 8.0283x; 1.0630x over previous
#include <cuda_runtime.h>
#include <cuda_fp16.h>
#include <cstdint>

#define SEQ   4096
#define HID   2048
#define NH    16
#define NKV   8
#define HD    128
#define QDIM  (NH*HD)    // 2048
#define KVDIM (NKV*HD)   // 1024
#define KDIM  2048
#define KC    (KDIM/64)  // 32
#define QKVN  4096       // merged QKV output width
// 1/sqrt(128) * log2(e)  (log2-domain softmax)
#define QSCALE (0.08838834764831845f * 1.4426950408889634f)

// fp32 intermediates
__device__ float g_qkv[(size_t)SEQ * QKVN];   // [s, q(2048) | k(1024) | v(1024)]
__device__ float g_attn[(size_t)SEQ * QDIM];

// fp16 flash operands
__device__ __half g_qh[SEQ * QDIM];
__device__ __half g_kh[SEQ * KVDIM];
__device__ __half g_vh[SEQ * KVDIM];

// int8 2-term packed operands + per-row scales
__device__ uint8_t g_pa[(size_t)SEQ * KDIM * 2];
__device__ uint8_t g_pw[(size_t)QKVN * KDIM * 2];    // wq|wk|wv merged
__device__ uint8_t g_pwo[(size_t)HID * KDIM * 2];
__device__ float g_sa[SEQ];
__device__ float g_sw[QKVN], g_swo[HID];

__device__ __forceinline__ void mma_i8(int* d,
    const uint32_t* a, uint32_t b0, uint32_t b1)
{
    asm volatile(
        "mma.sync.aligned.m16n8k32.row.col.s32.s8.s8.s32 "
        "{%0,%1,%2,%3}, {%4,%5,%6,%7}, {%8,%9}, {%0,%1,%2,%3};\n"
        : "+r"(d[0]), "+r"(d[1]), "+r"(d[2]), "+r"(d[3])
        : "r"(a[0]), "r"(a[1]), "r"(a[2]), "r"(a[3]), "r"(b0), "r"(b1));
}
__device__ __forceinline__ void mma_f16(float* d,
    const uint32_t* a, uint32_t b0, uint32_t b1)
{
    asm volatile(
        "mma.sync.aligned.m16n8k16.row.col.f32.f16.f16.f32 "
        "{%0,%1,%2,%3}, {%4,%5,%6,%7}, {%8,%9}, {%0,%1,%2,%3};\n"
        : "+f"(d[0]), "+f"(d[1]), "+f"(d[2]), "+f"(d[3])
        : "r"(a[0]), "r"(a[1]), "r"(a[2]), "r"(a[3]), "r"(b0), "r"(b1));
}
__device__ __forceinline__ void ldsm4(uint32_t* r, uint32_t addr) {
    asm volatile("ldmatrix.sync.aligned.m8n8.x4.shared.b16 {%0,%1,%2,%3}, [%4];"
                 : "=r"(r[0]), "=r"(r[1]), "=r"(r[2]), "=r"(r[3]) : "r"(addr));
}
__device__ __forceinline__ void ldsm4t(uint32_t* r, uint32_t addr) {
    asm volatile("ldmatrix.sync.aligned.m8n8.x4.trans.shared.b16 {%0,%1,%2,%3}, [%4];"
                 : "=r"(r[0]), "=r"(r[1]), "=r"(r[2]), "=r"(r[3]) : "r"(addr));
}
__device__ __forceinline__ uint32_t smem_u32(const void* p) {
    uint32_t a;
    asm("{ .reg .u64 t; cvta.to.shared.u64 t, %1; cvt.u32.u64 %0, t; }" : "=r"(a) : "l"(p));
    return a;
}
__device__ __forceinline__ void cp16(uint32_t d, const void* g) {
    asm volatile("cp.async.cg.shared.global [%0], [%1], 16;" :: "r"(d), "l"(g));
}
#define CP_COMMIT() asm volatile("cp.async.commit_group;")
#define CP_WAIT1()  asm volatile("cp.async.wait_group 1;")
#define CP_WAIT0()  asm volatile("cp.async.wait_group 0;")

// two exp2 in one MUFU op, result packed fp16x2
__device__ __forceinline__ uint32_t exp2h2(float a, float b) {
    __half2 h = __floats2half2_rn(a, b);
    uint32_t x = *(uint32_t*)&h, r;
    asm("ex2.approx.f16x2 %0, %1;" : "=r"(r) : "r"(x));
    return r;
}
__device__ __forceinline__ float exp2s(float x) {
    float r; asm("ex2.approx.f32 %0, %1;" : "=f"(r) : "f"(x)); return r;
}

// ===========================================================================
// pack_quant: fp32 [rows, 2048] -> per-row 2-term int8, tile-packed+swizzled.
// ===========================================================================
__global__ __launch_bounds__(256)
void pack_quant(const float* __restrict__ src, uint8_t* __restrict__ dst,
                float* __restrict__ scl)
{
    const int warp = threadIdx.x >> 5, lane = threadIdx.x & 31;
    const int row = blockIdx.x * 8 + warp;
    const float* s = src + (size_t)row * KDIM;

    float4 v[16];
    float mx = 0.f;
#pragma unroll
    for (int j = 0; j < 16; j++) {
        v[j] = *(const float4*)(s + lane * 4 + j * 128);
        mx = fmaxf(mx, fmaxf(fmaxf(fabsf(v[j].x), fabsf(v[j].y)),
                             fmaxf(fabsf(v[j].z), fabsf(v[j].w))));
    }
#pragma unroll
    for (int o = 16; o; o >>= 1) mx = fmaxf(mx, __shfl_xor_sync(0xffffffffu, mx, o));

    const float s1   = mx * (1.f / 127.f);
    const float inv1 = mx > 0.f ? 127.f / mx : 0.f;
    const float inv2 = inv1 * 128.f;
    if (lane == 0) scl[row] = s1;

    const int rt = row >> 7, rr = row & 127, sw = rr & 7;
    uint8_t* tbase0 = dst + ((size_t)rt * KC) * 16384 + rr * 128;

#pragma unroll
    for (int j = 0; j < 16; j++) {
        int k = lane * 4 + j * 128;
        int c = k >> 6, w16 = (k >> 4) & 3, bin = k & 15;
        float4 x = v[j];
        int q0 = __float2int_rn(x.x * inv1), q1 = __float2int_rn(x.y * inv1);
        int q2 = __float2int_rn(x.z * inv1), q3 = __float2int_rn(x.w * inv1);
        int r0 = __float2int_rn((x.x - q0 * s1) * inv2);
        int r1 = __float2int_rn((x.y - q1 * s1) * inv2);
        int r2 = __float2int_rn((x.z - q2 * s1) * inv2);
        int r3 = __float2int_rn((x.w - q3 * s1) * inv2);
        uint8_t* tb = tbase0 + c * 16384;
        *(char4*)(tb + (((w16     ^ sw) << 4) + bin)) =
            make_char4((char)q0, (char)q1, (char)q2, (char)q3);
        *(char4*)(tb + ((((w16+4) ^ sw) << 4) + bin)) =
            make_char4((char)r0, (char)r1, (char)r2, (char)r3);
    }
}

// ===========================================================================
// gemm_i8: 3-term int8 mma, 128x128 tile (unchanged, passing).
// ===========================================================================
__global__ __launch_bounds__(256)
void gemm_i8(const uint8_t* __restrict__ Ap, const uint8_t* __restrict__ Bp,
             const float* __restrict__ sA, const float* __restrict__ sB,
             float* __restrict__ C, int N)
{
    extern __shared__ uint8_t smi[];
    const uint32_t sb0 = smem_u32(smi);
    const int tid = threadIdx.x, lane = tid & 31, warp = tid >> 5;
    const int wm = warp >> 2, wn = warp & 3;
    const int bn = blockIdx.x, bm = blockIdx.y;

    const uint8_t* Asrc = Ap + (size_t)bm * KC * 16384 + tid * 16;
    const uint8_t* Bsrc = Bp + (size_t)bn * KC * 16384 + tid * 16;

    int acc1[4][4][4] = {}, acc2[4][4][4] = {};

    const int arow = wm * 64 + (lane & 7) + ((lane >> 3) & 1) * 8;
    const int akh  = lane >> 4;
    const int aw   = arow & 7;
    const int brow = wn * 32 + (lane & 7) + (lane >> 4) * 8;
    const int bkh  = (lane >> 3) & 1;
    const int bw   = brow & 7;

#pragma unroll
    for (int pre = 0; pre < 2; pre++) {
        uint32_t d = sb0 + pre * 32768 + tid * 16;
#pragma unroll
        for (int i = 0; i < 4; i++) cp16(d + i * 4096,         Asrc + (size_t)pre * 16384 + i * 4096);
#pragma unroll
        for (int i = 0; i < 4; i++) cp16(d + 16384 + i * 4096, Bsrc + (size_t)pre * 16384 + i * 4096);
        CP_COMMIT();
    }

    for (int kc = 0; kc < KC; kc++) {
        CP_WAIT1();
        __syncthreads();
        const uint32_t stA = sb0 + (kc & 1) * 32768, stB = stA + 16384;

#pragma unroll
        for (int s = 0; s < 2; s++) {
            uint32_t a1f[4][4], a2f[4][4];
            const int ga = 2 * s + akh;
#pragma unroll
            for (int mi = 0; mi < 4; mi++) {
                uint32_t ad = stA + (uint32_t)(arow + mi * 16) * 128;
                ldsm4(a1f[mi], ad + (uint32_t)(((ga     ^ aw) << 4)));
                ldsm4(a2f[mi], ad + (uint32_t)((((ga+4) ^ aw) << 4)));
            }
            const int gb = 2 * s + bkh;
#pragma unroll
            for (int nj = 0; nj < 2; nj++) {
                uint32_t bd = stB + (uint32_t)(brow + nj * 16) * 128;
                uint32_t b1f[4], b2f[4];
                ldsm4(b1f, bd + (uint32_t)(((gb     ^ bw) << 4)));
                ldsm4(b2f, bd + (uint32_t)((((gb+4) ^ bw) << 4)));
#pragma unroll
                for (int mi = 0; mi < 4; mi++) {
                    mma_i8(acc1[mi][2*nj],   a1f[mi], b1f[0], b1f[1]);
                    mma_i8(acc1[mi][2*nj+1], a1f[mi], b1f[2], b1f[3]);
                    mma_i8(acc2[mi][2*nj],   a1f[mi], b2f[0], b2f[1]);
                    mma_i8(acc2[mi][2*nj+1], a1f[mi], b2f[2], b2f[3]);
                    mma_i8(acc2[mi][2*nj],   a2f[mi], b1f[0], b1f[1]);
                    mma_i8(acc2[mi][2*nj+1], a2f[mi], b1f[2], b1f[3]);
                }
            }
        }
        __syncthreads();
        if (kc + 2 < KC) {
            uint32_t d = sb0 + (kc & 1) * 32768 + tid * 16;
#pragma unroll
            for (int i = 0; i < 4; i++) cp16(d + i * 4096,         Asrc + (size_t)(kc + 2) * 16384 + i * 4096);
#pragma unroll
            for (int i = 0; i < 4; i++) cp16(d + 16384 + i * 4096, Bsrc + (size_t)(kc + 2) * 16384 + i * 4096);
        }
        CP_COMMIT();
    }

    const int u = lane >> 2, qq = (lane & 3) * 2;
    const float k2 = 0.0078125f;
#pragma unroll
    for (int mi = 0; mi < 4; mi++) {
        int r0 = bm * 128 + wm * 64 + mi * 16 + u;
        float sa0 = sA[r0], sa1 = sA[r0 + 8];
#pragma unroll
        for (int nt = 0; nt < 4; nt++) {
            int c0 = bn * 128 + wn * 32 + nt * 8 + qq;
            float sb0v = sB[c0], sb1v = sB[c0 + 1];
            float d0 = (float)acc1[mi][nt][0] + (float)acc2[mi][nt][0] * k2;
            float d1 = (float)acc1[mi][nt][1] + (float)acc2[mi][nt][1] * k2;
            float d2 = (float)acc1[mi][nt][2] + (float)acc2[mi][nt][2] * k2;
            float d3 = (float)acc1[mi][nt][3] + (float)acc2[mi][nt][3] * k2;
            *(float2*)(C + (size_t)r0 * N + c0)       = make_float2(sa0 * sb0v * d0, sa0 * sb1v * d1);
            *(float2*)(C + (size_t)(r0 + 8) * N + c0) = make_float2(sa1 * sb0v * d2, sa1 * sb1v * d3);
        }
    }
}

// ===========================================================================
// Fused: Q-norm+RoPE (h<16), K-norm+RoPE (16<=h<24), V fp16 convert (h>=24).
// Reads merged g_qkv [s, 4096]. grid (SEQ, 32), block 128.
// Q output carries scale*log2e (log2-domain softmax).
// ===========================================================================
__global__ __launch_bounds__(128)
void norm_rope_cvt(const float* __restrict__ qkv, __half* __restrict__ qo,
                   __half* __restrict__ ko, __half* __restrict__ vo,
                   const float* __restrict__ cs, const float* __restrict__ sn,
                   const float* __restrict__ qw, const float* __restrict__ kw)
{
    const int s = blockIdx.x, h = blockIdx.y, d = threadIdx.x;

    if (h >= 24) {   // V convert
        int c = (h - 24) * 128 + d;
        vo[(size_t)s * KVDIM + c] = __float2half_rn(qkv[(size_t)s * QKVN + 3072 + c]);
        return;
    }
    const bool isq = h < 16;
    const int hh = isq ? h : h - 16;
    const float* w = isq ? qw : kw;
    const float scale = isq ? (float)QSCALE : 1.0f;
    const float v = qkv[(size_t)s * QKVN + (isq ? 0 : 2048) + hh * HD + d];

    float ss = v * v;
#pragma unroll
    for (int o = 16; o; o >>= 1) ss += __shfl_xor_sync(0xffffffffu, ss, o);

    __shared__ float red[4];
    __shared__ float sh[128];
    const int lane = d & 31, wid = d >> 5;
    if (lane == 0) red[wid] = ss;
    __syncthreads();
    float tot = red[0] + red[1] + red[2] + red[3];
    float r = rsqrtf(tot * (1.0f / 128.0f) + 1e-6f);
    float xn = v * r * w[d];
    sh[d] = xn;
    __syncthreads();
    float partner = sh[d ^ 64];
    float c  = cs[s * HD + d];
    float si = sn[s * HD + d];
    float outv = (xn * c + (d < 64 ? -partner : partner) * si) * scale;
    __half* out = isq ? (qo + (size_t)s * QDIM + hh * HD + d)
                      : (ko + (size_t)s * KVDIM + hh * HD + d);
    *out = __float2half_rn(outv);
}

// ===========================================================================
// fp16 flash attention, log2-domain softmax. grid (SEQ/64, NH), 128 thr.
// qb reversed (longest CTAs first). P via ex2.approx.f16x2 (1 MUFU / 2 elems),
// row sums via ones-mma (exact fp32, no shuffles).
// ===========================================================================
__global__ __launch_bounds__(128)
void flash_f16()
{
    extern __shared__ uint8_t smf[];
    const uint32_t sQ = smem_u32(smf);      // 64 rows x 256B each
    const uint32_t sK = sQ + 16384;
    const uint32_t sV = sQ + 32768;

    const int tid = threadIdx.x, lane = tid & 31, warp = tid >> 5;
    const int qb = gridDim.x - 1 - blockIdx.x;      // longest first
    const int h = blockIdx.y, kvh = h >> 1;
    const int q2 = lane & 3, u = lane >> 2;
    const uint32_t ONES2 = 0x3C003C00u;   // half2(1,1)

    {
        const uint8_t* Qg = (const uint8_t*)(g_qh + ((size_t)(qb * 64) * NH + h) * HD);
#pragma unroll
        for (int j = 0; j < 8; j++) {
            int idx = tid + j * 128;
            int row = idx >> 4, g = idx & 15;
            cp16(sQ + row * 256 + ((g ^ (row & 7)) << 4),
                 Qg + (size_t)row * NH * HD * 2 + g * 16);
        }
        CP_COMMIT();
    }
    CP_WAIT0();
    __syncthreads();

    uint32_t qf[8][4];
    {
        int row = warp * 16 + (lane & 7) + ((lane >> 3) & 1) * 8;
        int go  = lane >> 4;
        uint32_t rb = sQ + row * 256;
        int rw = (row & 7);
#pragma unroll
        for (int ks = 0; ks < 8; ks++)
            ldsm4(qf[ks], rb + (((2 * ks + go) ^ rw) << 4));
    }

    float o[16][4];
#pragma unroll
    for (int i = 0; i < 16; i++)
#pragma unroll
        for (int r = 0; r < 4; r++) o[i][r] = 0.f;
    float m0 = -1e30f, m1 = -1e30f, l0 = 0.f, l1 = 0.f;

    const int kkey = lane & 7;
    const int kgo  = lane >> 3;
    const int vkey = (lane & 7) + ((lane >> 3) & 1) * 8;
    const int vgo  = lane >> 4;

    for (int jb = 0; jb <= qb; jb++) {
        __syncthreads();
        {
            const uint8_t* Kg = (const uint8_t*)(g_kh + ((size_t)(jb * 64) * NKV + kvh) * HD);
            const uint8_t* Vg = (const uint8_t*)(g_vh + ((size_t)(jb * 64) * NKV + kvh) * HD);
#pragma unroll
            for (int j = 0; j < 8; j++) {
                int idx = tid + j * 128;
                int row = idx >> 4, g = idx & 15;
                uint32_t off = row * 256 + ((g ^ (row & 7)) << 4);
                size_t gsrc = (size_t)row * NKV * HD * 2 + g * 16;
                cp16(sK + off, Kg + gsrc);
                cp16(sV + off, Vg + gsrc);
            }
            CP_COMMIT();
        }
        CP_WAIT0();
        __syncthreads();

        // S = Q K^T (already in log2 domain: Q carries scale*log2e)
        float s[8][4];
#pragma unroll
        for (int nt = 0; nt < 8; nt++)
#pragma unroll
            for (int r = 0; r < 4; r++) s[nt][r] = 0.f;

#pragma unroll
        for (int g2 = 0; g2 < 4; g2++) {
#pragma unroll
            for (int nt = 0; nt < 8; nt++) {
                int key = 8 * nt + kkey;
                uint32_t bf[4];
                ldsm4(bf, sK + key * 256 + (((4 * g2 + kgo) ^ (key & 7)) << 4));
                mma_f16(s[nt], qf[2 * g2],     bf[0], bf[1]);
                mma_f16(s[nt], qf[2 * g2 + 1], bf[2], bf[3]);
            }
        }

        if (jb == qb) {
            int r0 = warp * 16 + u;
#pragma unroll
            for (int nt = 0; nt < 8; nt++) {
                int c = nt * 8 + q2 * 2;
                if (c     > r0)     s[nt][0] = -1e30f;
                if (c + 1 > r0)     s[nt][1] = -1e30f;
                if (c     > r0 + 8) s[nt][2] = -1e30f;
                if (c + 1 > r0 + 8) s[nt][3] = -1e30f;
            }
        }

        // online softmax (base-2)
        float mx0 = -1e30f, mx1 = -1e30f;
#pragma unroll
        for (int nt = 0; nt < 8; nt++) {
            mx0 = fmaxf(mx0, fmaxf(s[nt][0], s[nt][1]));
            mx1 = fmaxf(mx1, fmaxf(s[nt][2], s[nt][3]));
        }
        mx0 = fmaxf(mx0, __shfl_xor_sync(0xffffffffu, mx0, 1));
        mx0 = fmaxf(mx0, __shfl_xor_sync(0xffffffffu, mx0, 2));
        mx1 = fmaxf(mx1, __shfl_xor_sync(0xffffffffu, mx1, 1));
        mx1 = fmaxf(mx1, __shfl_xor_sync(0xffffffffu, mx1, 2));
        float mn0 = fmaxf(m0, mx0), mn1 = fmaxf(m1, mx1);
        float cf0 = exp2s(m0 - mn0), cf1 = exp2s(m1 - mn1);
        m0 = mn0; m1 = mn1;

        // P = exp2(S - m), packed fp16x2 straight out of MUFU
        uint32_t pf[4][4];
#pragma unroll
        for (int kt = 0; kt < 4; kt++) {
            pf[kt][0] = exp2h2(s[2*kt][0]   - mn0, s[2*kt][1]   - mn0);
            pf[kt][1] = exp2h2(s[2*kt][2]   - mn1, s[2*kt][3]   - mn1);
            pf[kt][2] = exp2h2(s[2*kt+1][0] - mn0, s[2*kt+1][1] - mn0);
            pf[kt][3] = exp2h2(s[2*kt+1][2] - mn1, s[2*kt+1][3] - mn1);
        }

        // exact row sums via ones-mma: d[0]=sum(rows lo), d[2]=sum(rows hi)
        float rsd[4] = {0.f, 0.f, 0.f, 0.f};
#pragma unroll
        for (int kt = 0; kt < 4; kt++)
            mma_f16(rsd, pf[kt], ONES2, ONES2);

        l0 = l0 * cf0 + rsd[0];
        l1 = l1 * cf1 + rsd[2];
#pragma unroll
        for (int nt2 = 0; nt2 < 16; nt2++) {
            o[nt2][0] *= cf0; o[nt2][1] *= cf0;
            o[nt2][2] *= cf1; o[nt2][3] *= cf1;
        }

        // O += P V
#pragma unroll
        for (int ks = 0; ks < 4; ks++) {
#pragma unroll
            for (int np = 0; np < 8; np++) {
                int key = 16 * ks + vkey;
                uint32_t vf[4];
                ldsm4t(vf, sV + key * 256 + (((2 * np + vgo) ^ (key & 7)) << 4));
                mma_f16(o[2 * np],     pf[ks], vf[0], vf[1]);
                mma_f16(o[2 * np + 1], pf[ks], vf[2], vf[3]);
            }
        }
    }

    float r0i = 1.f / l0, r1i = 1.f / l1;
    int grow = qb * 64 + warp * 16 + u;
#pragma unroll
    for (int nt2 = 0; nt2 < 16; nt2++) {
        int col = h * HD + nt2 * 8 + q2 * 2;
        *(float2*)(g_attn + (size_t)grow * QDIM + col) =
            make_float2(o[nt2][0] * r0i, o[nt2][1] * r0i);
        *(float2*)(g_attn + (size_t)(grow + 8) * QDIM + col) =
            make_float2(o[nt2][2] * r1i, o[nt2][3] * r1i);
    }
}

// ===========================================================================
extern "C" void kernel_launch(void* const* d_in, const int* in_sizes, int n_in,
                              void* d_out, int out_size)
{
    const float* hid  = (const float*)d_in[0];
    const float* cosp = (const float*)d_in[1];
    const float* sinp = (const float*)d_in[2];
    const float* wq   = (const float*)d_in[3];
    const float* wk   = (const float*)d_in[4];
    const float* wv   = (const float*)d_in[5];
    const float* wo   = (const float*)d_in[6];
    const float* qw   = (const float*)d_in[7];
    const float* kw   = (const float*)d_in[8];
    float* out = (float*)d_out;

    float *qkv, *ab;
    cudaGetSymbolAddress((void**)&qkv, g_qkv);
    cudaGetSymbolAddress((void**)&ab, g_attn);
    __half *qh, *kh, *vh;
    cudaGetSymbolAddress((void**)&qh, g_qh);
    cudaGetSymbolAddress((void**)&kh, g_kh);
    cudaGetSymbolAddress((void**)&vh, g_vh);
    uint8_t *pa, *pw, *pwo;
    cudaGetSymbolAddress((void**)&pa,  g_pa);
    cudaGetSymbolAddress((void**)&pw,  g_pw);
    cudaGetSymbolAddress((void**)&pwo, g_pwo);
    float *sa, *sw, *swo;
    cudaGetSymbolAddress((void**)&sa,  g_sa);
    cudaGetSymbolAddress((void**)&sw,  g_sw);
    cudaGetSymbolAddress((void**)&swo, g_swo);

    const int GEMM_SMEM  = 65536;
    const int FLASH_SMEM = 49152;
    cudaFuncSetAttribute(gemm_i8, cudaFuncAttributeMaxDynamicSharedMemorySize, GEMM_SMEM);
    cudaFuncSetAttribute(flash_f16, cudaFuncAttributeMaxDynamicSharedMemorySize, FLASH_SMEM);

    // pack activations + merged qkv weights + output weights
    pack_quant<<<SEQ / 8, 256>>>(hid, pa, sa);
    pack_quant<<<QDIM / 8, 256>>>(wq, pw, sw);
    pack_quant<<<KVDIM / 8, 256>>>(wk, pw + (size_t)QDIM * KDIM * 2, sw + QDIM);
    pack_quant<<<KVDIM / 8, 256>>>(wv, pw + (size_t)(QDIM + KVDIM) * KDIM * 2, sw + QDIM + KVDIM);
    pack_quant<<<HID / 8, 256>>>(wo, pwo, swo);

    // single merged QKV projection (1024 CTAs)
    gemm_i8<<<dim3(QKVN / 128, SEQ / 128), 256, GEMM_SMEM>>>(pa, pw, sa, sw, qkv, QKVN);

    // fused Q-norm/K-norm/RoPE/V-convert
    norm_rope_cvt<<<dim3(SEQ, 32), 128>>>(qkv, qh, kh, vh, cosp, sinp, qw, kw);

    // causal GQA flash attention (fp16, log2-domain)
    flash_f16<<<dim3(SEQ / 64, NH), 128, FLASH_SMEM>>>();

    // output projection
    pack_quant<<<SEQ / 8, 256>>>(ab, pa, sa);
    gemm_i8<<<dim3(HID / 128, SEQ / 128), 256, GEMM_SMEM>>>(pa, pwo, sa, swo, out, HID);
}

// round 8
// speedup vs baseline: 8.1361x; 1.0134x over previous
#include <cuda_runtime.h>
#include <cuda_fp16.h>
#include <cstdint>

#define SEQ   4096
#define HID   2048
#define NH    16
#define NKV   8
#define HD    128
#define QDIM  (NH*HD)    // 2048
#define KVDIM (NKV*HD)   // 1024
#define KDIM  2048
#define KC    (KDIM/64)  // 32
#define QKVN  4096
#define QSCALE (0.08838834764831845f * 1.4426950408889634f)

// fp32 intermediates
__device__ float g_qkv[(size_t)SEQ * QKVN];
__device__ float g_attn[(size_t)SEQ * QDIM];

// fp16 flash operands
__device__ __half g_qh[SEQ * QDIM];
__device__ __half g_kh[SEQ * KVDIM];
__device__ __half g_vh[SEQ * KVDIM];

// int8 2-term packed operands + per-row scales
__device__ uint8_t g_pa[(size_t)SEQ * KDIM * 2];
__device__ uint8_t g_pw[(size_t)QKVN * KDIM * 2];
__device__ uint8_t g_pwo[(size_t)HID * KDIM * 2];
__device__ float g_sa[SEQ];
__device__ float g_sw[QKVN], g_swo[HID];

__device__ __forceinline__ void mma_i8(int* d,
    const uint32_t* a, uint32_t b0, uint32_t b1)
{
    asm volatile(
        "mma.sync.aligned.m16n8k32.row.col.s32.s8.s8.s32 "
        "{%0,%1,%2,%3}, {%4,%5,%6,%7}, {%8,%9}, {%0,%1,%2,%3};\n"
        : "+r"(d[0]), "+r"(d[1]), "+r"(d[2]), "+r"(d[3])
        : "r"(a[0]), "r"(a[1]), "r"(a[2]), "r"(a[3]), "r"(b0), "r"(b1));
}
__device__ __forceinline__ void mma_f16(float* d,
    const uint32_t* a, uint32_t b0, uint32_t b1)
{
    asm volatile(
        "mma.sync.aligned.m16n8k16.row.col.f32.f16.f16.f32 "
        "{%0,%1,%2,%3}, {%4,%5,%6,%7}, {%8,%9}, {%0,%1,%2,%3};\n"
        : "+f"(d[0]), "+f"(d[1]), "+f"(d[2]), "+f"(d[3])
        : "r"(a[0]), "r"(a[1]), "r"(a[2]), "r"(a[3]), "r"(b0), "r"(b1));
}
__device__ __forceinline__ void ldsm4(uint32_t* r, uint32_t addr) {
    asm volatile("ldmatrix.sync.aligned.m8n8.x4.shared.b16 {%0,%1,%2,%3}, [%4];"
                 : "=r"(r[0]), "=r"(r[1]), "=r"(r[2]), "=r"(r[3]) : "r"(addr));
}
__device__ __forceinline__ void ldsm4t(uint32_t* r, uint32_t addr) {
    asm volatile("ldmatrix.sync.aligned.m8n8.x4.trans.shared.b16 {%0,%1,%2,%3}, [%4];"
                 : "=r"(r[0]), "=r"(r[1]), "=r"(r[2]), "=r"(r[3]) : "r"(addr));
}
__device__ __forceinline__ uint32_t smem_u32(const void* p) {
    uint32_t a;
    asm("{ .reg .u64 t; cvta.to.shared.u64 t, %1; cvt.u32.u64 %0, t; }" : "=r"(a) : "l"(p));
    return a;
}
__device__ __forceinline__ void cp16(uint32_t d, const void* g) {
    asm volatile("cp.async.cg.shared.global [%0], [%1], 16;" :: "r"(d), "l"(g));
}
#define CP_COMMIT() asm volatile("cp.async.commit_group;")
#define CP_WAIT2()  asm volatile("cp.async.wait_group 2;")
#define CP_WAIT0()  asm volatile("cp.async.wait_group 0;")

__device__ __forceinline__ uint32_t exp2h2(float a, float b) {
    __half2 h = __floats2half2_rn(a, b);
    uint32_t x = *(uint32_t*)&h, r;
    asm("ex2.approx.f16x2 %0, %1;" : "=r"(r) : "r"(x));
    return r;
}
__device__ __forceinline__ float exp2s(float x) {
    float r; asm("ex2.approx.f32 %0, %1;" : "=f"(r) : "f"(x)); return r;
}

// ===========================================================================
// pack_quant (unchanged, passing)
// ===========================================================================
__global__ __launch_bounds__(256)
void pack_quant(const float* __restrict__ src, uint8_t* __restrict__ dst,
                float* __restrict__ scl)
{
    const int warp = threadIdx.x >> 5, lane = threadIdx.x & 31;
    const int row = blockIdx.x * 8 + warp;
    const float* s = src + (size_t)row * KDIM;

    float4 v[16];
    float mx = 0.f;
#pragma unroll
    for (int j = 0; j < 16; j++) {
        v[j] = *(const float4*)(s + lane * 4 + j * 128);
        mx = fmaxf(mx, fmaxf(fmaxf(fabsf(v[j].x), fabsf(v[j].y)),
                             fmaxf(fabsf(v[j].z), fabsf(v[j].w))));
    }
#pragma unroll
    for (int o = 16; o; o >>= 1) mx = fmaxf(mx, __shfl_xor_sync(0xffffffffu, mx, o));

    const float s1   = mx * (1.f / 127.f);
    const float inv1 = mx > 0.f ? 127.f / mx : 0.f;
    const float inv2 = inv1 * 128.f;
    if (lane == 0) scl[row] = s1;

    const int rt = row >> 7, rr = row & 127, sw = rr & 7;
    uint8_t* tbase0 = dst + ((size_t)rt * KC) * 16384 + rr * 128;

#pragma unroll
    for (int j = 0; j < 16; j++) {
        int k = lane * 4 + j * 128;
        int c = k >> 6, w16 = (k >> 4) & 3, bin = k & 15;
        float4 x = v[j];
        int q0 = __float2int_rn(x.x * inv1), q1 = __float2int_rn(x.y * inv1);
        int q2 = __float2int_rn(x.z * inv1), q3 = __float2int_rn(x.w * inv1);
        int r0 = __float2int_rn((x.x - q0 * s1) * inv2);
        int r1 = __float2int_rn((x.y - q1 * s1) * inv2);
        int r2 = __float2int_rn((x.z - q2 * s1) * inv2);
        int r3 = __float2int_rn((x.w - q3 * s1) * inv2);
        uint8_t* tb = tbase0 + c * 16384;
        *(char4*)(tb + (((w16     ^ sw) << 4) + bin)) =
            make_char4((char)q0, (char)q1, (char)q2, (char)q3);
        *(char4*)(tb + ((((w16+4) ^ sw) << 4) + bin)) =
            make_char4((char)r0, (char)r1, (char)r2, (char)r3);
    }
}

// ===========================================================================
// gemm_i8: 3-term int8 mma, 128x128 tile, 3-stage cp.async pipeline (96KB).
// ===========================================================================
__global__ __launch_bounds__(256)
void gemm_i8(const uint8_t* __restrict__ Ap, const uint8_t* __restrict__ Bp,
             const float* __restrict__ sA, const float* __restrict__ sB,
             float* __restrict__ C, int N)
{
    extern __shared__ uint8_t smi[];   // [3][A 16KB | B 16KB]
    const uint32_t sb0 = smem_u32(smi);
    const int tid = threadIdx.x, lane = tid & 31, warp = tid >> 5;
    const int wm = warp >> 2, wn = warp & 3;
    const int bn = blockIdx.x, bm = blockIdx.y;

    const uint8_t* Asrc = Ap + (size_t)bm * KC * 16384 + tid * 16;
    const uint8_t* Bsrc = Bp + (size_t)bn * KC * 16384 + tid * 16;

    int acc1[4][4][4] = {}, acc2[4][4][4] = {};

    const int arow = wm * 64 + (lane & 7) + ((lane >> 3) & 1) * 8;
    const int akh  = lane >> 4;
    const int aw   = arow & 7;
    const int brow = wn * 32 + (lane & 7) + (lane >> 4) * 8;
    const int bkh  = (lane >> 3) & 1;
    const int bw   = brow & 7;

#pragma unroll
    for (int pre = 0; pre < 3; pre++) {
        uint32_t d = sb0 + pre * 32768 + tid * 16;
#pragma unroll
        for (int i = 0; i < 4; i++) cp16(d + i * 4096,         Asrc + (size_t)pre * 16384 + i * 4096);
#pragma unroll
        for (int i = 0; i < 4; i++) cp16(d + 16384 + i * 4096, Bsrc + (size_t)pre * 16384 + i * 4096);
        CP_COMMIT();
    }

    int stage = 0;
    for (int kc = 0; kc < KC; kc++) {
        CP_WAIT2();
        __syncthreads();
        const uint32_t stA = sb0 + stage * 32768, stB = stA + 16384;

#pragma unroll
        for (int s = 0; s < 2; s++) {
            uint32_t a1f[4][4], a2f[4][4];
            const int ga = 2 * s + akh;
#pragma unroll
            for (int mi = 0; mi < 4; mi++) {
                uint32_t ad = stA + (uint32_t)(arow + mi * 16) * 128;
                ldsm4(a1f[mi], ad + (uint32_t)(((ga     ^ aw) << 4)));
                ldsm4(a2f[mi], ad + (uint32_t)((((ga+4) ^ aw) << 4)));
            }
            const int gb = 2 * s + bkh;
#pragma unroll
            for (int nj = 0; nj < 2; nj++) {
                uint32_t bd = stB + (uint32_t)(brow + nj * 16) * 128;
                uint32_t b1f[4], b2f[4];
                ldsm4(b1f, bd + (uint32_t)(((gb     ^ bw) << 4)));
                ldsm4(b2f, bd + (uint32_t)((((gb+4) ^ bw) << 4)));
#pragma unroll
                for (int mi = 0; mi < 4; mi++) {
                    mma_i8(acc1[mi][2*nj],   a1f[mi], b1f[0], b1f[1]);
                    mma_i8(acc1[mi][2*nj+1], a1f[mi], b1f[2], b1f[3]);
                    mma_i8(acc2[mi][2*nj],   a1f[mi], b2f[0], b2f[1]);
                    mma_i8(acc2[mi][2*nj+1], a1f[mi], b2f[2], b2f[3]);
                    mma_i8(acc2[mi][2*nj],   a2f[mi], b1f[0], b1f[1]);
                    mma_i8(acc2[mi][2*nj+1], a2f[mi], b1f[2], b1f[3]);
                }
            }
        }
        __syncthreads();
        if (kc + 3 < KC) {
            uint32_t d = sb0 + stage * 32768 + tid * 16;
#pragma unroll
            for (int i = 0; i < 4; i++) cp16(d + i * 4096,         Asrc + (size_t)(kc + 3) * 16384 + i * 4096);
#pragma unroll
            for (int i = 0; i < 4; i++) cp16(d + 16384 + i * 4096, Bsrc + (size_t)(kc + 3) * 16384 + i * 4096);
        }
        CP_COMMIT();
        if (++stage == 3) stage = 0;
    }

    const int u = lane >> 2, qq = (lane & 3) * 2;
    const float k2 = 0.0078125f;
#pragma unroll
    for (int mi = 0; mi < 4; mi++) {
        int r0 = bm * 128 + wm * 64 + mi * 16 + u;
        float sa0 = sA[r0], sa1 = sA[r0 + 8];
#pragma unroll
        for (int nt = 0; nt < 4; nt++) {
            int c0 = bn * 128 + wn * 32 + nt * 8 + qq;
            float sb0v = sB[c0], sb1v = sB[c0 + 1];
            float d0 = (float)acc1[mi][nt][0] + (float)acc2[mi][nt][0] * k2;
            float d1 = (float)acc1[mi][nt][1] + (float)acc2[mi][nt][1] * k2;
            float d2 = (float)acc1[mi][nt][2] + (float)acc2[mi][nt][2] * k2;
            float d3 = (float)acc1[mi][nt][3] + (float)acc2[mi][nt][3] * k2;
            *(float2*)(C + (size_t)r0 * N + c0)       = make_float2(sa0 * sb0v * d0, sa0 * sb1v * d1);
            *(float2*)(C + (size_t)(r0 + 8) * N + c0) = make_float2(sa1 * sb0v * d2, sa1 * sb1v * d3);
        }
    }
}

// ===========================================================================
// Fused Q/K norm+RoPE + V convert (unchanged, passing).
// ===========================================================================
__global__ __launch_bounds__(128)
void norm_rope_cvt(const float* __restrict__ qkv, __half* __restrict__ qo,
                   __half* __restrict__ ko, __half* __restrict__ vo,
                   const float* __restrict__ cs, const float* __restrict__ sn,
                   const float* __restrict__ qw, const float* __restrict__ kw)
{
    const int s = blockIdx.x, h = blockIdx.y, d = threadIdx.x;

    if (h >= 24) {
        int c = (h - 24) * 128 + d;
        vo[(size_t)s * KVDIM + c] = __float2half_rn(qkv[(size_t)s * QKVN + 3072 + c]);
        return;
    }
    const bool isq = h < 16;
    const int hh = isq ? h : h - 16;
    const float* w = isq ? qw : kw;
    const float scale = isq ? (float)QSCALE : 1.0f;
    const float v = qkv[(size_t)s * QKVN + (isq ? 0 : 2048) + hh * HD + d];

    float ss = v * v;
#pragma unroll
    for (int o = 16; o; o >>= 1) ss += __shfl_xor_sync(0xffffffffu, ss, o);

    __shared__ float red[4];
    __shared__ float sh[128];
    const int lane = d & 31, wid = d >> 5;
    if (lane == 0) red[wid] = ss;
    __syncthreads();
    float tot = red[0] + red[1] + red[2] + red[3];
    float r = rsqrtf(tot * (1.0f / 128.0f) + 1e-6f);
    float xn = v * r * w[d];
    sh[d] = xn;
    __syncthreads();
    float partner = sh[d ^ 64];
    float c  = cs[s * HD + d];
    float si = sn[s * HD + d];
    float outv = (xn * c + (d < 64 ? -partner : partner) * si) * scale;
    __half* out = isq ? (qo + (size_t)s * QDIM + hh * HD + d)
                      : (ko + (size_t)s * KVDIM + hh * HD + d);
    *out = __float2half_rn(outv);
}

// ===========================================================================
// fp16 flash attention, 128-row Q tiles, 256 thr = 8 warps, log2 softmax.
// grid (SEQ/128, NH) reversed. smem: Q 32KB + K 16KB + V 16KB = 64KB.
// ===========================================================================
__global__ __launch_bounds__(256)
void flash_f16()
{
    extern __shared__ uint8_t smf[];
    const uint32_t sQ = smem_u32(smf);      // 128 rows x 256B
    const uint32_t sK = sQ + 32768;         // 64 rows x 256B
    const uint32_t sV = sK + 16384;

    const int tid = threadIdx.x, lane = tid & 31, warp = tid >> 5;
    const int qb = gridDim.x - 1 - blockIdx.x;
    const int h = blockIdx.y, kvh = h >> 1;
    const int q2 = lane & 3, u = lane >> 2;
    const uint32_t ONES2 = 0x3C003C00u;

    {
        const uint8_t* Qg = (const uint8_t*)(g_qh + ((size_t)(qb * 128) * NH + h) * HD);
#pragma unroll
        for (int j = 0; j < 8; j++) {
            int idx = tid + j * 256;
            int row = idx >> 4, g = idx & 15;
            cp16(sQ + row * 256 + ((g ^ (row & 7)) << 4),
                 Qg + (size_t)row * NH * HD * 2 + g * 16);
        }
        CP_COMMIT();
    }
    CP_WAIT0();
    __syncthreads();

    uint32_t qf[8][4];
    {
        int row = warp * 16 + (lane & 7) + ((lane >> 3) & 1) * 8;
        int go  = lane >> 4;
        uint32_t rb = sQ + row * 256;
        int rw = (row & 7);
#pragma unroll
        for (int ks = 0; ks < 8; ks++)
            ldsm4(qf[ks], rb + (((2 * ks + go) ^ rw) << 4));
    }

    float o[16][4];
#pragma unroll
    for (int i = 0; i < 16; i++)
#pragma unroll
        for (int r = 0; r < 4; r++) o[i][r] = 0.f;
    float m0 = -1e30f, m1 = -1e30f, l0 = 0.f, l1 = 0.f;

    const int kkey = lane & 7;
    const int kgo  = lane >> 3;
    const int vkey = (lane & 7) + ((lane >> 3) & 1) * 8;
    const int vgo  = lane >> 4;

    const int njb = 2 * qb + 2;
    for (int jb = 0; jb < njb; jb++) {
        __syncthreads();
        {
            const uint8_t* Kg = (const uint8_t*)(g_kh + ((size_t)(jb * 64) * NKV + kvh) * HD);
            const uint8_t* Vg = (const uint8_t*)(g_vh + ((size_t)(jb * 64) * NKV + kvh) * HD);
#pragma unroll
            for (int j = 0; j < 4; j++) {
                int idx = tid + j * 256;
                int row = idx >> 4, g = idx & 15;
                uint32_t off = row * 256 + ((g ^ (row & 7)) << 4);
                size_t gsrc = (size_t)row * NKV * HD * 2 + g * 16;
                cp16(sK + off, Kg + gsrc);
                cp16(sV + off, Vg + gsrc);
            }
            CP_COMMIT();
        }
        CP_WAIT0();
        __syncthreads();

        float s[8][4];
#pragma unroll
        for (int nt = 0; nt < 8; nt++)
#pragma unroll
            for (int r = 0; r < 4; r++) s[nt][r] = 0.f;

#pragma unroll
        for (int g2 = 0; g2 < 4; g2++) {
#pragma unroll
            for (int nt = 0; nt < 8; nt++) {
                int key = 8 * nt + kkey;
                uint32_t bf[4];
                ldsm4(bf, sK + key * 256 + (((4 * g2 + kgo) ^ (key & 7)) << 4));
                mma_f16(s[nt], qf[2 * g2],     bf[0], bf[1]);
                mma_f16(s[nt], qf[2 * g2 + 1], bf[2], bf[3]);
            }
        }

        if (jb >= 2 * qb) {   // only the last two tiles can cross the diagonal
            int r0g = qb * 128 + warp * 16 + u;
            int cb = jb * 64 + q2 * 2;
#pragma unroll
            for (int nt = 0; nt < 8; nt++) {
                int c = cb + nt * 8;
                if (c     > r0g)     s[nt][0] = -1e30f;
                if (c + 1 > r0g)     s[nt][1] = -1e30f;
                if (c     > r0g + 8) s[nt][2] = -1e30f;
                if (c + 1 > r0g + 8) s[nt][3] = -1e30f;
            }
        }

        float mx0 = -1e30f, mx1 = -1e30f;
#pragma unroll
        for (int nt = 0; nt < 8; nt++) {
            mx0 = fmaxf(mx0, fmaxf(s[nt][0], s[nt][1]));
            mx1 = fmaxf(mx1, fmaxf(s[nt][2], s[nt][3]));
        }
        mx0 = fmaxf(mx0, __shfl_xor_sync(0xffffffffu, mx0, 1));
        mx0 = fmaxf(mx0, __shfl_xor_sync(0xffffffffu, mx0, 2));
        mx1 = fmaxf(mx1, __shfl_xor_sync(0xffffffffu, mx1, 1));
        mx1 = fmaxf(mx1, __shfl_xor_sync(0xffffffffu, mx1, 2));
        float mn0 = fmaxf(m0, mx0), mn1 = fmaxf(m1, mx1);
        float cf0 = exp2s(m0 - mn0), cf1 = exp2s(m1 - mn1);
        m0 = mn0; m1 = mn1;

        uint32_t pf[4][4];
#pragma unroll
        for (int kt = 0; kt < 4; kt++) {
            pf[kt][0] = exp2h2(s[2*kt][0]   - mn0, s[2*kt][1]   - mn0);
            pf[kt][1] = exp2h2(s[2*kt][2]   - mn1, s[2*kt][3]   - mn1);
            pf[kt][2] = exp2h2(s[2*kt+1][0] - mn0, s[2*kt+1][1] - mn0);
            pf[kt][3] = exp2h2(s[2*kt+1][2] - mn1, s[2*kt+1][3] - mn1);
        }

        float rsd[4] = {0.f, 0.f, 0.f, 0.f};
#pragma unroll
        for (int kt = 0; kt < 4; kt++)
            mma_f16(rsd, pf[kt], ONES2, ONES2);

        l0 = l0 * cf0 + rsd[0];
        l1 = l1 * cf1 + rsd[2];
#pragma unroll
        for (int nt2 = 0; nt2 < 16; nt2++) {
            o[nt2][0] *= cf0; o[nt2][1] *= cf0;
            o[nt2][2] *= cf1; o[nt2][3] *= cf1;
        }

#pragma unroll
        for (int ks = 0; ks < 4; ks++) {
#pragma unroll
            for (int np = 0; np < 8; np++) {
                int key = 16 * ks + vkey;
                uint32_t vf[4];
                ldsm4t(vf, sV + key * 256 + (((2 * np + vgo) ^ (key & 7)) << 4));
                mma_f16(o[2 * np],     pf[ks], vf[0], vf[1]);
                mma_f16(o[2 * np + 1], pf[ks], vf[2], vf[3]);
            }
        }
    }

    float r0i = 1.f / l0, r1i = 1.f / l1;
    int grow = qb * 128 + warp * 16 + u;
#pragma unroll
    for (int nt2 = 0; nt2 < 16; nt2++) {
        int col = h * HD + nt2 * 8 + q2 * 2;
        *(float2*)(g_attn + (size_t)grow * QDIM + col) =
            make_float2(o[nt2][0] * r0i, o[nt2][1] * r0i);
        *(float2*)(g_attn + (size_t)(grow + 8) * QDIM + col) =
            make_float2(o[nt2][2] * r1i, o[nt2][3] * r1i);
    }
}

// ===========================================================================
extern "C" void kernel_launch(void* const* d_in, const int* in_sizes, int n_in,
                              void* d_out, int out_size)
{
    const float* hid  = (const float*)d_in[0];
    const float* cosp = (const float*)d_in[1];
    const float* sinp = (const float*)d_in[2];
    const float* wq   = (const float*)d_in[3];
    const float* wk   = (const float*)d_in[4];
    const float* wv   = (const float*)d_in[5];
    const float* wo   = (const float*)d_in[6];
    const float* qw   = (const float*)d_in[7];
    const float* kw   = (const float*)d_in[8];
    float* out = (float*)d_out;

    float *qkv, *ab;
    cudaGetSymbolAddress((void**)&qkv, g_qkv);
    cudaGetSymbolAddress((void**)&ab, g_attn);
    __half *qh, *kh, *vh;
    cudaGetSymbolAddress((void**)&qh, g_qh);
    cudaGetSymbolAddress((void**)&kh, g_kh);
    cudaGetSymbolAddress((void**)&vh, g_vh);
    uint8_t *pa, *pw, *pwo;
    cudaGetSymbolAddress((void**)&pa,  g_pa);
    cudaGetSymbolAddress((void**)&pw,  g_pw);
    cudaGetSymbolAddress((void**)&pwo, g_pwo);
    float *sa, *sw, *swo;
    cudaGetSymbolAddress((void**)&sa,  g_sa);
    cudaGetSymbolAddress((void**)&sw,  g_sw);
    cudaGetSymbolAddress((void**)&swo, g_swo);

    const int GEMM_SMEM  = 98304;   // 3 stages x 32KB
    const int FLASH_SMEM = 65536;
    cudaFuncSetAttribute(gemm_i8, cudaFuncAttributeMaxDynamicSharedMemorySize, GEMM_SMEM);
    cudaFuncSetAttribute(flash_f16, cudaFuncAttributeMaxDynamicSharedMemorySize, FLASH_SMEM);

    pack_quant<<<SEQ / 8, 256>>>(hid, pa, sa);
    pack_quant<<<QDIM / 8, 256>>>(wq, pw, sw);
    pack_quant<<<KVDIM / 8, 256>>>(wk, pw + (size_t)QDIM * KDIM * 2, sw + QDIM);
    pack_quant<<<KVDIM / 8, 256>>>(wv, pw + (size_t)(QDIM + KVDIM) * KDIM * 2, sw + QDIM + KVDIM);
    pack_quant<<<HID / 8, 256>>>(wo, pwo, swo);

    gemm_i8<<<dim3(QKVN / 128, SEQ / 128), 256, GEMM_SMEM>>>(pa, pw, sa, sw, qkv, QKVN);

    norm_rope_cvt<<<dim3(SEQ, 32), 128>>>(qkv, qh, kh, vh, cosp, sinp, qw, kw);

    flash_f16<<<dim3(SEQ / 128, NH), 256, FLASH_SMEM>>>();

    pack_quant<<<SEQ / 8, 256>>>(ab, pa, sa);
    gemm_i8<<<dim3(HID / 128, SEQ / 128), 256, GEMM_SMEM>>>(pa, pwo, sa, swo, out, HID);
}

// round 9
// speedup vs baseline: 8.4743x; 1.0416x over previous
#include <cuda_runtime.h>
#include <cuda_fp16.h>
#include <cstdint>

#define SEQ   4096
#define HID   2048
#define NH    16
#define NKV   8
#define HD    128
#define QDIM  (NH*HD)    // 2048
#define KVDIM (NKV*HD)   // 1024
#define KDIM  2048
#define KC    (KDIM/64)  // 32
#define QKVN  4096
#define QSCALE (0.08838834764831845f * 1.4426950408889634f)

// fp32 intermediates
__device__ float g_qkv[(size_t)SEQ * QKVN];
__device__ float g_attn[(size_t)SEQ * QDIM];

// fp16 flash operands
__device__ __half g_qh[SEQ * QDIM];
__device__ __half g_kh[SEQ * KVDIM];
__device__ __half g_vh[SEQ * KVDIM];

// int8 2-term packed operands + per-row scales
__device__ uint8_t g_pa[(size_t)SEQ * KDIM * 2];
__device__ uint8_t g_pw[(size_t)QKVN * KDIM * 2];
__device__ uint8_t g_pwo[(size_t)HID * KDIM * 2];
__device__ float g_sa[SEQ];
__device__ float g_sw[QKVN], g_swo[HID];

__device__ __forceinline__ void mma_i8(int* d,
    const uint32_t* a, uint32_t b0, uint32_t b1)
{
    asm volatile(
        "mma.sync.aligned.m16n8k32.row.col.s32.s8.s8.s32 "
        "{%0,%1,%2,%3}, {%4,%5,%6,%7}, {%8,%9}, {%0,%1,%2,%3};\n"
        : "+r"(d[0]), "+r"(d[1]), "+r"(d[2]), "+r"(d[3])
        : "r"(a[0]), "r"(a[1]), "r"(a[2]), "r"(a[3]), "r"(b0), "r"(b1));
}
__device__ __forceinline__ void mma_f16(float* d,
    const uint32_t* a, uint32_t b0, uint32_t b1)
{
    asm volatile(
        "mma.sync.aligned.m16n8k16.row.col.f32.f16.f16.f32 "
        "{%0,%1,%2,%3}, {%4,%5,%6,%7}, {%8,%9}, {%0,%1,%2,%3};\n"
        : "+f"(d[0]), "+f"(d[1]), "+f"(d[2]), "+f"(d[3])
        : "r"(a[0]), "r"(a[1]), "r"(a[2]), "r"(a[3]), "r"(b0), "r"(b1));
}
__device__ __forceinline__ void ldsm4(uint32_t* r, uint32_t addr) {
    asm volatile("ldmatrix.sync.aligned.m8n8.x4.shared.b16 {%0,%1,%2,%3}, [%4];"
                 : "=r"(r[0]), "=r"(r[1]), "=r"(r[2]), "=r"(r[3]) : "r"(addr));
}
__device__ __forceinline__ void ldsm4t(uint32_t* r, uint32_t addr) {
    asm volatile("ldmatrix.sync.aligned.m8n8.x4.trans.shared.b16 {%0,%1,%2,%3}, [%4];"
                 : "=r"(r[0]), "=r"(r[1]), "=r"(r[2]), "=r"(r[3]) : "r"(addr));
}
__device__ __forceinline__ uint32_t smem_u32(const void* p) {
    uint32_t a;
    asm("{ .reg .u64 t; cvta.to.shared.u64 t, %1; cvt.u32.u64 %0, t; }" : "=r"(a) : "l"(p));
    return a;
}
__device__ __forceinline__ void cp16(uint32_t d, const void* g) {
    asm volatile("cp.async.cg.shared.global [%0], [%1], 16;" :: "r"(d), "l"(g));
}
#define CP_COMMIT() asm volatile("cp.async.commit_group;")
#define CP_WAIT2()  asm volatile("cp.async.wait_group 2;")
#define CP_WAIT1()  asm volatile("cp.async.wait_group 1;")
#define CP_WAIT0()  asm volatile("cp.async.wait_group 0;")

__device__ __forceinline__ uint32_t exp2h2(float a, float b) {
    __half2 h = __floats2half2_rn(a, b);
    uint32_t x = *(uint32_t*)&h, r;
    asm("ex2.approx.f16x2 %0, %1;" : "=r"(r) : "r"(x));
    return r;
}
__device__ __forceinline__ float exp2s(float x) {
    float r; asm("ex2.approx.f32 %0, %1;" : "=f"(r) : "f"(x)); return r;
}

// ===========================================================================
// pack_quant (unchanged, passing)
// ===========================================================================
__global__ __launch_bounds__(256)
void pack_quant(const float* __restrict__ src, uint8_t* __restrict__ dst,
                float* __restrict__ scl)
{
    const int warp = threadIdx.x >> 5, lane = threadIdx.x & 31;
    const int row = blockIdx.x * 8 + warp;
    const float* s = src + (size_t)row * KDIM;

    float4 v[16];
    float mx = 0.f;
#pragma unroll
    for (int j = 0; j < 16; j++) {
        v[j] = *(const float4*)(s + lane * 4 + j * 128);
        mx = fmaxf(mx, fmaxf(fmaxf(fabsf(v[j].x), fabsf(v[j].y)),
                             fmaxf(fabsf(v[j].z), fabsf(v[j].w))));
    }
#pragma unroll
    for (int o = 16; o; o >>= 1) mx = fmaxf(mx, __shfl_xor_sync(0xffffffffu, mx, o));

    const float s1   = mx * (1.f / 127.f);
    const float inv1 = mx > 0.f ? 127.f / mx : 0.f;
    const float inv2 = inv1 * 128.f;
    if (lane == 0) scl[row] = s1;

    const int rt = row >> 7, rr = row & 127, sw = rr & 7;
    uint8_t* tbase0 = dst + ((size_t)rt * KC) * 16384 + rr * 128;

#pragma unroll
    for (int j = 0; j < 16; j++) {
        int k = lane * 4 + j * 128;
        int c = k >> 6, w16 = (k >> 4) & 3, bin = k & 15;
        float4 x = v[j];
        int q0 = __float2int_rn(x.x * inv1), q1 = __float2int_rn(x.y * inv1);
        int q2 = __float2int_rn(x.z * inv1), q3 = __float2int_rn(x.w * inv1);
        int r0 = __float2int_rn((x.x - q0 * s1) * inv2);
        int r1 = __float2int_rn((x.y - q1 * s1) * inv2);
        int r2 = __float2int_rn((x.z - q2 * s1) * inv2);
        int r3 = __float2int_rn((x.w - q3 * s1) * inv2);
        uint8_t* tb = tbase0 + c * 16384;
        *(char4*)(tb + (((w16     ^ sw) << 4) + bin)) =
            make_char4((char)q0, (char)q1, (char)q2, (char)q3);
        *(char4*)(tb + ((((w16+4) ^ sw) << 4) + bin)) =
            make_char4((char)r0, (char)r1, (char)r2, (char)r3);
    }
}

// ===========================================================================
// gemm_i8: 3-term int8 mma, 128x128 tile, 3-stage cp.async (unchanged).
// ===========================================================================
__global__ __launch_bounds__(256)
void gemm_i8(const uint8_t* __restrict__ Ap, const uint8_t* __restrict__ Bp,
             const float* __restrict__ sA, const float* __restrict__ sB,
             float* __restrict__ C, int N)
{
    extern __shared__ uint8_t smi[];
    const uint32_t sb0 = smem_u32(smi);
    const int tid = threadIdx.x, lane = tid & 31, warp = tid >> 5;
    const int wm = warp >> 2, wn = warp & 3;
    const int bn = blockIdx.x, bm = blockIdx.y;

    const uint8_t* Asrc = Ap + (size_t)bm * KC * 16384 + tid * 16;
    const uint8_t* Bsrc = Bp + (size_t)bn * KC * 16384 + tid * 16;

    int acc1[4][4][4] = {}, acc2[4][4][4] = {};

    const int arow = wm * 64 + (lane & 7) + ((lane >> 3) & 1) * 8;
    const int akh  = lane >> 4;
    const int aw   = arow & 7;
    const int brow = wn * 32 + (lane & 7) + (lane >> 4) * 8;
    const int bkh  = (lane >> 3) & 1;
    const int bw   = brow & 7;

#pragma unroll
    for (int pre = 0; pre < 3; pre++) {
        uint32_t d = sb0 + pre * 32768 + tid * 16;
#pragma unroll
        for (int i = 0; i < 4; i++) cp16(d + i * 4096,         Asrc + (size_t)pre * 16384 + i * 4096);
#pragma unroll
        for (int i = 0; i < 4; i++) cp16(d + 16384 + i * 4096, Bsrc + (size_t)pre * 16384 + i * 4096);
        CP_COMMIT();
    }

    int stage = 0;
    for (int kc = 0; kc < KC; kc++) {
        CP_WAIT2();
        __syncthreads();
        const uint32_t stA = sb0 + stage * 32768, stB = stA + 16384;

#pragma unroll
        for (int s = 0; s < 2; s++) {
            uint32_t a1f[4][4], a2f[4][4];
            const int ga = 2 * s + akh;
#pragma unroll
            for (int mi = 0; mi < 4; mi++) {
                uint32_t ad = stA + (uint32_t)(arow + mi * 16) * 128;
                ldsm4(a1f[mi], ad + (uint32_t)(((ga     ^ aw) << 4)));
                ldsm4(a2f[mi], ad + (uint32_t)((((ga+4) ^ aw) << 4)));
            }
            const int gb = 2 * s + bkh;
#pragma unroll
            for (int nj = 0; nj < 2; nj++) {
                uint32_t bd = stB + (uint32_t)(brow + nj * 16) * 128;
                uint32_t b1f[4], b2f[4];
                ldsm4(b1f, bd + (uint32_t)(((gb     ^ bw) << 4)));
                ldsm4(b2f, bd + (uint32_t)((((gb+4) ^ bw) << 4)));
#pragma unroll
                for (int mi = 0; mi < 4; mi++) {
                    mma_i8(acc1[mi][2*nj],   a1f[mi], b1f[0], b1f[1]);
                    mma_i8(acc1[mi][2*nj+1], a1f[mi], b1f[2], b1f[3]);
                    mma_i8(acc2[mi][2*nj],   a1f[mi], b2f[0], b2f[1]);
                    mma_i8(acc2[mi][2*nj+1], a1f[mi], b2f[2], b2f[3]);
                    mma_i8(acc2[mi][2*nj],   a2f[mi], b1f[0], b1f[1]);
                    mma_i8(acc2[mi][2*nj+1], a2f[mi], b1f[2], b1f[3]);
                }
            }
        }
        __syncthreads();
        if (kc + 3 < KC) {
            uint32_t d = sb0 + stage * 32768 + tid * 16;
#pragma unroll
            for (int i = 0; i < 4; i++) cp16(d + i * 4096,         Asrc + (size_t)(kc + 3) * 16384 + i * 4096);
#pragma unroll
            for (int i = 0; i < 4; i++) cp16(d + 16384 + i * 4096, Bsrc + (size_t)(kc + 3) * 16384 + i * 4096);
        }
        CP_COMMIT();
        if (++stage == 3) stage = 0;
    }

    const int u = lane >> 2, qq = (lane & 3) * 2;
    const float k2 = 0.0078125f;
#pragma unroll
    for (int mi = 0; mi < 4; mi++) {
        int r0 = bm * 128 + wm * 64 + mi * 16 + u;
        float sa0 = sA[r0], sa1 = sA[r0 + 8];
#pragma unroll
        for (int nt = 0; nt < 4; nt++) {
            int c0 = bn * 128 + wn * 32 + nt * 8 + qq;
            float sb0v = sB[c0], sb1v = sB[c0 + 1];
            float d0 = (float)acc1[mi][nt][0] + (float)acc2[mi][nt][0] * k2;
            float d1 = (float)acc1[mi][nt][1] + (float)acc2[mi][nt][1] * k2;
            float d2 = (float)acc1[mi][nt][2] + (float)acc2[mi][nt][2] * k2;
            float d3 = (float)acc1[mi][nt][3] + (float)acc2[mi][nt][3] * k2;
            *(float2*)(C + (size_t)r0 * N + c0)       = make_float2(sa0 * sb0v * d0, sa0 * sb1v * d1);
            *(float2*)(C + (size_t)(r0 + 8) * N + c0) = make_float2(sa1 * sb0v * d2, sa1 * sb1v * d3);
        }
    }
}

// ===========================================================================
// Fused Q/K norm+RoPE + V convert (unchanged, passing).
// ===========================================================================
__global__ __launch_bounds__(128)
void norm_rope_cvt(const float* __restrict__ qkv, __half* __restrict__ qo,
                   __half* __restrict__ ko, __half* __restrict__ vo,
                   const float* __restrict__ cs, const float* __restrict__ sn,
                   const float* __restrict__ qw, const float* __restrict__ kw)
{
    const int s = blockIdx.x, h = blockIdx.y, d = threadIdx.x;

    if (h >= 24) {
        int c = (h - 24) * 128 + d;
        vo[(size_t)s * KVDIM + c] = __float2half_rn(qkv[(size_t)s * QKVN + 3072 + c]);
        return;
    }
    const bool isq = h < 16;
    const int hh = isq ? h : h - 16;
    const float* w = isq ? qw : kw;
    const float scale = isq ? (float)QSCALE : 1.0f;
    const float v = qkv[(size_t)s * QKVN + (isq ? 0 : 2048) + hh * HD + d];

    float ss = v * v;
#pragma unroll
    for (int o = 16; o; o >>= 1) ss += __shfl_xor_sync(0xffffffffu, ss, o);

    __shared__ float red[4];
    __shared__ float sh[128];
    const int lane = d & 31, wid = d >> 5;
    if (lane == 0) red[wid] = ss;
    __syncthreads();
    float tot = red[0] + red[1] + red[2] + red[3];
    float r = rsqrtf(tot * (1.0f / 128.0f) + 1e-6f);
    float xn = v * r * w[d];
    sh[d] = xn;
    __syncthreads();
    float partner = sh[d ^ 64];
    float c  = cs[s * HD + d];
    float si = sn[s * HD + d];
    float outv = (xn * c + (d < 64 ? -partner : partner) * si) * scale;
    __half* out = isq ? (qo + (size_t)s * QDIM + hh * HD + d)
                      : (ko + (size_t)s * KVDIM + hh * HD + d);
    *out = __float2half_rn(outv);
}

// ===========================================================================
// fp16 flash attention, 128-row Q tiles, DOUBLE-BUFFERED K/V (96KB smem).
// grid (SEQ/128, NH) reversed, 256 thr = 8 warps, log2 softmax.
// Prefetch of tile jb+1 overlaps compute of tile jb.
// ===========================================================================
__global__ __launch_bounds__(256)
void flash_f16()
{
    extern __shared__ uint8_t smf[];
    const uint32_t sQ = smem_u32(smf);          // 128 rows x 256B = 32KB
    const uint32_t sKV0 = sQ + 32768;           // stage stride 32KB (K16+V16)

    const int tid = threadIdx.x, lane = tid & 31, warp = tid >> 5;
    const int qb = gridDim.x - 1 - blockIdx.x;
    const int h = blockIdx.y, kvh = h >> 1;
    const int q2 = lane & 3, u = lane >> 2;
    const uint32_t ONES2 = 0x3C003C00u;

    const uint8_t* Kg0 = (const uint8_t*)(g_kh + (size_t)kvh * HD);
    const uint8_t* Vg0 = (const uint8_t*)(g_vh + (size_t)kvh * HD);
    const int njb = 2 * qb + 2;

    // per-thread K/V load coords (16 granules x 64 rows, 4 iters of 256 thr)
    // group 0: Q tile; group 1: KV tile 0
    {
        const uint8_t* Qg = (const uint8_t*)(g_qh + ((size_t)(qb * 128) * NH + h) * HD);
#pragma unroll
        for (int j = 0; j < 8; j++) {
            int idx = tid + j * 256;
            int row = idx >> 4, g = idx & 15;
            cp16(sQ + row * 256 + ((g ^ (row & 7)) << 4),
                 Qg + (size_t)row * NH * HD * 2 + g * 16);
        }
        CP_COMMIT();
    }
    {
        uint32_t sK = sKV0, sV = sKV0 + 16384;
#pragma unroll
        for (int j = 0; j < 4; j++) {
            int idx = tid + j * 256;
            int row = idx >> 4, g = idx & 15;
            uint32_t off = row * 256 + ((g ^ (row & 7)) << 4);
            size_t gsrc = (size_t)row * NKV * HD * 2 + g * 16;
            cp16(sK + off, Kg0 + gsrc);
            cp16(sV + off, Vg0 + gsrc);
        }
        CP_COMMIT();
    }

    CP_WAIT1();          // Q resident (KV0 may be in flight)
    __syncthreads();

    uint32_t qf[8][4];
    {
        int row = warp * 16 + (lane & 7) + ((lane >> 3) & 1) * 8;
        int go  = lane >> 4;
        uint32_t rb = sQ + row * 256;
        int rw = (row & 7);
#pragma unroll
        for (int ks = 0; ks < 8; ks++)
            ldsm4(qf[ks], rb + (((2 * ks + go) ^ rw) << 4));
    }

    float o[16][4];
#pragma unroll
    for (int i = 0; i < 16; i++)
#pragma unroll
        for (int r = 0; r < 4; r++) o[i][r] = 0.f;
    float m0 = -1e30f, m1 = -1e30f, l0 = 0.f, l1 = 0.f;

    const int kkey = lane & 7;
    const int kgo  = lane >> 3;
    const int vkey = (lane & 7) + ((lane >> 3) & 1) * 8;
    const int vgo  = lane >> 4;

    for (int jb = 0; jb < njb; jb++) {
        // all warps done reading the alternate stage from iteration jb-1
        __syncthreads();
        if (jb + 1 < njb) {   // prefetch next tile into alternate stage
            uint32_t st = sKV0 + ((jb + 1) & 1) * 32768;
            const uint8_t* Kg = Kg0 + (size_t)((jb + 1) * 64) * NKV * HD * 2;
            const uint8_t* Vg = Vg0 + (size_t)((jb + 1) * 64) * NKV * HD * 2;
#pragma unroll
            for (int j = 0; j < 4; j++) {
                int idx = tid + j * 256;
                int row = idx >> 4, g = idx & 15;
                uint32_t off = row * 256 + ((g ^ (row & 7)) << 4);
                size_t gsrc = (size_t)row * NKV * HD * 2 + g * 16;
                cp16(st + off, Kg + gsrc);
                cp16(st + 16384 + off, Vg + gsrc);
            }
        }
        CP_COMMIT();
        CP_WAIT1();          // current stage resident; prefetch in flight
        __syncthreads();

        const uint32_t sK = sKV0 + (jb & 1) * 32768, sV = sK + 16384;

        float s[8][4];
#pragma unroll
        for (int nt = 0; nt < 8; nt++)
#pragma unroll
            for (int r = 0; r < 4; r++) s[nt][r] = 0.f;

#pragma unroll
        for (int g2 = 0; g2 < 4; g2++) {
#pragma unroll
            for (int nt = 0; nt < 8; nt++) {
                int key = 8 * nt + kkey;
                uint32_t bf[4];
                ldsm4(bf, sK + key * 256 + (((4 * g2 + kgo) ^ (key & 7)) << 4));
                mma_f16(s[nt], qf[2 * g2],     bf[0], bf[1]);
                mma_f16(s[nt], qf[2 * g2 + 1], bf[2], bf[3]);
            }
        }

        if (jb >= 2 * qb) {
            int r0g = qb * 128 + warp * 16 + u;
            int cb = jb * 64 + q2 * 2;
#pragma unroll
            for (int nt = 0; nt < 8; nt++) {
                int c = cb + nt * 8;
                if (c     > r0g)     s[nt][0] = -1e30f;
                if (c + 1 > r0g)     s[nt][1] = -1e30f;
                if (c     > r0g + 8) s[nt][2] = -1e30f;
                if (c + 1 > r0g + 8) s[nt][3] = -1e30f;
            }
        }

        float mx0 = -1e30f, mx1 = -1e30f;
#pragma unroll
        for (int nt = 0; nt < 8; nt++) {
            mx0 = fmaxf(mx0, fmaxf(s[nt][0], s[nt][1]));
            mx1 = fmaxf(mx1, fmaxf(s[nt][2], s[nt][3]));
        }
        mx0 = fmaxf(mx0, __shfl_xor_sync(0xffffffffu, mx0, 1));
        mx0 = fmaxf(mx0, __shfl_xor_sync(0xffffffffu, mx0, 2));
        mx1 = fmaxf(mx1, __shfl_xor_sync(0xffffffffu, mx1, 1));
        mx1 = fmaxf(mx1, __shfl_xor_sync(0xffffffffu, mx1, 2));
        float mn0 = fmaxf(m0, mx0), mn1 = fmaxf(m1, mx1);
        float cf0 = exp2s(m0 - mn0), cf1 = exp2s(m1 - mn1);
        m0 = mn0; m1 = mn1;

        uint32_t pf[4][4];
#pragma unroll
        for (int kt = 0; kt < 4; kt++) {
            pf[kt][0] = exp2h2(s[2*kt][0]   - mn0, s[2*kt][1]   - mn0);
            pf[kt][1] = exp2h2(s[2*kt][2]   - mn1, s[2*kt][3]   - mn1);
            pf[kt][2] = exp2h2(s[2*kt+1][0] - mn0, s[2*kt+1][1] - mn0);
            pf[kt][3] = exp2h2(s[2*kt+1][2] - mn1, s[2*kt+1][3] - mn1);
        }

        float rsd[4] = {0.f, 0.f, 0.f, 0.f};
#pragma unroll
        for (int kt = 0; kt < 4; kt++)
            mma_f16(rsd, pf[kt], ONES2, ONES2);

        l0 = l0 * cf0 + rsd[0];
        l1 = l1 * cf1 + rsd[2];
#pragma unroll
        for (int nt2 = 0; nt2 < 16; nt2++) {
            o[nt2][0] *= cf0; o[nt2][1] *= cf0;
            o[nt2][2] *= cf1; o[nt2][3] *= cf1;
        }

#pragma unroll
        for (int ks = 0; ks < 4; ks++) {
#pragma unroll
            for (int np = 0; np < 8; np++) {
                int key = 16 * ks + vkey;
                uint32_t vf[4];
                ldsm4t(vf, sV + key * 256 + (((2 * np + vgo) ^ (key & 7)) << 4));
                mma_f16(o[2 * np],     pf[ks], vf[0], vf[1]);
                mma_f16(o[2 * np + 1], pf[ks], vf[2], vf[3]);
            }
        }
    }

    float r0i = 1.f / l0, r1i = 1.f / l1;
    int grow = qb * 128 + warp * 16 + u;
#pragma unroll
    for (int nt2 = 0; nt2 < 16; nt2++) {
        int col = h * HD + nt2 * 8 + q2 * 2;
        *(float2*)(g_attn + (size_t)grow * QDIM + col) =
            make_float2(o[nt2][0] * r0i, o[nt2][1] * r0i);
        *(float2*)(g_attn + (size_t)(grow + 8) * QDIM + col) =
            make_float2(o[nt2][2] * r1i, o[nt2][3] * r1i);
    }
}

// ===========================================================================
extern "C" void kernel_launch(void* const* d_in, const int* in_sizes, int n_in,
                              void* d_out, int out_size)
{
    const float* hid  = (const float*)d_in[0];
    const float* cosp = (const float*)d_in[1];
    const float* sinp = (const float*)d_in[2];
    const float* wq   = (const float*)d_in[3];
    const float* wk   = (const float*)d_in[4];
    const float* wv   = (const float*)d_in[5];
    const float* wo   = (const float*)d_in[6];
    const float* qw   = (const float*)d_in[7];
    const float* kw   = (const float*)d_in[8];
    float* out = (float*)d_out;

    float *qkv, *ab;
    cudaGetSymbolAddress((void**)&qkv, g_qkv);
    cudaGetSymbolAddress((void**)&ab, g_attn);
    __half *qh, *kh, *vh;
    cudaGetSymbolAddress((void**)&qh, g_qh);
    cudaGetSymbolAddress((void**)&kh, g_kh);
    cudaGetSymbolAddress((void**)&vh, g_vh);
    uint8_t *pa, *pw, *pwo;
    cudaGetSymbolAddress((void**)&pa,  g_pa);
    cudaGetSymbolAddress((void**)&pw,  g_pw);
    cudaGetSymbolAddress((void**)&pwo, g_pwo);
    float *sa, *sw, *swo;
    cudaGetSymbolAddress((void**)&sa,  g_sa);
    cudaGetSymbolAddress((void**)&sw,  g_sw);
    cudaGetSymbolAddress((void**)&swo, g_swo);

    const int GEMM_SMEM  = 98304;
    const int FLASH_SMEM = 98304;   // Q 32KB + 2 x (K16+V16)
    cudaFuncSetAttribute(gemm_i8, cudaFuncAttributeMaxDynamicSharedMemorySize, GEMM_SMEM);
    cudaFuncSetAttribute(flash_f16, cudaFuncAttributeMaxDynamicSharedMemorySize, FLASH_SMEM);

    pack_quant<<<SEQ / 8, 256>>>(hid, pa, sa);
    pack_quant<<<QDIM / 8, 256>>>(wq, pw, sw);
    pack_quant<<<KVDIM / 8, 256>>>(wk, pw + (size_t)QDIM * KDIM * 2, sw + QDIM);
    pack_quant<<<KVDIM / 8, 256>>>(wv, pw + (size_t)(QDIM + KVDIM) * KDIM * 2, sw + QDIM + KVDIM);
    pack_quant<<<HID / 8, 256>>>(wo, pwo, swo);

    gemm_i8<<<dim3(QKVN / 128, SEQ / 128), 256, GEMM_SMEM>>>(pa, pw, sa, sw, qkv, QKVN);

    norm_rope_cvt<<<dim3(SEQ, 32), 128>>>(qkv, qh, kh, vh, cosp, sinp, qw, kw);

    flash_f16<<<dim3(SEQ / 128, NH), 256, FLASH_SMEM>>>();

    pack_quant<<<SEQ / 8, 256>>>(ab, pa, sa);
    gemm_i8<<<dim3(HID / 128, SEQ / 128), 256, GEMM_SMEM>>>(pa, pwo, sa, swo, out, HID);
}

// round 10
// speedup vs baseline: 9.1727x; 1.0824x over previous
#include <cuda_runtime.h>
#include <cuda_fp16.h>
#include <cstdint>

#define SEQ   4096
#define HID   2048
#define NH    16
#define NKV   8
#define HD    128
#define QDIM  (NH*HD)    // 2048
#define KVDIM (NKV*HD)   // 1024
#define KDIM  2048
#define KC    (KDIM/64)  // 32
#define QKVN  4096
#define QSCALE (0.08838834764831845f * 1.4426950408889634f)

// fp32 intermediates
__device__ float g_qkv[(size_t)SEQ * QKVN];
__device__ float g_attn[(size_t)SEQ * QDIM];

// fp16 flash operands
__device__ __half g_qh[SEQ * QDIM];
__device__ __half g_kh[SEQ * KVDIM];
__device__ __half g_vh[SEQ * KVDIM];

// int8 2-term packed operands + per-row scales
__device__ uint8_t g_pa[(size_t)SEQ * KDIM * 2];
__device__ uint8_t g_pw[(size_t)QKVN * KDIM * 2];
__device__ uint8_t g_pwo[(size_t)HID * KDIM * 2];
__device__ float g_sa[SEQ];
__device__ float g_sw[QKVN], g_swo[HID];

__device__ __forceinline__ void mma_i8(int* d,
    const uint32_t* a, uint32_t b0, uint32_t b1)
{
    asm volatile(
        "mma.sync.aligned.m16n8k32.row.col.s32.s8.s8.s32 "
        "{%0,%1,%2,%3}, {%4,%5,%6,%7}, {%8,%9}, {%0,%1,%2,%3};\n"
        : "+r"(d[0]), "+r"(d[1]), "+r"(d[2]), "+r"(d[3])
        : "r"(a[0]), "r"(a[1]), "r"(a[2]), "r"(a[3]), "r"(b0), "r"(b1));
}
__device__ __forceinline__ void mma_f16(float* d,
    const uint32_t* a, uint32_t b0, uint32_t b1)
{
    asm volatile(
        "mma.sync.aligned.m16n8k16.row.col.f32.f16.f16.f32 "
        "{%0,%1,%2,%3}, {%4,%5,%6,%7}, {%8,%9}, {%0,%1,%2,%3};\n"
        : "+f"(d[0]), "+f"(d[1]), "+f"(d[2]), "+f"(d[3])
        : "r"(a[0]), "r"(a[1]), "r"(a[2]), "r"(a[3]), "r"(b0), "r"(b1));
}
__device__ __forceinline__ void ldsm4(uint32_t* r, uint32_t addr) {
    asm volatile("ldmatrix.sync.aligned.m8n8.x4.shared.b16 {%0,%1,%2,%3}, [%4];"
                 : "=r"(r[0]), "=r"(r[1]), "=r"(r[2]), "=r"(r[3]) : "r"(addr));
}
__device__ __forceinline__ void ldsm4t(uint32_t* r, uint32_t addr) {
    asm volatile("ldmatrix.sync.aligned.m8n8.x4.trans.shared.b16 {%0,%1,%2,%3}, [%4];"
                 : "=r"(r[0]), "=r"(r[1]), "=r"(r[2]), "=r"(r[3]) : "r"(addr));
}
__device__ __forceinline__ uint32_t smem_u32(const void* p) {
    uint32_t a;
    asm("{ .reg .u64 t; cvta.to.shared.u64 t, %1; cvt.u32.u64 %0, t; }" : "=r"(a) : "l"(p));
    return a;
}
__device__ __forceinline__ void cp16(uint32_t d, const void* g) {
    asm volatile("cp.async.cg.shared.global [%0], [%1], 16;" :: "r"(d), "l"(g));
}
#define CP_COMMIT() asm volatile("cp.async.commit_group;")
#define CP_WAIT2()  asm volatile("cp.async.wait_group 2;")
#define CP_WAIT1()  asm volatile("cp.async.wait_group 1;")
#define CP_WAIT0()  asm volatile("cp.async.wait_group 0;")

__device__ __forceinline__ uint32_t exp2h2(float a, float b) {
    __half2 h = __floats2half2_rn(a, b);
    uint32_t x = *(uint32_t*)&h, r;
    asm("ex2.approx.f16x2 %0, %1;" : "=r"(r) : "r"(x));
    return r;
}
__device__ __forceinline__ float exp2s(float x) {
    float r; asm("ex2.approx.f32 %0, %1;" : "=f"(r) : "f"(x)); return r;
}
__device__ __forceinline__ uint32_t pk2(float lo, float hi) {
    __half2 t = __floats2half2_rn(lo, hi);
    return *(uint32_t*)&t;
}

// ===========================================================================
// pack_quant (unchanged, passing)
// ===========================================================================
__global__ __launch_bounds__(256)
void pack_quant(const float* __restrict__ src, uint8_t* __restrict__ dst,
                float* __restrict__ scl)
{
    const int warp = threadIdx.x >> 5, lane = threadIdx.x & 31;
    const int row = blockIdx.x * 8 + warp;
    const float* s = src + (size_t)row * KDIM;

    float4 v[16];
    float mx = 0.f;
#pragma unroll
    for (int j = 0; j < 16; j++) {
        v[j] = *(const float4*)(s + lane * 4 + j * 128);
        mx = fmaxf(mx, fmaxf(fmaxf(fabsf(v[j].x), fabsf(v[j].y)),
                             fmaxf(fabsf(v[j].z), fabsf(v[j].w))));
    }
#pragma unroll
    for (int o = 16; o; o >>= 1) mx = fmaxf(mx, __shfl_xor_sync(0xffffffffu, mx, o));

    const float s1   = mx * (1.f / 127.f);
    const float inv1 = mx > 0.f ? 127.f / mx : 0.f;
    const float inv2 = inv1 * 128.f;
    if (lane == 0) scl[row] = s1;

    const int rt = row >> 7, rr = row & 127, sw = rr & 7;
    uint8_t* tbase0 = dst + ((size_t)rt * KC) * 16384 + rr * 128;

#pragma unroll
    for (int j = 0; j < 16; j++) {
        int k = lane * 4 + j * 128;
        int c = k >> 6, w16 = (k >> 4) & 3, bin = k & 15;
        float4 x = v[j];
        int q0 = __float2int_rn(x.x * inv1), q1 = __float2int_rn(x.y * inv1);
        int q2 = __float2int_rn(x.z * inv1), q3 = __float2int_rn(x.w * inv1);
        int r0 = __float2int_rn((x.x - q0 * s1) * inv2);
        int r1 = __float2int_rn((x.y - q1 * s1) * inv2);
        int r2 = __float2int_rn((x.z - q2 * s1) * inv2);
        int r3 = __float2int_rn((x.w - q3 * s1) * inv2);
        uint8_t* tb = tbase0 + c * 16384;
        *(char4*)(tb + (((w16     ^ sw) << 4) + bin)) =
            make_char4((char)q0, (char)q1, (char)q2, (char)q3);
        *(char4*)(tb + ((((w16+4) ^ sw) << 4) + bin)) =
            make_char4((char)r0, (char)r1, (char)r2, (char)r3);
    }
}

// ===========================================================================
// gemm_i8: 3-term int8 mma, 128x128 tile, 3-stage / SINGLE sync per chunk.
// Prologue issues chunks 0,1; iter kc refills chunk kc+2 into stage (kc+2)%3
// (free: compute of kc-1 fenced by this iteration's barrier).
// ===========================================================================
__global__ __launch_bounds__(256)
void gemm_i8(const uint8_t* __restrict__ Ap, const uint8_t* __restrict__ Bp,
             const float* __restrict__ sA, const float* __restrict__ sB,
             float* __restrict__ C, int N)
{
    extern __shared__ uint8_t smi[];
    const uint32_t sb0 = smem_u32(smi);
    const int tid = threadIdx.x, lane = tid & 31, warp = tid >> 5;
    const int wm = warp >> 2, wn = warp & 3;
    const int bn = blockIdx.x, bm = blockIdx.y;

    const uint8_t* Asrc = Ap + (size_t)bm * KC * 16384 + tid * 16;
    const uint8_t* Bsrc = Bp + (size_t)bn * KC * 16384 + tid * 16;

    int acc1[4][4][4] = {}, acc2[4][4][4] = {};

    const int arow = wm * 64 + (lane & 7) + ((lane >> 3) & 1) * 8;
    const int akh  = lane >> 4;
    const int aw   = arow & 7;
    const int brow = wn * 32 + (lane & 7) + (lane >> 4) * 8;
    const int bkh  = (lane >> 3) & 1;
    const int bw   = brow & 7;

#pragma unroll
    for (int pre = 0; pre < 2; pre++) {
        uint32_t d = sb0 + pre * 32768 + tid * 16;
#pragma unroll
        for (int i = 0; i < 4; i++) cp16(d + i * 4096,         Asrc + (size_t)pre * 16384 + i * 4096);
#pragma unroll
        for (int i = 0; i < 4; i++) cp16(d + 16384 + i * 4096, Bsrc + (size_t)pre * 16384 + i * 4096);
        CP_COMMIT();
    }

    for (int kc = 0; kc < KC; kc++) {
        CP_WAIT1();
        __syncthreads();
        if (kc + 2 < KC) {
            int st2 = (kc + 2) % 3;
            uint32_t d = sb0 + st2 * 32768 + tid * 16;
#pragma unroll
            for (int i = 0; i < 4; i++) cp16(d + i * 4096,         Asrc + (size_t)(kc + 2) * 16384 + i * 4096);
#pragma unroll
            for (int i = 0; i < 4; i++) cp16(d + 16384 + i * 4096, Bsrc + (size_t)(kc + 2) * 16384 + i * 4096);
        }
        CP_COMMIT();

        const uint32_t stA = sb0 + (kc % 3) * 32768, stB = stA + 16384;

#pragma unroll
        for (int s = 0; s < 2; s++) {
            uint32_t a1f[4][4], a2f[4][4];
            const int ga = 2 * s + akh;
#pragma unroll
            for (int mi = 0; mi < 4; mi++) {
                uint32_t ad = stA + (uint32_t)(arow + mi * 16) * 128;
                ldsm4(a1f[mi], ad + (uint32_t)(((ga     ^ aw) << 4)));
                ldsm4(a2f[mi], ad + (uint32_t)((((ga+4) ^ aw) << 4)));
            }
            const int gb = 2 * s + bkh;
#pragma unroll
            for (int nj = 0; nj < 2; nj++) {
                uint32_t bd = stB + (uint32_t)(brow + nj * 16) * 128;
                uint32_t b1f[4], b2f[4];
                ldsm4(b1f, bd + (uint32_t)(((gb     ^ bw) << 4)));
                ldsm4(b2f, bd + (uint32_t)((((gb+4) ^ bw) << 4)));
#pragma unroll
                for (int mi = 0; mi < 4; mi++) {
                    mma_i8(acc1[mi][2*nj],   a1f[mi], b1f[0], b1f[1]);
                    mma_i8(acc1[mi][2*nj+1], a1f[mi], b1f[2], b1f[3]);
                    mma_i8(acc2[mi][2*nj],   a1f[mi], b2f[0], b2f[1]);
                    mma_i8(acc2[mi][2*nj+1], a1f[mi], b2f[2], b2f[3]);
                    mma_i8(acc2[mi][2*nj],   a2f[mi], b1f[0], b1f[1]);
                    mma_i8(acc2[mi][2*nj+1], a2f[mi], b1f[2], b1f[3]);
                }
            }
        }
    }

    const int u = lane >> 2, qq = (lane & 3) * 2;
    const float k2 = 0.0078125f;
#pragma unroll
    for (int mi = 0; mi < 4; mi++) {
        int r0 = bm * 128 + wm * 64 + mi * 16 + u;
        float sa0 = sA[r0], sa1 = sA[r0 + 8];
#pragma unroll
        for (int nt = 0; nt < 4; nt++) {
            int c0 = bn * 128 + wn * 32 + nt * 8 + qq;
            float sb0v = sB[c0], sb1v = sB[c0 + 1];
            float d0 = (float)acc1[mi][nt][0] + (float)acc2[mi][nt][0] * k2;
            float d1 = (float)acc1[mi][nt][1] + (float)acc2[mi][nt][1] * k2;
            float d2 = (float)acc1[mi][nt][2] + (float)acc2[mi][nt][2] * k2;
            float d3 = (float)acc1[mi][nt][3] + (float)acc2[mi][nt][3] * k2;
            *(float2*)(C + (size_t)r0 * N + c0)       = make_float2(sa0 * sb0v * d0, sa0 * sb1v * d1);
            *(float2*)(C + (size_t)(r0 + 8) * N + c0) = make_float2(sa1 * sb0v * d2, sa1 * sb1v * d3);
        }
    }
}

// ===========================================================================
// norm_rope_cvt: WARP-PER-HEAD. grid (SEQ, 4), 256 thr = 8 warps.
//  y=0: Q heads 0-7   y=1: Q heads 8-15   y=2: K heads 0-7   y=3: V segments.
// RoPE partner d^64 lives in lane^16 (4 shuffles); 5-shuffle warp reduction;
// no smem, no block barriers. Same fp32 math as before -> same numerics.
// ===========================================================================
__global__ __launch_bounds__(256)
void norm_rope_cvt(const float* __restrict__ qkv, __half* __restrict__ qo,
                   __half* __restrict__ ko, __half* __restrict__ vo,
                   const float* __restrict__ cs, const float* __restrict__ sn,
                   const float* __restrict__ qw, const float* __restrict__ kw)
{
    const int s = blockIdx.x, y = blockIdx.y;
    const int warp = threadIdx.x >> 5, lane = threadIdx.x & 31;

    if (y == 3) {   // V convert: warp handles 128 contiguous elements
        int c = warp * 128 + lane * 4;
        float4 x = *(const float4*)(qkv + (size_t)s * QKVN + 3072 + c);
        uint2 p; p.x = pk2(x.x, x.y); p.y = pk2(x.z, x.w);
        *(uint2*)(vo + (size_t)s * KVDIM + c) = p;
        return;
    }
    const bool isq = y < 2;
    const int hh = isq ? (y * 8 + warp) : warp;
    const float* w = isq ? qw : kw;
    const float scale = isq ? (float)QSCALE : 1.0f;
    const int d0 = lane * 4;

    float4 x = *(const float4*)(qkv + (size_t)s * QKVN + (isq ? 0 : 2048) + hh * HD + d0);
    float ss = x.x * x.x + x.y * x.y + x.z * x.z + x.w * x.w;
#pragma unroll
    for (int o = 16; o; o >>= 1) ss += __shfl_xor_sync(0xffffffffu, ss, o);
    float r = rsqrtf(ss * (1.0f / 128.0f) + 1e-6f);

    float4 wv = *(const float4*)(w + d0);
    float xn0 = x.x * r * wv.x, xn1 = x.y * r * wv.y;
    float xn2 = x.z * r * wv.z, xn3 = x.w * r * wv.w;

    // partner values: element d^64 is in lane^16, same slot
    float p0 = __shfl_xor_sync(0xffffffffu, xn0, 16);
    float p1 = __shfl_xor_sync(0xffffffffu, xn1, 16);
    float p2 = __shfl_xor_sync(0xffffffffu, xn2, 16);
    float p3 = __shfl_xor_sync(0xffffffffu, xn3, 16);
    float sg = (lane < 16) ? -1.0f : 1.0f;

    float4 c4 = *(const float4*)(cs + s * HD + d0);
    float4 s4 = *(const float4*)(sn + s * HD + d0);
    float o0 = (xn0 * c4.x + sg * p0 * s4.x) * scale;
    float o1 = (xn1 * c4.y + sg * p1 * s4.y) * scale;
    float o2 = (xn2 * c4.z + sg * p2 * s4.z) * scale;
    float o3 = (xn3 * c4.w + sg * p3 * s4.w) * scale;

    uint2 pk; pk.x = pk2(o0, o1); pk.y = pk2(o2, o3);
    if (isq) *(uint2*)(qo + (size_t)s * QDIM + hh * HD + d0) = pk;
    else     *(uint2*)(ko + (size_t)s * KVDIM + hh * HD + d0) = pk;
}

// ===========================================================================
// fp16 flash attention, 128-row Q tiles, 3-STAGE K/V pipeline (128KB smem),
// single __syncthreads per iteration, distance-2 prefetch. log2 softmax.
// ===========================================================================
__global__ __launch_bounds__(256)
void flash_f16()
{
    extern __shared__ uint8_t smf[];
    const uint32_t sQ = smem_u32(smf);          // 128 rows x 256B = 32KB
    const uint32_t sKV0 = sQ + 32768;           // 3 stages x 32KB (K16+V16)

    const int tid = threadIdx.x, lane = tid & 31, warp = tid >> 5;
    const int qb = gridDim.x - 1 - blockIdx.x;
    const int h = blockIdx.y, kvh = h >> 1;
    const int q2 = lane & 3, u = lane >> 2;
    const uint32_t ONES2 = 0x3C003C00u;

    const uint8_t* Kg0 = (const uint8_t*)(g_kh + (size_t)kvh * HD);
    const uint8_t* Vg0 = (const uint8_t*)(g_vh + (size_t)kvh * HD);
    const int njb = 2 * qb + 2;

    // prologue: Q (group 1), KV0 (group 2), KV1 (group 3)
    {
        const uint8_t* Qg = (const uint8_t*)(g_qh + ((size_t)(qb * 128) * NH + h) * HD);
#pragma unroll
        for (int j = 0; j < 8; j++) {
            int idx = tid + j * 256;
            int row = idx >> 4, g = idx & 15;
            cp16(sQ + row * 256 + ((g ^ (row & 7)) << 4),
                 Qg + (size_t)row * NH * HD * 2 + g * 16);
        }
        CP_COMMIT();
    }
#pragma unroll
    for (int pre = 0; pre < 2; pre++) {   // njb >= 2 always
        uint32_t st = sKV0 + pre * 32768;
        const uint8_t* Kg = Kg0 + (size_t)(pre * 64) * NKV * HD * 2;
        const uint8_t* Vg = Vg0 + (size_t)(pre * 64) * NKV * HD * 2;
#pragma unroll
        for (int j = 0; j < 4; j++) {
            int idx = tid + j * 256;
            int row = idx >> 4, g = idx & 15;
            uint32_t off = row * 256 + ((g ^ (row & 7)) << 4);
            size_t gsrc = (size_t)row * NKV * HD * 2 + g * 16;
            cp16(st + off, Kg + gsrc);
            cp16(st + 16384 + off, Vg + gsrc);
        }
        CP_COMMIT();
    }

    CP_WAIT2();          // Q resident (KV0, KV1 may be in flight)
    __syncthreads();

    uint32_t qf[8][4];
    {
        int row = warp * 16 + (lane & 7) + ((lane >> 3) & 1) * 8;
        int go  = lane >> 4;
        uint32_t rb = sQ + row * 256;
        int rw = (row & 7);
#pragma unroll
        for (int ks = 0; ks < 8; ks++)
            ldsm4(qf[ks], rb + (((2 * ks + go) ^ rw) << 4));
    }

    float o[16][4];
#pragma unroll
    for (int i = 0; i < 16; i++)
#pragma unroll
        for (int r = 0; r < 4; r++) o[i][r] = 0.f;
    float m0 = -1e30f, m1 = -1e30f, l0 = 0.f, l1 = 0.f;

    const int kkey = lane & 7;
    const int kgo  = lane >> 3;
    const int vkey = (lane & 7) + ((lane >> 3) & 1) * 8;
    const int vgo  = lane >> 4;

    for (int jb = 0; jb < njb; jb++) {
        CP_WAIT1();       // KV(jb) resident; KV(jb+1) may fly
        __syncthreads();  // also fences compute(jb-1): stage (jb+2)%3 is free

        if (jb + 2 < njb) {
            uint32_t st = sKV0 + ((jb + 2) % 3) * 32768;
            const uint8_t* Kg = Kg0 + (size_t)((jb + 2) * 64) * NKV * HD * 2;
            const uint8_t* Vg = Vg0 + (size_t)((jb + 2) * 64) * NKV * HD * 2;
#pragma unroll
            for (int j = 0; j < 4; j++) {
                int idx = tid + j * 256;
                int row = idx >> 4, g = idx & 15;
                uint32_t off = row * 256 + ((g ^ (row & 7)) << 4);
                size_t gsrc = (size_t)row * NKV * HD * 2 + g * 16;
                cp16(st + off, Kg + gsrc);
                cp16(st + 16384 + off, Vg + gsrc);
            }
        }
        CP_COMMIT();      // unconditional: keeps group counting aligned

        const uint32_t sK = sKV0 + (jb % 3) * 32768, sV = sK + 16384;

        float s[8][4];
#pragma unroll
        for (int nt = 0; nt < 8; nt++)
#pragma unroll
            for (int r = 0; r < 4; r++) s[nt][r] = 0.f;

#pragma unroll
        for (int g2 = 0; g2 < 4; g2++) {
#pragma unroll
            for (int nt = 0; nt < 8; nt++) {
                int key = 8 * nt + kkey;
                uint32_t bf[4];
                ldsm4(bf, sK + key * 256 + (((4 * g2 + kgo) ^ (key & 7)) << 4));
                mma_f16(s[nt], qf[2 * g2],     bf[0], bf[1]);
                mma_f16(s[nt], qf[2 * g2 + 1], bf[2], bf[3]);
            }
        }

        if (jb >= 2 * qb) {
            int r0g = qb * 128 + warp * 16 + u;
            int cb = jb * 64 + q2 * 2;
#pragma unroll
            for (int nt = 0; nt < 8; nt++) {
                int c = cb + nt * 8;
                if (c     > r0g)     s[nt][0] = -1e30f;
                if (c + 1 > r0g)     s[nt][1] = -1e30f;
                if (c     > r0g + 8) s[nt][2] = -1e30f;
                if (c + 1 > r0g + 8) s[nt][3] = -1e30f;
            }
        }

        float mx0 = -1e30f, mx1 = -1e30f;
#pragma unroll
        for (int nt = 0; nt < 8; nt++) {
            mx0 = fmaxf(mx0, fmaxf(s[nt][0], s[nt][1]));
            mx1 = fmaxf(mx1, fmaxf(s[nt][2], s[nt][3]));
        }
        mx0 = fmaxf(mx0, __shfl_xor_sync(0xffffffffu, mx0, 1));
        mx0 = fmaxf(mx0, __shfl_xor_sync(0xffffffffu, mx0, 2));
        mx1 = fmaxf(mx1, __shfl_xor_sync(0xffffffffu, mx1, 1));
        mx1 = fmaxf(mx1, __shfl_xor_sync(0xffffffffu, mx1, 2));
        float mn0 = fmaxf(m0, mx0), mn1 = fmaxf(m1, mx1);
        float cf0 = exp2s(m0 - mn0), cf1 = exp2s(m1 - mn1);
        m0 = mn0; m1 = mn1;

        uint32_t pf[4][4];
#pragma unroll
        for (int kt = 0; kt < 4; kt++) {
            pf[kt][0] = exp2h2(s[2*kt][0]   - mn0, s[2*kt][1]   - mn0);
            pf[kt][1] = exp2h2(s[2*kt][2]   - mn1, s[2*kt][3]   - mn1);
            pf[kt][2] = exp2h2(s[2*kt+1][0] - mn0, s[2*kt+1][1] - mn0);
            pf[kt][3] = exp2h2(s[2*kt+1][2] - mn1, s[2*kt+1][3] - mn1);
        }

        float rsd[4] = {0.f, 0.f, 0.f, 0.f};
#pragma unroll
        for (int kt = 0; kt < 4; kt++)
            mma_f16(rsd, pf[kt], ONES2, ONES2);

        l0 = l0 * cf0 + rsd[0];
        l1 = l1 * cf1 + rsd[2];
#pragma unroll
        for (int nt2 = 0; nt2 < 16; nt2++) {
            o[nt2][0] *= cf0; o[nt2][1] *= cf0;
            o[nt2][2] *= cf1; o[nt2][3] *= cf1;
        }

#pragma unroll
        for (int ks = 0; ks < 4; ks++) {
#pragma unroll
            for (int np = 0; np < 8; np++) {
                int key = 16 * ks + vkey;
                uint32_t vf[4];
                ldsm4t(vf, sV + key * 256 + (((2 * np + vgo) ^ (key & 7)) << 4));
                mma_f16(o[2 * np],     pf[ks], vf[0], vf[1]);
                mma_f16(o[2 * np + 1], pf[ks], vf[2], vf[3]);
            }
        }
    }

    float r0i = 1.f / l0, r1i = 1.f / l1;
    int grow = qb * 128 + warp * 16 + u;
#pragma unroll
    for (int nt2 = 0; nt2 < 16; nt2++) {
        int col = h * HD + nt2 * 8 + q2 * 2;
        *(float2*)(g_attn + (size_t)grow * QDIM + col) =
            make_float2(o[nt2][0] * r0i, o[nt2][1] * r0i);
        *(float2*)(g_attn + (size_t)(grow + 8) * QDIM + col) =
            make_float2(o[nt2][2] * r1i, o[nt2][3] * r1i);
    }
}

// ===========================================================================
extern "C" void kernel_launch(void* const* d_in, const int* in_sizes, int n_in,
                              void* d_out, int out_size)
{
    const float* hid  = (const float*)d_in[0];
    const float* cosp = (const float*)d_in[1];
    const float* sinp = (const float*)d_in[2];
    const float* wq   = (const float*)d_in[3];
    const float* wk   = (const float*)d_in[4];
    const float* wv   = (const float*)d_in[5];
    const float* wo   = (const float*)d_in[6];
    const float* qw   = (const float*)d_in[7];
    const float* kw   = (const float*)d_in[8];
    float* out = (float*)d_out;

    float *qkv, *ab;
    cudaGetSymbolAddress((void**)&qkv, g_qkv);
    cudaGetSymbolAddress((void**)&ab, g_attn);
    __half *qh, *kh, *vh;
    cudaGetSymbolAddress((void**)&qh, g_qh);
    cudaGetSymbolAddress((void**)&kh, g_kh);
    cudaGetSymbolAddress((void**)&vh, g_vh);
    uint8_t *pa, *pw, *pwo;
    cudaGetSymbolAddress((void**)&pa,  g_pa);
    cudaGetSymbolAddress((void**)&pw,  g_pw);
    cudaGetSymbolAddress((void**)&pwo, g_pwo);
    float *sa, *sw, *swo;
    cudaGetSymbolAddress((void**)&sa,  g_sa);
    cudaGetSymbolAddress((void**)&sw,  g_sw);
    cudaGetSymbolAddress((void**)&swo, g_swo);

    const int GEMM_SMEM  = 98304;    // 3 stages x 32KB
    const int FLASH_SMEM = 131072;   // Q 32KB + 3 x (K16+V16)
    cudaFuncSetAttribute(gemm_i8, cudaFuncAttributeMaxDynamicSharedMemorySize, GEMM_SMEM);
    cudaFuncSetAttribute(flash_f16, cudaFuncAttributeMaxDynamicSharedMemorySize, FLASH_SMEM);

    pack_quant<<<SEQ / 8, 256>>>(hid, pa, sa);
    pack_quant<<<QDIM / 8, 256>>>(wq, pw, sw);
    pack_quant<<<KVDIM / 8, 256>>>(wk, pw + (size_t)QDIM * KDIM * 2, sw + QDIM);
    pack_quant<<<KVDIM / 8, 256>>>(wv, pw + (size_t)(QDIM + KVDIM) * KDIM * 2, sw + QDIM + KVDIM);
    pack_quant<<<HID / 8, 256>>>(wo, pwo, swo);

    gemm_i8<<<dim3(QKVN / 128, SEQ / 128), 256, GEMM_SMEM>>>(pa, pw, sa, sw, qkv, QKVN);

    norm_rope_cvt<<<dim3(SEQ, 4), 256>>>(qkv, qh, kh, vh, cosp, sinp, qw, kw);

    flash_f16<<<dim3(SEQ / 128, NH), 256, FLASH_SMEM>>>();

    pack_quant<<<SEQ / 8, 256>>>(ab, pa, sa);
    gemm_i8<<<dim3(HID / 128, SEQ / 128), 256, GEMM_SMEM>>>(pa, pwo, sa, swo, out, HID);
}

// round 13
// speedup vs baseline: 9.3415x; 1.0184x over previous
#include <cuda_runtime.h>
#include <cuda_fp16.h>
#include <cstdint>

#define SEQ   4096
#define HID   2048
#define NH    16
#define NKV   8
#define HD    128
#define QDIM  (NH*HD)    // 2048
#define KVDIM (NKV*HD)   // 1024
#define KDIM  2048
#define KC    (KDIM/64)  // 32
#define QKVN  4096
#define QSCALE (0.08838834764831845f * 1.4426950408889634f)

// fp32 intermediates
__device__ float g_qkv[(size_t)SEQ * QKVN];
__device__ float g_attn[(size_t)SEQ * QDIM];

// fp16 flash operands
__device__ __half g_qh[SEQ * QDIM];
__device__ __half g_kh[SEQ * KVDIM];
__device__ __half g_vh[SEQ * KVDIM];

// int8 2-term packed operands + per-row scales
__device__ uint8_t g_pa[(size_t)SEQ * KDIM * 2];
__device__ uint8_t g_pw[(size_t)QKVN * KDIM * 2];
__device__ uint8_t g_pwo[(size_t)HID * KDIM * 2];
__device__ float g_sa[SEQ];
__device__ float g_sw[QKVN], g_swo[HID];

__device__ __forceinline__ void mma_i8(int* d,
    const uint32_t* a, uint32_t b0, uint32_t b1)
{
    asm volatile(
        "mma.sync.aligned.m16n8k32.row.col.s32.s8.s8.s32 "
        "{%0,%1,%2,%3}, {%4,%5,%6,%7}, {%8,%9}, {%0,%1,%2,%3};\n"
        : "+r"(d[0]), "+r"(d[1]), "+r"(d[2]), "+r"(d[3])
        : "r"(a[0]), "r"(a[1]), "r"(a[2]), "r"(a[3]), "r"(b0), "r"(b1));
}
__device__ __forceinline__ void mma_f16(float* d,
    const uint32_t* a, uint32_t b0, uint32_t b1)
{
    asm volatile(
        "mma.sync.aligned.m16n8k16.row.col.f32.f16.f16.f32 "
        "{%0,%1,%2,%3}, {%4,%5,%6,%7}, {%8,%9}, {%0,%1,%2,%3};\n"
        : "+f"(d[0]), "+f"(d[1]), "+f"(d[2]), "+f"(d[3])
        : "r"(a[0]), "r"(a[1]), "r"(a[2]), "r"(a[3]), "r"(b0), "r"(b1));
}
__device__ __forceinline__ void ldsm4(uint32_t* r, uint32_t addr) {
    asm volatile("ldmatrix.sync.aligned.m8n8.x4.shared.b16 {%0,%1,%2,%3}, [%4];"
                 : "=r"(r[0]), "=r"(r[1]), "=r"(r[2]), "=r"(r[3]) : "r"(addr));
}
__device__ __forceinline__ void ldsm4t(uint32_t* r, uint32_t addr) {
    asm volatile("ldmatrix.sync.aligned.m8n8.x4.trans.shared.b16 {%0,%1,%2,%3}, [%4];"
                 : "=r"(r[0]), "=r"(r[1]), "=r"(r[2]), "=r"(r[3]) : "r"(addr));
}
__device__ __forceinline__ uint32_t smem_u32(const void* p) {
    uint32_t a;
    asm("{ .reg .u64 t; cvta.to.shared.u64 t, %1; cvt.u32.u64 %0, t; }" : "=r"(a) : "l"(p));
    return a;
}
__device__ __forceinline__ void cp16(uint32_t d, const void* g) {
    asm volatile("cp.async.cg.shared.global [%0], [%1], 16;" :: "r"(d), "l"(g));
}
#define CP_COMMIT() asm volatile("cp.async.commit_group;")
#define CP_WAIT2()  asm volatile("cp.async.wait_group 2;")
#define CP_WAIT1()  asm volatile("cp.async.wait_group 1;")

__device__ __forceinline__ uint32_t exp2h2(float a, float b) {
    __half2 h = __floats2half2_rn(a, b);
    uint32_t x = *(uint32_t*)&h, r;
    asm("ex2.approx.f16x2 %0, %1;" : "=r"(r) : "r"(x));
    return r;
}
__device__ __forceinline__ float exp2s(float x) {
    float r; asm("ex2.approx.f32 %0, %1;" : "=f"(r) : "f"(x)); return r;
}
__device__ __forceinline__ uint32_t pk2(float lo, float hi) {
    __half2 t = __floats2half2_rn(lo, hi);
    return *(uint32_t*)&t;
}

// ===========================================================================
// pack_row: fp32 row [KDIM] -> 2-term int8, tile-packed+swizzled (warp-wide).
// ===========================================================================
__device__ __forceinline__ void pack_row(const float* __restrict__ src,
                                         uint8_t* __restrict__ dst,
                                         float* __restrict__ scl,
                                         int row, int lane)
{
    const float* s = src + (size_t)row * KDIM;

    float4 v[16];
    float mx = 0.f;
#pragma unroll
    for (int j = 0; j < 16; j++) {
        v[j] = *(const float4*)(s + lane * 4 + j * 128);
        mx = fmaxf(mx, fmaxf(fmaxf(fabsf(v[j].x), fabsf(v[j].y)),
                             fmaxf(fabsf(v[j].z), fabsf(v[j].w))));
    }
#pragma unroll
    for (int o = 16; o; o >>= 1) mx = fmaxf(mx, __shfl_xor_sync(0xffffffffu, mx, o));

    const float s1   = mx * (1.f / 127.f);
    const float inv1 = mx > 0.f ? 127.f / mx : 0.f;
    const float inv2 = inv1 * 128.f;
    if (lane == 0) scl[row] = s1;

    const int rt = row >> 7, rr = row & 127, sw = rr & 7;
    uint8_t* tbase0 = dst + ((size_t)rt * KC) * 16384 + rr * 128;

#pragma unroll
    for (int j = 0; j < 16; j++) {
        int k = lane * 4 + j * 128;
        int c = k >> 6, w16 = (k >> 4) & 3, bin = k & 15;
        float4 x = v[j];
        int q0 = __float2int_rn(x.x * inv1), q1 = __float2int_rn(x.y * inv1);
        int q2 = __float2int_rn(x.z * inv1), q3 = __float2int_rn(x.w * inv1);
        int r0 = __float2int_rn((x.x - q0 * s1) * inv2);
        int r1 = __float2int_rn((x.y - q1 * s1) * inv2);
        int r2 = __float2int_rn((x.z - q2 * s1) * inv2);
        int r3 = __float2int_rn((x.w - q3 * s1) * inv2);
        uint8_t* tb = tbase0 + c * 16384;
        *(char4*)(tb + (((w16     ^ sw) << 4) + bin)) =
            make_char4((char)q0, (char)q1, (char)q2, (char)q3);
        *(char4*)(tb + ((((w16+4) ^ sw) << 4) + bin)) =
            make_char4((char)r0, (char)r1, (char)r2, (char)r3);
    }
}

// activation pack (hid / attn): grid rows/8
__global__ __launch_bounds__(256)
void pack_quant(const float* __restrict__ src, uint8_t* __restrict__ dst,
                float* __restrict__ scl)
{
    const int warp = threadIdx.x >> 5, lane = threadIdx.x & 31;
    pack_row(src, dst, scl, blockIdx.x * 8 + warp, lane);
}

// merged weight pack: one launch for wq|wk|wv (into pw) and wo (into pwo).
// grid 768 x 8 rows: [0,2048) wq, [2048,3072) wk, [3072,4096) wv, [4096,6144) wo
__global__ __launch_bounds__(256)
void pack_quant_w(const float* __restrict__ wq, const float* __restrict__ wk,
                  const float* __restrict__ wv, const float* __restrict__ wo,
                  uint8_t* __restrict__ pw, uint8_t* __restrict__ pwo,
                  float* __restrict__ sw, float* __restrict__ swo)
{
    const int warp = threadIdx.x >> 5, lane = threadIdx.x & 31;
    const int gr = blockIdx.x * 8 + warp;

    const float* src; uint8_t* dst; float* scl; int row;
    if (gr < 2048)      { src = wq; dst = pw;                              scl = sw;        row = gr; }
    else if (gr < 3072) { src = wk; dst = pw + (size_t)2048 * KDIM * 2;    scl = sw + 2048; row = gr - 2048; }
    else if (gr < 4096) { src = wv; dst = pw + (size_t)3072 * KDIM * 2;    scl = sw + 3072; row = gr - 3072; }
    else                { src = wo; dst = pwo;                             scl = swo;       row = gr - 4096; }
    pack_row(src, dst, scl, row, lane);
}

// ===========================================================================
// gemm_i8: 3-term int8 mma, 128x128 tile, 3-stage single-sync (unchanged).
// ===========================================================================
__global__ __launch_bounds__(256)
void gemm_i8(const uint8_t* __restrict__ Ap, const uint8_t* __restrict__ Bp,
             const float* __restrict__ sA, const float* __restrict__ sB,
             float* __restrict__ C, int N)
{
    extern __shared__ uint8_t smi[];
    const uint32_t sb0 = smem_u32(smi);
    const int tid = threadIdx.x, lane = tid & 31, warp = tid >> 5;
    const int wm = warp >> 2, wn = warp & 3;
    const int bn = blockIdx.x, bm = blockIdx.y;

    const uint8_t* Asrc = Ap + (size_t)bm * KC * 16384 + tid * 16;
    const uint8_t* Bsrc = Bp + (size_t)bn * KC * 16384 + tid * 16;

    int acc1[4][4][4] = {}, acc2[4][4][4] = {};

    const int arow = wm * 64 + (lane & 7) + ((lane >> 3) & 1) * 8;
    const int akh  = lane >> 4;
    const int aw   = arow & 7;
    const int brow = wn * 32 + (lane & 7) + (lane >> 4) * 8;
    const int bkh  = (lane >> 3) & 1;
    const int bw   = brow & 7;

#pragma unroll
    for (int pre = 0; pre < 2; pre++) {
        uint32_t d = sb0 + pre * 32768 + tid * 16;
#pragma unroll
        for (int i = 0; i < 4; i++) cp16(d + i * 4096,         Asrc + (size_t)pre * 16384 + i * 4096);
#pragma unroll
        for (int i = 0; i < 4; i++) cp16(d + 16384 + i * 4096, Bsrc + (size_t)pre * 16384 + i * 4096);
        CP_COMMIT();
    }

    for (int kc = 0; kc < KC; kc++) {
        CP_WAIT1();
        __syncthreads();
        if (kc + 2 < KC) {
            int st2 = (kc + 2) % 3;
            uint32_t d = sb0 + st2 * 32768 + tid * 16;
#pragma unroll
            for (int i = 0; i < 4; i++) cp16(d + i * 4096,         Asrc + (size_t)(kc + 2) * 16384 + i * 4096);
#pragma unroll
            for (int i = 0; i < 4; i++) cp16(d + 16384 + i * 4096, Bsrc + (size_t)(kc + 2) * 16384 + i * 4096);
        }
        CP_COMMIT();

        const uint32_t stA = sb0 + (kc % 3) * 32768, stB = stA + 16384;

#pragma unroll
        for (int s = 0; s < 2; s++) {
            uint32_t a1f[4][4], a2f[4][4];
            const int ga = 2 * s + akh;
#pragma unroll
            for (int mi = 0; mi < 4; mi++) {
                uint32_t ad = stA + (uint32_t)(arow + mi * 16) * 128;
                ldsm4(a1f[mi], ad + (uint32_t)(((ga     ^ aw) << 4)));
                ldsm4(a2f[mi], ad + (uint32_t)((((ga+4) ^ aw) << 4)));
            }
            const int gb = 2 * s + bkh;
#pragma unroll
            for (int nj = 0; nj < 2; nj++) {
                uint32_t bd = stB + (uint32_t)(brow + nj * 16) * 128;
                uint32_t b1f[4], b2f[4];
                ldsm4(b1f, bd + (uint32_t)(((gb     ^ bw) << 4)));
                ldsm4(b2f, bd + (uint32_t)((((gb+4) ^ bw) << 4)));
#pragma unroll
                for (int mi = 0; mi < 4; mi++) {
                    mma_i8(acc1[mi][2*nj],   a1f[mi], b1f[0], b1f[1]);
                    mma_i8(acc1[mi][2*nj+1], a1f[mi], b1f[2], b1f[3]);
                    mma_i8(acc2[mi][2*nj],   a1f[mi], b2f[0], b2f[1]);
                    mma_i8(acc2[mi][2*nj+1], a1f[mi], b2f[2], b2f[3]);
                    mma_i8(acc2[mi][2*nj],   a2f[mi], b1f[0], b1f[1]);
                    mma_i8(acc2[mi][2*nj+1], a2f[mi], b1f[2], b1f[3]);
                }
            }
        }
    }

    const int u = lane >> 2, qq = (lane & 3) * 2;
    const float k2 = 0.0078125f;
#pragma unroll
    for (int mi = 0; mi < 4; mi++) {
        int r0 = bm * 128 + wm * 64 + mi * 16 + u;
        float sa0 = sA[r0], sa1 = sA[r0 + 8];
#pragma unroll
        for (int nt = 0; nt < 4; nt++) {
            int c0 = bn * 128 + wn * 32 + nt * 8 + qq;
            float sb0v = sB[c0], sb1v = sB[c0 + 1];
            float d0 = (float)acc1[mi][nt][0] + (float)acc2[mi][nt][0] * k2;
            float d1 = (float)acc1[mi][nt][1] + (float)acc2[mi][nt][1] * k2;
            float d2 = (float)acc1[mi][nt][2] + (float)acc2[mi][nt][2] * k2;
            float d3 = (float)acc1[mi][nt][3] + (float)acc2[mi][nt][3] * k2;
            *(float2*)(C + (size_t)r0 * N + c0)       = make_float2(sa0 * sb0v * d0, sa0 * sb1v * d1);
            *(float2*)(C + (size_t)(r0 + 8) * N + c0) = make_float2(sa1 * sb0v * d2, sa1 * sb1v * d3);
        }
    }
}

// ===========================================================================
// norm_rope_cvt: warp-per-head (unchanged, passing).
// ===========================================================================
__global__ __launch_bounds__(256)
void norm_rope_cvt(const float* __restrict__ qkv, __half* __restrict__ qo,
                   __half* __restrict__ ko, __half* __restrict__ vo,
                   const float* __restrict__ cs, const float* __restrict__ sn,
                   const float* __restrict__ qw, const float* __restrict__ kw)
{
    const int s = blockIdx.x, y = blockIdx.y;
    const int warp = threadIdx.x >> 5, lane = threadIdx.x & 31;

    if (y == 3) {
        int c = warp * 128 + lane * 4;
        float4 x = *(const float4*)(qkv + (size_t)s * QKVN + 3072 + c);
        uint2 p; p.x = pk2(x.x, x.y); p.y = pk2(x.z, x.w);
        *(uint2*)(vo + (size_t)s * KVDIM + c) = p;
        return;
    }
    const bool isq = y < 2;
    const int hh = isq ? (y * 8 + warp) : warp;
    const float* w = isq ? qw : kw;
    const float scale = isq ? (float)QSCALE : 1.0f;
    const int d0 = lane * 4;

    float4 x = *(const float4*)(qkv + (size_t)s * QKVN + (isq ? 0 : 2048) + hh * HD + d0);
    float ss = x.x * x.x + x.y * x.y + x.z * x.z + x.w * x.w;
#pragma unroll
    for (int o = 16; o; o >>= 1) ss += __shfl_xor_sync(0xffffffffu, ss, o);
    float r = rsqrtf(ss * (1.0f / 128.0f) + 1e-6f);

    float4 wv = *(const float4*)(w + d0);
    float xn0 = x.x * r * wv.x, xn1 = x.y * r * wv.y;
    float xn2 = x.z * r * wv.z, xn3 = x.w * r * wv.w;

    float p0 = __shfl_xor_sync(0xffffffffu, xn0, 16);
    float p1 = __shfl_xor_sync(0xffffffffu, xn1, 16);
    float p2 = __shfl_xor_sync(0xffffffffu, xn2, 16);
    float p3 = __shfl_xor_sync(0xffffffffu, xn3, 16);
    float sg = (lane < 16) ? -1.0f : 1.0f;

    float4 c4 = *(const float4*)(cs + s * HD + d0);
    float4 s4 = *(const float4*)(sn + s * HD + d0);
    float o0 = (xn0 * c4.x + sg * p0 * s4.x) * scale;
    float o1 = (xn1 * c4.y + sg * p1 * s4.y) * scale;
    float o2 = (xn2 * c4.z + sg * p2 * s4.z) * scale;
    float o3 = (xn3 * c4.w + sg * p3 * s4.w) * scale;

    uint2 pk; pk.x = pk2(o0, o1); pk.y = pk2(o2, o3);
    if (isq) *(uint2*)(qo + (size_t)s * QDIM + hh * HD + d0) = pk;
    else     *(uint2*)(ko + (size_t)s * KVDIM + hh * HD + d0) = pk;
}

// ===========================================================================
// fp16 flash attention — R10 online-softmax version (passing at 773.8us).
// 128-row Q tiles, 3-stage K/V pipeline, 1 sync/iter, distance-2 prefetch,
// log2-domain online softmax, ones-mma row sums.
// ===========================================================================
__global__ __launch_bounds__(256)
void flash_f16()
{
    extern __shared__ uint8_t smf[];
    const uint32_t sQ = smem_u32(smf);          // 128 rows x 256B = 32KB
    const uint32_t sKV0 = sQ + 32768;           // 3 stages x 32KB (K16+V16)

    const int tid = threadIdx.x, lane = tid & 31, warp = tid >> 5;
    const int qb = gridDim.x - 1 - blockIdx.x;
    const int h = blockIdx.y, kvh = h >> 1;
    const int q2 = lane & 3, u = lane >> 2;
    const uint32_t ONES2 = 0x3C003C00u;

    const uint8_t* Kg0 = (const uint8_t*)(g_kh + (size_t)kvh * HD);
    const uint8_t* Vg0 = (const uint8_t*)(g_vh + (size_t)kvh * HD);
    const int njb = 2 * qb + 2;

    {
        const uint8_t* Qg = (const uint8_t*)(g_qh + ((size_t)(qb * 128) * NH + h) * HD);
#pragma unroll
        for (int j = 0; j < 8; j++) {
            int idx = tid + j * 256;
            int row = idx >> 4, g = idx & 15;
            cp16(sQ + row * 256 + ((g ^ (row & 7)) << 4),
                 Qg + (size_t)row * NH * HD * 2 + g * 16);
        }
        CP_COMMIT();
    }
#pragma unroll
    for (int pre = 0; pre < 2; pre++) {
        uint32_t st = sKV0 + pre * 32768;
        const uint8_t* Kg = Kg0 + (size_t)(pre * 64) * NKV * HD * 2;
        const uint8_t* Vg = Vg0 + (size_t)(pre * 64) * NKV * HD * 2;
#pragma unroll
        for (int j = 0; j < 4; j++) {
            int idx = tid + j * 256;
            int row = idx >> 4, g = idx & 15;
            uint32_t off = row * 256 + ((g ^ (row & 7)) << 4);
            size_t gsrc = (size_t)row * NKV * HD * 2 + g * 16;
            cp16(st + off, Kg + gsrc);
            cp16(st + 16384 + off, Vg + gsrc);
        }
        CP_COMMIT();
    }

    CP_WAIT2();
    __syncthreads();

    uint32_t qf[8][4];
    {
        int row = warp * 16 + (lane & 7) + ((lane >> 3) & 1) * 8;
        int go  = lane >> 4;
        uint32_t rb = sQ + row * 256;
        int rw = (row & 7);
#pragma unroll
        for (int ks = 0; ks < 8; ks++)
            ldsm4(qf[ks], rb + (((2 * ks + go) ^ rw) << 4));
    }

    float o[16][4];
#pragma unroll
    for (int i = 0; i < 16; i++)
#pragma unroll
        for (int r = 0; r < 4; r++) o[i][r] = 0.f;
    float m0 = -1e30f, m1 = -1e30f, l0 = 0.f, l1 = 0.f;

    const int kkey = lane & 7;
    const int kgo  = lane >> 3;
    const int vkey = (lane & 7) + ((lane >> 3) & 1) * 8;
    const int vgo  = lane >> 4;

    for (int jb = 0; jb < njb; jb++) {
        CP_WAIT1();
        __syncthreads();

        if (jb + 2 < njb) {
            uint32_t st = sKV0 + ((jb + 2) % 3) * 32768;
            const uint8_t* Kg = Kg0 + (size_t)((jb + 2) * 64) * NKV * HD * 2;
            const uint8_t* Vg = Vg0 + (size_t)((jb + 2) * 64) * NKV * HD * 2;
#pragma unroll
            for (int j = 0; j < 4; j++) {
                int idx = tid + j * 256;
                int row = idx >> 4, g = idx & 15;
                uint32_t off = row * 256 + ((g ^ (row & 7)) << 4);
                size_t gsrc = (size_t)row * NKV * HD * 2 + g * 16;
                cp16(st + off, Kg + gsrc);
                cp16(st + 16384 + off, Vg + gsrc);
            }
        }
        CP_COMMIT();

        const uint32_t sK = sKV0 + (jb % 3) * 32768, sV = sK + 16384;

        float s[8][4];
#pragma unroll
        for (int nt = 0; nt < 8; nt++)
#pragma unroll
            for (int r = 0; r < 4; r++) s[nt][r] = 0.f;

#pragma unroll
        for (int g2 = 0; g2 < 4; g2++) {
#pragma unroll
            for (int nt = 0; nt < 8; nt++) {
                int key = 8 * nt + kkey;
                uint32_t bf[4];
                ldsm4(bf, sK + key * 256 + (((4 * g2 + kgo) ^ (key & 7)) << 4));
                mma_f16(s[nt], qf[2 * g2],     bf[0], bf[1]);
                mma_f16(s[nt], qf[2 * g2 + 1], bf[2], bf[3]);
            }
        }

        if (jb >= 2 * qb) {
            int r0g = qb * 128 + warp * 16 + u;
            int cb = jb * 64 + q2 * 2;
#pragma unroll
            for (int nt = 0; nt < 8; nt++) {
                int c = cb + nt * 8;
                if (c     > r0g)     s[nt][0] = -1e30f;
                if (c + 1 > r0g)     s[nt][1] = -1e30f;
                if (c     > r0g + 8) s[nt][2] = -1e30f;
                if (c + 1 > r0g + 8) s[nt][3] = -1e30f;
            }
        }

        float mx0 = -1e30f, mx1 = -1e30f;
#pragma unroll
        for (int nt = 0; nt < 8; nt++) {
            mx0 = fmaxf(mx0, fmaxf(s[nt][0], s[nt][1]));
            mx1 = fmaxf(mx1, fmaxf(s[nt][2], s[nt][3]));
        }
        mx0 = fmaxf(mx0, __shfl_xor_sync(0xffffffffu, mx0, 1));
        mx0 = fmaxf(mx0, __shfl_xor_sync(0xffffffffu, mx0, 2));
        mx1 = fmaxf(mx1, __shfl_xor_sync(0xffffffffu, mx1, 1));
        mx1 = fmaxf(mx1, __shfl_xor_sync(0xffffffffu, mx1, 2));
        float mn0 = fmaxf(m0, mx0), mn1 = fmaxf(m1, mx1);
        float cf0 = exp2s(m0 - mn0), cf1 = exp2s(m1 - mn1);
        m0 = mn0; m1 = mn1;

        uint32_t pf[4][4];
#pragma unroll
        for (int kt = 0; kt < 4; kt++) {
            pf[kt][0] = exp2h2(s[2*kt][0]   - mn0, s[2*kt][1]   - mn0);
            pf[kt][1] = exp2h2(s[2*kt][2]   - mn1, s[2*kt][3]   - mn1);
            pf[kt][2] = exp2h2(s[2*kt+1][0] - mn0, s[2*kt+1][1] - mn0);
            pf[kt][3] = exp2h2(s[2*kt+1][2] - mn1, s[2*kt+1][3] - mn1);
        }

        float rsd[4] = {0.f, 0.f, 0.f, 0.f};
#pragma unroll
        for (int kt = 0; kt < 4; kt++)
            mma_f16(rsd, pf[kt], ONES2, ONES2);

        l0 = l0 * cf0 + rsd[0];
        l1 = l1 * cf1 + rsd[2];
#pragma unroll
        for (int nt2 = 0; nt2 < 16; nt2++) {
            o[nt2][0] *= cf0; o[nt2][1] *= cf0;
            o[nt2][2] *= cf1; o[nt2][3] *= cf1;
        }

#pragma unroll
        for (int ks = 0; ks < 4; ks++) {
#pragma unroll
            for (int np = 0; np < 8; np++) {
                int key = 16 * ks + vkey;
                uint32_t vf[4];
                ldsm4t(vf, sV + key * 256 + (((2 * np + vgo) ^ (key & 7)) << 4));
                mma_f16(o[2 * np],     pf[ks], vf[0], vf[1]);
                mma_f16(o[2 * np + 1], pf[ks], vf[2], vf[3]);
            }
        }
    }

    float r0i = 1.f / l0, r1i = 1.f / l1;
    int grow = qb * 128 + warp * 16 + u;
#pragma unroll
    for (int nt2 = 0; nt2 < 16; nt2++) {
        int col = h * HD + nt2 * 8 + q2 * 2;
        *(float2*)(g_attn + (size_t)grow * QDIM + col) =
            make_float2(o[nt2][0] * r0i, o[nt2][1] * r0i);
        *(float2*)(g_attn + (size_t)(grow + 8) * QDIM + col) =
            make_float2(o[nt2][2] * r1i, o[nt2][3] * r1i);
    }
}

// ===========================================================================
extern "C" void kernel_launch(void* const* d_in, const int* in_sizes, int n_in,
                              void* d_out, int out_size)
{
    const float* hid  = (const float*)d_in[0];
    const float* cosp = (const float*)d_in[1];
    const float* sinp = (const float*)d_in[2];
    const float* wq   = (const float*)d_in[3];
    const float* wk   = (const float*)d_in[4];
    const float* wv   = (const float*)d_in[5];
    const float* wo   = (const float*)d_in[6];
    const float* qw   = (const float*)d_in[7];
    const float* kw   = (const float*)d_in[8];
    float* out = (float*)d_out;

    float *qkv, *ab;
    cudaGetSymbolAddress((void**)&qkv, g_qkv);
    cudaGetSymbolAddress((void**)&ab, g_attn);
    __half *qh, *kh, *vh;
    cudaGetSymbolAddress((void**)&qh, g_qh);
    cudaGetSymbolAddress((void**)&kh, g_kh);
    cudaGetSymbolAddress((void**)&vh, g_vh);
    uint8_t *pa, *pw, *pwo;
    cudaGetSymbolAddress((void**)&pa,  g_pa);
    cudaGetSymbolAddress((void**)&pw,  g_pw);
    cudaGetSymbolAddress((void**)&pwo, g_pwo);
    float *sa, *sw, *swo;
    cudaGetSymbolAddress((void**)&sa,  g_sa);
    cudaGetSymbolAddress((void**)&sw,  g_sw);
    cudaGetSymbolAddress((void**)&swo, g_swo);

    const int GEMM_SMEM  = 98304;
    const int FLASH_SMEM = 131072;
    cudaFuncSetAttribute(gemm_i8, cudaFuncAttributeMaxDynamicSharedMemorySize, GEMM_SMEM);
    cudaFuncSetAttribute(flash_f16, cudaFuncAttributeMaxDynamicSharedMemorySize, FLASH_SMEM);

    // packs: activations + all weights (single merged launch)
    pack_quant<<<SEQ / 8, 256>>>(hid, pa, sa);
    pack_quant_w<<<768, 256>>>(wq, wk, wv, wo, pw, pwo, sw, swo);

    gemm_i8<<<dim3(QKVN / 128, SEQ / 128), 256, GEMM_SMEM>>>(pa, pw, sa, sw, qkv, QKVN);

    norm_rope_cvt<<<dim3(SEQ, 4), 256>>>(qkv, qh, kh, vh, cosp, sinp, qw, kw);

    flash_f16<<<dim3(SEQ / 128, NH), 256, FLASH_SMEM>>>();

    pack_quant<<<SEQ / 8, 256>>>(ab, pa, sa);
    gemm_i8<<<dim3(HID / 128, SEQ / 128), 256, GEMM_SMEM>>>(pa, pwo, sa, swo, out, HID);
}

// round 14
// speedup vs baseline: 9.3894x; 1.0051x over previous
#include <cuda_runtime.h>
#include <cuda_fp16.h>
#include <cstdint>

#define SEQ   4096
#define HID   2048
#define NH    16
#define NKV   8
#define HD    128
#define QDIM  (NH*HD)    // 2048
#define KVDIM (NKV*HD)   // 1024
#define KDIM  2048
#define KC    (KDIM/64)  // 32
#define QKVN  4096
#define QSCALE (0.08838834764831845f * 1.4426950408889634f)

// fp32 intermediates
__device__ float g_qkv[(size_t)SEQ * QKVN];
__device__ float g_attn[(size_t)SEQ * QDIM];

// fp16 flash operands
__device__ __half g_qh[SEQ * QDIM];
__device__ __half g_kh[SEQ * KVDIM];
__device__ __half g_vh[SEQ * KVDIM];

// int8 2-term packed operands + per-row scales
__device__ uint8_t g_pa[(size_t)SEQ * KDIM * 2];
__device__ uint8_t g_pw[(size_t)QKVN * KDIM * 2];
__device__ uint8_t g_pwo[(size_t)HID * KDIM * 2];
__device__ float g_sa[SEQ];
__device__ float g_sw[QKVN], g_swo[HID];

__device__ __forceinline__ void mma_i8(int* d,
    const uint32_t* a, uint32_t b0, uint32_t b1)
{
    asm volatile(
        "mma.sync.aligned.m16n8k32.row.col.s32.s8.s8.s32 "
        "{%0,%1,%2,%3}, {%4,%5,%6,%7}, {%8,%9}, {%0,%1,%2,%3};\n"
        : "+r"(d[0]), "+r"(d[1]), "+r"(d[2]), "+r"(d[3])
        : "r"(a[0]), "r"(a[1]), "r"(a[2]), "r"(a[3]), "r"(b0), "r"(b1));
}
__device__ __forceinline__ void mma_f16(float* d,
    const uint32_t* a, uint32_t b0, uint32_t b1)
{
    asm volatile(
        "mma.sync.aligned.m16n8k16.row.col.f32.f16.f16.f32 "
        "{%0,%1,%2,%3}, {%4,%5,%6,%7}, {%8,%9}, {%0,%1,%2,%3};\n"
        : "+f"(d[0]), "+f"(d[1]), "+f"(d[2]), "+f"(d[3])
        : "r"(a[0]), "r"(a[1]), "r"(a[2]), "r"(a[3]), "r"(b0), "r"(b1));
}
__device__ __forceinline__ void ldsm4(uint32_t* r, uint32_t addr) {
    asm volatile("ldmatrix.sync.aligned.m8n8.x4.shared.b16 {%0,%1,%2,%3}, [%4];"
                 : "=r"(r[0]), "=r"(r[1]), "=r"(r[2]), "=r"(r[3]) : "r"(addr));
}
__device__ __forceinline__ void ldsm4t(uint32_t* r, uint32_t addr) {
    asm volatile("ldmatrix.sync.aligned.m8n8.x4.trans.shared.b16 {%0,%1,%2,%3}, [%4];"
                 : "=r"(r[0]), "=r"(r[1]), "=r"(r[2]), "=r"(r[3]) : "r"(addr));
}
__device__ __forceinline__ uint32_t smem_u32(const void* p) {
    uint32_t a;
    asm("{ .reg .u64 t; cvta.to.shared.u64 t, %1; cvt.u32.u64 %0, t; }" : "=r"(a) : "l"(p));
    return a;
}
__device__ __forceinline__ void cp16(uint32_t d, const void* g) {
    asm volatile("cp.async.cg.shared.global [%0], [%1], 16;" :: "r"(d), "l"(g));
}
#define CP_COMMIT() asm volatile("cp.async.commit_group;")
#define CP_WAIT2()  asm volatile("cp.async.wait_group 2;")
#define CP_WAIT1()  asm volatile("cp.async.wait_group 1;")

__device__ __forceinline__ uint32_t exp2h2(float a, float b) {
    __half2 h = __floats2half2_rn(a, b);
    uint32_t x = *(uint32_t*)&h, r;
    asm("ex2.approx.f16x2 %0, %1;" : "=r"(r) : "r"(x));
    return r;
}
__device__ __forceinline__ float exp2s(float x) {
    float r; asm("ex2.approx.f32 %0, %1;" : "=f"(r) : "f"(x)); return r;
}
__device__ __forceinline__ uint32_t pk2(float lo, float hi) {
    __half2 t = __floats2half2_rn(lo, hi);
    return *(uint32_t*)&t;
}

// ===========================================================================
// pack_row: fp32 row [KDIM] -> 2-term int8, tile-packed+swizzled (warp-wide).
// ===========================================================================
__device__ __forceinline__ void pack_row(const float* __restrict__ src,
                                         uint8_t* __restrict__ dst,
                                         float* __restrict__ scl,
                                         int row, int lane)
{
    const float* s = src + (size_t)row * KDIM;

    float4 v[16];
    float mx = 0.f;
#pragma unroll
    for (int j = 0; j < 16; j++) {
        v[j] = *(const float4*)(s + lane * 4 + j * 128);
        mx = fmaxf(mx, fmaxf(fmaxf(fabsf(v[j].x), fabsf(v[j].y)),
                             fmaxf(fabsf(v[j].z), fabsf(v[j].w))));
    }
#pragma unroll
    for (int o = 16; o; o >>= 1) mx = fmaxf(mx, __shfl_xor_sync(0xffffffffu, mx, o));

    const float s1   = mx * (1.f / 127.f);
    const float inv1 = mx > 0.f ? 127.f / mx : 0.f;
    const float inv2 = inv1 * 128.f;
    if (lane == 0) scl[row] = s1;

    const int rt = row >> 7, rr = row & 127, sw = rr & 7;
    uint8_t* tbase0 = dst + ((size_t)rt * KC) * 16384 + rr * 128;

#pragma unroll
    for (int j = 0; j < 16; j++) {
        int k = lane * 4 + j * 128;
        int c = k >> 6, w16 = (k >> 4) & 3, bin = k & 15;
        float4 x = v[j];
        int q0 = __float2int_rn(x.x * inv1), q1 = __float2int_rn(x.y * inv1);
        int q2 = __float2int_rn(x.z * inv1), q3 = __float2int_rn(x.w * inv1);
        int r0 = __float2int_rn((x.x - q0 * s1) * inv2);
        int r1 = __float2int_rn((x.y - q1 * s1) * inv2);
        int r2 = __float2int_rn((x.z - q2 * s1) * inv2);
        int r3 = __float2int_rn((x.w - q3 * s1) * inv2);
        uint8_t* tb = tbase0 + c * 16384;
        *(char4*)(tb + (((w16     ^ sw) << 4) + bin)) =
            make_char4((char)q0, (char)q1, (char)q2, (char)q3);
        *(char4*)(tb + ((((w16+4) ^ sw) << 4) + bin)) =
            make_char4((char)r0, (char)r1, (char)r2, (char)r3);
    }
}

__global__ __launch_bounds__(256)
void pack_quant(const float* __restrict__ src, uint8_t* __restrict__ dst,
                float* __restrict__ scl)
{
    const int warp = threadIdx.x >> 5, lane = threadIdx.x & 31;
    pack_row(src, dst, scl, blockIdx.x * 8 + warp, lane);
}

__global__ __launch_bounds__(256)
void pack_quant_w(const float* __restrict__ wq, const float* __restrict__ wk,
                  const float* __restrict__ wv, const float* __restrict__ wo,
                  uint8_t* __restrict__ pw, uint8_t* __restrict__ pwo,
                  float* __restrict__ sw, float* __restrict__ swo)
{
    const int warp = threadIdx.x >> 5, lane = threadIdx.x & 31;
    const int gr = blockIdx.x * 8 + warp;

    const float* src; uint8_t* dst; float* scl; int row;
    if (gr < 2048)      { src = wq; dst = pw;                              scl = sw;        row = gr; }
    else if (gr < 3072) { src = wk; dst = pw + (size_t)2048 * KDIM * 2;    scl = sw + 2048; row = gr - 2048; }
    else if (gr < 4096) { src = wv; dst = pw + (size_t)3072 * KDIM * 2;    scl = sw + 3072; row = gr - 3072; }
    else                { src = wo; dst = pwo;                             scl = swo;       row = gr - 4096; }
    pack_row(src, dst, scl, row, lane);
}

// ===========================================================================
// gemm_i8: 3-term int8 mma, 128x128 tile, 3-stage single-sync (unchanged).
// ===========================================================================
__global__ __launch_bounds__(256)
void gemm_i8(const uint8_t* __restrict__ Ap, const uint8_t* __restrict__ Bp,
             const float* __restrict__ sA, const float* __restrict__ sB,
             float* __restrict__ C, int N)
{
    extern __shared__ uint8_t smi[];
    const uint32_t sb0 = smem_u32(smi);
    const int tid = threadIdx.x, lane = tid & 31, warp = tid >> 5;
    const int wm = warp >> 2, wn = warp & 3;
    const int bn = blockIdx.x, bm = blockIdx.y;

    const uint8_t* Asrc = Ap + (size_t)bm * KC * 16384 + tid * 16;
    const uint8_t* Bsrc = Bp + (size_t)bn * KC * 16384 + tid * 16;

    int acc1[4][4][4] = {}, acc2[4][4][4] = {};

    const int arow = wm * 64 + (lane & 7) + ((lane >> 3) & 1) * 8;
    const int akh  = lane >> 4;
    const int aw   = arow & 7;
    const int brow = wn * 32 + (lane & 7) + (lane >> 4) * 8;
    const int bkh  = (lane >> 3) & 1;
    const int bw   = brow & 7;

#pragma unroll
    for (int pre = 0; pre < 2; pre++) {
        uint32_t d = sb0 + pre * 32768 + tid * 16;
#pragma unroll
        for (int i = 0; i < 4; i++) cp16(d + i * 4096,         Asrc + (size_t)pre * 16384 + i * 4096);
#pragma unroll
        for (int i = 0; i < 4; i++) cp16(d + 16384 + i * 4096, Bsrc + (size_t)pre * 16384 + i * 4096);
        CP_COMMIT();
    }

    for (int kc = 0; kc < KC; kc++) {
        CP_WAIT1();
        __syncthreads();
        if (kc + 2 < KC) {
            int st2 = (kc + 2) % 3;
            uint32_t d = sb0 + st2 * 32768 + tid * 16;
#pragma unroll
            for (int i = 0; i < 4; i++) cp16(d + i * 4096,         Asrc + (size_t)(kc + 2) * 16384 + i * 4096);
#pragma unroll
            for (int i = 0; i < 4; i++) cp16(d + 16384 + i * 4096, Bsrc + (size_t)(kc + 2) * 16384 + i * 4096);
        }
        CP_COMMIT();

        const uint32_t stA = sb0 + (kc % 3) * 32768, stB = stA + 16384;

#pragma unroll
        for (int s = 0; s < 2; s++) {
            uint32_t a1f[4][4], a2f[4][4];
            const int ga = 2 * s + akh;
#pragma unroll
            for (int mi = 0; mi < 4; mi++) {
                uint32_t ad = stA + (uint32_t)(arow + mi * 16) * 128;
                ldsm4(a1f[mi], ad + (uint32_t)(((ga     ^ aw) << 4)));
                ldsm4(a2f[mi], ad + (uint32_t)((((ga+4) ^ aw) << 4)));
            }
            const int gb = 2 * s + bkh;
#pragma unroll
            for (int nj = 0; nj < 2; nj++) {
                uint32_t bd = stB + (uint32_t)(brow + nj * 16) * 128;
                uint32_t b1f[4], b2f[4];
                ldsm4(b1f, bd + (uint32_t)(((gb     ^ bw) << 4)));
                ldsm4(b2f, bd + (uint32_t)((((gb+4) ^ bw) << 4)));
#pragma unroll
                for (int mi = 0; mi < 4; mi++) {
                    mma_i8(acc1[mi][2*nj],   a1f[mi], b1f[0], b1f[1]);
                    mma_i8(acc1[mi][2*nj+1], a1f[mi], b1f[2], b1f[3]);
                    mma_i8(acc2[mi][2*nj],   a1f[mi], b2f[0], b2f[1]);
                    mma_i8(acc2[mi][2*nj+1], a1f[mi], b2f[2], b2f[3]);
                    mma_i8(acc2[mi][2*nj],   a2f[mi], b1f[0], b1f[1]);
                    mma_i8(acc2[mi][2*nj+1], a2f[mi], b1f[2], b1f[3]);
                }
            }
        }
    }

    const int u = lane >> 2, qq = (lane & 3) * 2;
    const float k2 = 0.0078125f;
#pragma unroll
    for (int mi = 0; mi < 4; mi++) {
        int r0 = bm * 128 + wm * 64 + mi * 16 + u;
        float sa0 = sA[r0], sa1 = sA[r0 + 8];
#pragma unroll
        for (int nt = 0; nt < 4; nt++) {
            int c0 = bn * 128 + wn * 32 + nt * 8 + qq;
            float sb0v = sB[c0], sb1v = sB[c0 + 1];
            float d0 = (float)acc1[mi][nt][0] + (float)acc2[mi][nt][0] * k2;
            float d1 = (float)acc1[mi][nt][1] + (float)acc2[mi][nt][1] * k2;
            float d2 = (float)acc1[mi][nt][2] + (float)acc2[mi][nt][2] * k2;
            float d3 = (float)acc1[mi][nt][3] + (float)acc2[mi][nt][3] * k2;
            *(float2*)(C + (size_t)r0 * N + c0)       = make_float2(sa0 * sb0v * d0, sa0 * sb1v * d1);
            *(float2*)(C + (size_t)(r0 + 8) * N + c0) = make_float2(sa1 * sb0v * d2, sa1 * sb1v * d3);
        }
    }
}

// ===========================================================================
// norm_rope_cvt: warp-per-head (unchanged, passing).
// ===========================================================================
__global__ __launch_bounds__(256)
void norm_rope_cvt(const float* __restrict__ qkv, __half* __restrict__ qo,
                   __half* __restrict__ ko, __half* __restrict__ vo,
                   const float* __restrict__ cs, const float* __restrict__ sn,
                   const float* __restrict__ qw, const float* __restrict__ kw)
{
    const int s = blockIdx.x, y = blockIdx.y;
    const int warp = threadIdx.x >> 5, lane = threadIdx.x & 31;

    if (y == 3) {
        int c = warp * 128 + lane * 4;
        float4 x = *(const float4*)(qkv + (size_t)s * QKVN + 3072 + c);
        uint2 p; p.x = pk2(x.x, x.y); p.y = pk2(x.z, x.w);
        *(uint2*)(vo + (size_t)s * KVDIM + c) = p;
        return;
    }
    const bool isq = y < 2;
    const int hh = isq ? (y * 8 + warp) : warp;
    const float* w = isq ? qw : kw;
    const float scale = isq ? (float)QSCALE : 1.0f;
    const int d0 = lane * 4;

    float4 x = *(const float4*)(qkv + (size_t)s * QKVN + (isq ? 0 : 2048) + hh * HD + d0);
    float ss = x.x * x.x + x.y * x.y + x.z * x.z + x.w * x.w;
#pragma unroll
    for (int o = 16; o; o >>= 1) ss += __shfl_xor_sync(0xffffffffu, ss, o);
    float r = rsqrtf(ss * (1.0f / 128.0f) + 1e-6f);

    float4 wv = *(const float4*)(w + d0);
    float xn0 = x.x * r * wv.x, xn1 = x.y * r * wv.y;
    float xn2 = x.z * r * wv.z, xn3 = x.w * r * wv.w;

    float p0 = __shfl_xor_sync(0xffffffffu, xn0, 16);
    float p1 = __shfl_xor_sync(0xffffffffu, xn1, 16);
    float p2 = __shfl_xor_sync(0xffffffffu, xn2, 16);
    float p3 = __shfl_xor_sync(0xffffffffu, xn3, 16);
    float sg = (lane < 16) ? -1.0f : 1.0f;

    float4 c4 = *(const float4*)(cs + s * HD + d0);
    float4 s4 = *(const float4*)(sn + s * HD + d0);
    float o0 = (xn0 * c4.x + sg * p0 * s4.x) * scale;
    float o1 = (xn1 * c4.y + sg * p1 * s4.y) * scale;
    float o2 = (xn2 * c4.z + sg * p2 * s4.z) * scale;
    float o3 = (xn3 * c4.w + sg * p3 * s4.w) * scale;

    uint2 pk; pk.x = pk2(o0, o1); pk.y = pk2(o2, o3);
    if (isq) *(uint2*)(qo + (size_t)s * QDIM + hh * HD + d0) = pk;
    else     *(uint2*)(ko + (size_t)s * KVDIM + hh * HD + d0) = pk;
}

// ===========================================================================
// fp16 flash attention, 128-row Q tiles x 128-KEY KV tiles.
// smem: Q 32KB + 3 stages x (K32+V32) = 224KB. 1 sync/iter, distance-2
// prefetch, log2 online softmax (half the softmax passes of the 64-key ver).
// ===========================================================================
__global__ __launch_bounds__(256)
void flash_f16()
{
    extern __shared__ uint8_t smf[];
    const uint32_t sQ = smem_u32(smf);          // 128 rows x 256B = 32KB
    const uint32_t sKV0 = sQ + 32768;           // 3 stages x 64KB (K32+V32)

    const int tid = threadIdx.x, lane = tid & 31, warp = tid >> 5;
    const int qb = gridDim.x - 1 - blockIdx.x;
    const int h = blockIdx.y, kvh = h >> 1;
    const int q2 = lane & 3, u = lane >> 2;
    const uint32_t ONES2 = 0x3C003C00u;

    const uint8_t* Kg0 = (const uint8_t*)(g_kh + (size_t)kvh * HD);
    const uint8_t* Vg0 = (const uint8_t*)(g_vh + (size_t)kvh * HD);
    const int njb = qb + 1;   // 128-key tiles; last one is the diagonal

    {
        const uint8_t* Qg = (const uint8_t*)(g_qh + ((size_t)(qb * 128) * NH + h) * HD);
#pragma unroll
        for (int j = 0; j < 8; j++) {
            int idx = tid + j * 256;
            int row = idx >> 4, g = idx & 15;
            cp16(sQ + row * 256 + ((g ^ (row & 7)) << 4),
                 Qg + (size_t)row * NH * HD * 2 + g * 16);
        }
        CP_COMMIT();
    }
#pragma unroll
    for (int pre = 0; pre < 2; pre++) {   // tiles 0,1 (tile 1 in-bounds even if unused)
        uint32_t st = sKV0 + pre * 65536;
        const uint8_t* Kg = Kg0 + (size_t)(pre * 128) * NKV * HD * 2;
        const uint8_t* Vg = Vg0 + (size_t)(pre * 128) * NKV * HD * 2;
#pragma unroll
        for (int j = 0; j < 8; j++) {
            int idx = tid + j * 256;
            int row = idx >> 4, g = idx & 15;
            uint32_t off = row * 256 + ((g ^ (row & 7)) << 4);
            size_t gsrc = (size_t)row * NKV * HD * 2 + g * 16;
            cp16(st + off, Kg + gsrc);
            cp16(st + 32768 + off, Vg + gsrc);
        }
        CP_COMMIT();
    }

    CP_WAIT2();
    __syncthreads();

    uint32_t qf[8][4];
    {
        int row = warp * 16 + (lane & 7) + ((lane >> 3) & 1) * 8;
        int go  = lane >> 4;
        uint32_t rb = sQ + row * 256;
        int rw = (row & 7);
#pragma unroll
        for (int ks = 0; ks < 8; ks++)
            ldsm4(qf[ks], rb + (((2 * ks + go) ^ rw) << 4));
    }

    float o[16][4];
#pragma unroll
    for (int i = 0; i < 16; i++)
#pragma unroll
        for (int r = 0; r < 4; r++) o[i][r] = 0.f;
    float m0 = -1e30f, m1 = -1e30f, l0 = 0.f, l1 = 0.f;

    const int kkey = lane & 7;
    const int kgo  = lane >> 3;
    const int vkey = (lane & 7) + ((lane >> 3) & 1) * 8;
    const int vgo  = lane >> 4;

    for (int jb = 0; jb < njb; jb++) {
        CP_WAIT1();
        __syncthreads();

        if (jb + 2 < njb) {
            uint32_t st = sKV0 + ((jb + 2) % 3) * 65536;
            const uint8_t* Kg = Kg0 + (size_t)((jb + 2) * 128) * NKV * HD * 2;
            const uint8_t* Vg = Vg0 + (size_t)((jb + 2) * 128) * NKV * HD * 2;
#pragma unroll
            for (int j = 0; j < 8; j++) {
                int idx = tid + j * 256;
                int row = idx >> 4, g = idx & 15;
                uint32_t off = row * 256 + ((g ^ (row & 7)) << 4);
                size_t gsrc = (size_t)row * NKV * HD * 2 + g * 16;
                cp16(st + off, Kg + gsrc);
                cp16(st + 32768 + off, Vg + gsrc);
            }
        }
        CP_COMMIT();

        const uint32_t sK = sKV0 + (jb % 3) * 65536, sV = sK + 32768;

        // S = Q K^T over 128 keys
        float s[16][4];
#pragma unroll
        for (int nt = 0; nt < 16; nt++)
#pragma unroll
            for (int r = 0; r < 4; r++) s[nt][r] = 0.f;

#pragma unroll
        for (int g2 = 0; g2 < 4; g2++) {
#pragma unroll
            for (int nt = 0; nt < 16; nt++) {
                int key = 8 * nt + kkey;
                uint32_t bf[4];
                ldsm4(bf, sK + key * 256 + (((4 * g2 + kgo) ^ (key & 7)) << 4));
                mma_f16(s[nt], qf[2 * g2],     bf[0], bf[1]);
                mma_f16(s[nt], qf[2 * g2 + 1], bf[2], bf[3]);
            }
        }

        if (jb == qb) {   // diagonal tile
            int r0g = qb * 128 + warp * 16 + u;
            int cb = jb * 128 + q2 * 2;
#pragma unroll
            for (int nt = 0; nt < 16; nt++) {
                int c = cb + nt * 8;
                if (c     > r0g)     s[nt][0] = -1e30f;
                if (c + 1 > r0g)     s[nt][1] = -1e30f;
                if (c     > r0g + 8) s[nt][2] = -1e30f;
                if (c + 1 > r0g + 8) s[nt][3] = -1e30f;
            }
        }

        // online softmax (base-2), one pass per 128 keys
        float mx0 = -1e30f, mx1 = -1e30f;
#pragma unroll
        for (int nt = 0; nt < 16; nt++) {
            mx0 = fmaxf(mx0, fmaxf(s[nt][0], s[nt][1]));
            mx1 = fmaxf(mx1, fmaxf(s[nt][2], s[nt][3]));
        }
        mx0 = fmaxf(mx0, __shfl_xor_sync(0xffffffffu, mx0, 1));
        mx0 = fmaxf(mx0, __shfl_xor_sync(0xffffffffu, mx0, 2));
        mx1 = fmaxf(mx1, __shfl_xor_sync(0xffffffffu, mx1, 1));
        mx1 = fmaxf(mx1, __shfl_xor_sync(0xffffffffu, mx1, 2));
        float mn0 = fmaxf(m0, mx0), mn1 = fmaxf(m1, mx1);
        float cf0 = exp2s(m0 - mn0), cf1 = exp2s(m1 - mn1);
        m0 = mn0; m1 = mn1;

        uint32_t pf[8][4];
#pragma unroll
        for (int kt = 0; kt < 8; kt++) {
            pf[kt][0] = exp2h2(s[2*kt][0]   - mn0, s[2*kt][1]   - mn0);
            pf[kt][1] = exp2h2(s[2*kt][2]   - mn1, s[2*kt][3]   - mn1);
            pf[kt][2] = exp2h2(s[2*kt+1][0] - mn0, s[2*kt+1][1] - mn0);
            pf[kt][3] = exp2h2(s[2*kt+1][2] - mn1, s[2*kt+1][3] - mn1);
        }

        float rsd[4] = {0.f, 0.f, 0.f, 0.f};
#pragma unroll
        for (int kt = 0; kt < 8; kt++)
            mma_f16(rsd, pf[kt], ONES2, ONES2);

        l0 = l0 * cf0 + rsd[0];
        l1 = l1 * cf1 + rsd[2];
#pragma unroll
        for (int nt2 = 0; nt2 < 16; nt2++) {
            o[nt2][0] *= cf0; o[nt2][1] *= cf0;
            o[nt2][2] *= cf1; o[nt2][3] *= cf1;
        }

        // O += P V over 128 keys
#pragma unroll
        for (int ks = 0; ks < 8; ks++) {
#pragma unroll
            for (int np = 0; np < 8; np++) {
                int key = 16 * ks + vkey;
                uint32_t vf[4];
                ldsm4t(vf, sV + key * 256 + (((2 * np + vgo) ^ (key & 7)) << 4));
                mma_f16(o[2 * np],     pf[ks], vf[0], vf[1]);
                mma_f16(o[2 * np + 1], pf[ks], vf[2], vf[3]);
            }
        }
    }

    float r0i = 1.f / l0, r1i = 1.f / l1;
    int grow = qb * 128 + warp * 16 + u;
#pragma unroll
    for (int nt2 = 0; nt2 < 16; nt2++) {
        int col = h * HD + nt2 * 8 + q2 * 2;
        *(float2*)(g_attn + (size_t)grow * QDIM + col) =
            make_float2(o[nt2][0] * r0i, o[nt2][1] * r0i);
        *(float2*)(g_attn + (size_t)(grow + 8) * QDIM + col) =
            make_float2(o[nt2][2] * r1i, o[nt2][3] * r1i);
    }
}

// ===========================================================================
extern "C" void kernel_launch(void* const* d_in, const int* in_sizes, int n_in,
                              void* d_out, int out_size)
{
    const float* hid  = (const float*)d_in[0];
    const float* cosp = (const float*)d_in[1];
    const float* sinp = (const float*)d_in[2];
    const float* wq   = (const float*)d_in[3];
    const float* wk   = (const float*)d_in[4];
    const float* wv   = (const float*)d_in[5];
    const float* wo   = (const float*)d_in[6];
    const float* qw   = (const float*)d_in[7];
    const float* kw   = (const float*)d_in[8];
    float* out = (float*)d_out;

    float *qkv, *ab;
    cudaGetSymbolAddress((void**)&qkv, g_qkv);
    cudaGetSymbolAddress((void**)&ab, g_attn);
    __half *qh, *kh, *vh;
    cudaGetSymbolAddress((void**)&qh, g_qh);
    cudaGetSymbolAddress((void**)&kh, g_kh);
    cudaGetSymbolAddress((void**)&vh, g_vh);
    uint8_t *pa, *pw, *pwo;
    cudaGetSymbolAddress((void**)&pa,  g_pa);
    cudaGetSymbolAddress((void**)&pw,  g_pw);
    cudaGetSymbolAddress((void**)&pwo, g_pwo);
    float *sa, *sw, *swo;
    cudaGetSymbolAddress((void**)&sa,  g_sa);
    cudaGetSymbolAddress((void**)&sw,  g_sw);
    cudaGetSymbolAddress((void**)&swo, g_swo);

    const int GEMM_SMEM  = 98304;
    const int FLASH_SMEM = 229376;   // Q 32KB + 3 x (K32+V32)
    cudaFuncSetAttribute(gemm_i8, cudaFuncAttributeMaxDynamicSharedMemorySize, GEMM_SMEM);
    cudaFuncSetAttribute(flash_f16, cudaFuncAttributeMaxDynamicSharedMemorySize, FLASH_SMEM);

    pack_quant<<<SEQ / 8, 256>>>(hid, pa, sa);
    pack_quant_w<<<768, 256>>>(wq, wk, wv, wo, pw, pwo, sw, swo);

    gemm_i8<<<dim3(QKVN / 128, SEQ / 128), 256, GEMM_SMEM>>>(pa, pw, sa, sw, qkv, QKVN);

    norm_rope_cvt<<<dim3(SEQ, 4), 256>>>(qkv, qh, kh, vh, cosp, sinp, qw, kw);

    flash_f16<<<dim3(SEQ / 128, NH), 256, FLASH_SMEM>>>();

    pack_quant<<<SEQ / 8, 256>>>(ab, pa, sa);
    gemm_i8<<<dim3(HID / 128, SEQ / 128), 256, GEMM_SMEM>>>(pa, pwo, sa, swo, out, HID);
}

// round 15
// speedup vs baseline: 9.4704x; 1.0086x over previous
#include <cuda_runtime.h>
#include <cuda_fp16.h>
#include <cstdint>

#define SEQ   4096
#define HID   2048
#define NH    16
#define NKV   8
#define HD    128
#define QDIM  (NH*HD)    // 2048
#define KVDIM (NKV*HD)   // 1024
#define KDIM  2048
#define KC    (KDIM/64)  // 32
#define QKVN  4096
#define QSCALE (0.08838834764831845f * 1.4426950408889634f)

// fp32 intermediates
__device__ float g_qkv[(size_t)SEQ * QKVN];   // V columns unused (fp16 direct)
__device__ float g_attn[(size_t)SEQ * QDIM];

// fp16 flash operands
__device__ __half g_qh[SEQ * QDIM];
__device__ __half g_kh[SEQ * KVDIM];
__device__ __half g_vh[SEQ * KVDIM];

// int8 2-term packed operands + per-row scales
__device__ uint8_t g_pa[(size_t)SEQ * KDIM * 2];
__device__ uint8_t g_pw[(size_t)QKVN * KDIM * 2];
__device__ uint8_t g_pwo[(size_t)HID * KDIM * 2];
__device__ float g_sa[SEQ];
__device__ float g_sw[QKVN], g_swo[HID];

__device__ __forceinline__ void mma_i8(int* d,
    const uint32_t* a, uint32_t b0, uint32_t b1)
{
    asm volatile(
        "mma.sync.aligned.m16n8k32.row.col.s32.s8.s8.s32 "
        "{%0,%1,%2,%3}, {%4,%5,%6,%7}, {%8,%9}, {%0,%1,%2,%3};\n"
        : "+r"(d[0]), "+r"(d[1]), "+r"(d[2]), "+r"(d[3])
        : "r"(a[0]), "r"(a[1]), "r"(a[2]), "r"(a[3]), "r"(b0), "r"(b1));
}
__device__ __forceinline__ void mma_f16(float* d,
    const uint32_t* a, uint32_t b0, uint32_t b1)
{
    asm volatile(
        "mma.sync.aligned.m16n8k16.row.col.f32.f16.f16.f32 "
        "{%0,%1,%2,%3}, {%4,%5,%6,%7}, {%8,%9}, {%0,%1,%2,%3};\n"
        : "+f"(d[0]), "+f"(d[1]), "+f"(d[2]), "+f"(d[3])
        : "r"(a[0]), "r"(a[1]), "r"(a[2]), "r"(a[3]), "r"(b0), "r"(b1));
}
__device__ __forceinline__ void ldsm4(uint32_t* r, uint32_t addr) {
    asm volatile("ldmatrix.sync.aligned.m8n8.x4.shared.b16 {%0,%1,%2,%3}, [%4];"
                 : "=r"(r[0]), "=r"(r[1]), "=r"(r[2]), "=r"(r[3]) : "r"(addr));
}
__device__ __forceinline__ void ldsm4t(uint32_t* r, uint32_t addr) {
    asm volatile("ldmatrix.sync.aligned.m8n8.x4.trans.shared.b16 {%0,%1,%2,%3}, [%4];"
                 : "=r"(r[0]), "=r"(r[1]), "=r"(r[2]), "=r"(r[3]) : "r"(addr));
}
__device__ __forceinline__ uint32_t smem_u32(const void* p) {
    uint32_t a;
    asm("{ .reg .u64 t; cvta.to.shared.u64 t, %1; cvt.u32.u64 %0, t; }" : "=r"(a) : "l"(p));
    return a;
}
__device__ __forceinline__ void cp16(uint32_t d, const void* g) {
    asm volatile("cp.async.cg.shared.global [%0], [%1], 16;" :: "r"(d), "l"(g));
}
#define CP_COMMIT() asm volatile("cp.async.commit_group;")
#define CP_WAIT2()  asm volatile("cp.async.wait_group 2;")
#define CP_WAIT1()  asm volatile("cp.async.wait_group 1;")

__device__ __forceinline__ uint32_t exp2h2(float a, float b) {
    __half2 h = __floats2half2_rn(a, b);
    uint32_t x = *(uint32_t*)&h, r;
    asm("ex2.approx.f16x2 %0, %1;" : "=r"(r) : "r"(x));
    return r;
}
__device__ __forceinline__ float exp2s(float x) {
    float r; asm("ex2.approx.f32 %0, %1;" : "=f"(r) : "f"(x)); return r;
}
__device__ __forceinline__ uint32_t pk2(float lo, float hi) {
    __half2 t = __floats2half2_rn(lo, hi);
    return *(uint32_t*)&t;
}

// ===========================================================================
// pack_row: fp32 row [KDIM] -> 2-term int8, tile-packed+swizzled (warp-wide).
// ===========================================================================
__device__ __forceinline__ void pack_row(const float* __restrict__ src,
                                         uint8_t* __restrict__ dst,
                                         float* __restrict__ scl,
                                         int row, int lane)
{
    const float* s = src + (size_t)row * KDIM;

    float4 v[16];
    float mx = 0.f;
#pragma unroll
    for (int j = 0; j < 16; j++) {
        v[j] = *(const float4*)(s + lane * 4 + j * 128);
        mx = fmaxf(mx, fmaxf(fmaxf(fabsf(v[j].x), fabsf(v[j].y)),
                             fmaxf(fabsf(v[j].z), fabsf(v[j].w))));
    }
#pragma unroll
    for (int o = 16; o; o >>= 1) mx = fmaxf(mx, __shfl_xor_sync(0xffffffffu, mx, o));

    const float s1   = mx * (1.f / 127.f);
    const float inv1 = mx > 0.f ? 127.f / mx : 0.f;
    const float inv2 = inv1 * 128.f;
    if (lane == 0) scl[row] = s1;

    const int rt = row >> 7, rr = row & 127, sw = rr & 7;
    uint8_t* tbase0 = dst + ((size_t)rt * KC) * 16384 + rr * 128;

#pragma unroll
    for (int j = 0; j < 16; j++) {
        int k = lane * 4 + j * 128;
        int c = k >> 6, w16 = (k >> 4) & 3, bin = k & 15;
        float4 x = v[j];
        int q0 = __float2int_rn(x.x * inv1), q1 = __float2int_rn(x.y * inv1);
        int q2 = __float2int_rn(x.z * inv1), q3 = __float2int_rn(x.w * inv1);
        int r0 = __float2int_rn((x.x - q0 * s1) * inv2);
        int r1 = __float2int_rn((x.y - q1 * s1) * inv2);
        int r2 = __float2int_rn((x.z - q2 * s1) * inv2);
        int r3 = __float2int_rn((x.w - q3 * s1) * inv2);
        uint8_t* tb = tbase0 + c * 16384;
        *(char4*)(tb + (((w16     ^ sw) << 4) + bin)) =
            make_char4((char)q0, (char)q1, (char)q2, (char)q3);
        *(char4*)(tb + ((((w16+4) ^ sw) << 4) + bin)) =
            make_char4((char)r0, (char)r1, (char)r2, (char)r3);
    }
}

// activation pack (attn output): grid rows/8
__global__ __launch_bounds__(256)
void pack_quant(const float* __restrict__ src, uint8_t* __restrict__ dst,
                float* __restrict__ scl)
{
    const int warp = threadIdx.x >> 5, lane = threadIdx.x & 31;
    pack_row(src, dst, scl, blockIdx.x * 8 + warp, lane);
}

// merged pack: activations + ALL weights in one launch. grid 1280 x 8 rows.
// [0,4096) hid->pa  [4096,6144) wq  [6144,7168) wk  [7168,8192) wv  [8192,10240) wo
__global__ __launch_bounds__(256)
void pack_all(const float* __restrict__ hid,
              const float* __restrict__ wq, const float* __restrict__ wk,
              const float* __restrict__ wv, const float* __restrict__ wo,
              uint8_t* __restrict__ pa, uint8_t* __restrict__ pw,
              uint8_t* __restrict__ pwo,
              float* __restrict__ sa, float* __restrict__ sw,
              float* __restrict__ swo)
{
    const int warp = threadIdx.x >> 5, lane = threadIdx.x & 31;
    const int gr = blockIdx.x * 8 + warp;

    const float* src; uint8_t* dst; float* scl; int row;
    if (gr < 4096)      { src = hid; dst = pa;                            scl = sa;        row = gr; }
    else if (gr < 6144) { src = wq;  dst = pw;                            scl = sw;        row = gr - 4096; }
    else if (gr < 7168) { src = wk;  dst = pw + (size_t)2048 * KDIM * 2;  scl = sw + 2048; row = gr - 6144; }
    else if (gr < 8192) { src = wv;  dst = pw + (size_t)3072 * KDIM * 2;  scl = sw + 3072; row = gr - 7168; }
    else                { src = wo;  dst = pwo;                           scl = swo;       row = gr - 8192; }
    pack_row(src, dst, scl, row, lane);
}

// ===========================================================================
// gemm_i8: 3-term int8 mma, 128x128 tile, 3-stage single-sync.
// If Vh != nullptr, CTAs with bn >= 24 (cols 3072+) write fp16 V directly.
// ===========================================================================
__global__ __launch_bounds__(256)
void gemm_i8(const uint8_t* __restrict__ Ap, const uint8_t* __restrict__ Bp,
             const float* __restrict__ sA, const float* __restrict__ sB,
             float* __restrict__ C, int N, __half* __restrict__ Vh)
{
    extern __shared__ uint8_t smi[];
    const uint32_t sb0 = smem_u32(smi);
    const int tid = threadIdx.x, lane = tid & 31, warp = tid >> 5;
    const int wm = warp >> 2, wn = warp & 3;
    const int bn = blockIdx.x, bm = blockIdx.y;

    const uint8_t* Asrc = Ap + (size_t)bm * KC * 16384 + tid * 16;
    const uint8_t* Bsrc = Bp + (size_t)bn * KC * 16384 + tid * 16;

    int acc1[4][4][4] = {}, acc2[4][4][4] = {};

    const int arow = wm * 64 + (lane & 7) + ((lane >> 3) & 1) * 8;
    const int akh  = lane >> 4;
    const int aw   = arow & 7;
    const int brow = wn * 32 + (lane & 7) + (lane >> 4) * 8;
    const int bkh  = (lane >> 3) & 1;
    const int bw   = brow & 7;

#pragma unroll
    for (int pre = 0; pre < 2; pre++) {
        uint32_t d = sb0 + pre * 32768 + tid * 16;
#pragma unroll
        for (int i = 0; i < 4; i++) cp16(d + i * 4096,         Asrc + (size_t)pre * 16384 + i * 4096);
#pragma unroll
        for (int i = 0; i < 4; i++) cp16(d + 16384 + i * 4096, Bsrc + (size_t)pre * 16384 + i * 4096);
        CP_COMMIT();
    }

    for (int kc = 0; kc < KC; kc++) {
        CP_WAIT1();
        __syncthreads();
        if (kc + 2 < KC) {
            int st2 = (kc + 2) % 3;
            uint32_t d = sb0 + st2 * 32768 + tid * 16;
#pragma unroll
            for (int i = 0; i < 4; i++) cp16(d + i * 4096,         Asrc + (size_t)(kc + 2) * 16384 + i * 4096);
#pragma unroll
            for (int i = 0; i < 4; i++) cp16(d + 16384 + i * 4096, Bsrc + (size_t)(kc + 2) * 16384 + i * 4096);
        }
        CP_COMMIT();

        const uint32_t stA = sb0 + (kc % 3) * 32768, stB = stA + 16384;

#pragma unroll
        for (int s = 0; s < 2; s++) {
            uint32_t a1f[4][4], a2f[4][4];
            const int ga = 2 * s + akh;
#pragma unroll
            for (int mi = 0; mi < 4; mi++) {
                uint32_t ad = stA + (uint32_t)(arow + mi * 16) * 128;
                ldsm4(a1f[mi], ad + (uint32_t)(((ga     ^ aw) << 4)));
                ldsm4(a2f[mi], ad + (uint32_t)((((ga+4) ^ aw) << 4)));
            }
            const int gb = 2 * s + bkh;
#pragma unroll
            for (int nj = 0; nj < 2; nj++) {
                uint32_t bd = stB + (uint32_t)(brow + nj * 16) * 128;
                uint32_t b1f[4], b2f[4];
                ldsm4(b1f, bd + (uint32_t)(((gb     ^ bw) << 4)));
                ldsm4(b2f, bd + (uint32_t)((((gb+4) ^ bw) << 4)));
#pragma unroll
                for (int mi = 0; mi < 4; mi++) {
                    mma_i8(acc1[mi][2*nj],   a1f[mi], b1f[0], b1f[1]);
                    mma_i8(acc1[mi][2*nj+1], a1f[mi], b1f[2], b1f[3]);
                    mma_i8(acc2[mi][2*nj],   a1f[mi], b2f[0], b2f[1]);
                    mma_i8(acc2[mi][2*nj+1], a1f[mi], b2f[2], b2f[3]);
                    mma_i8(acc2[mi][2*nj],   a2f[mi], b1f[0], b1f[1]);
                    mma_i8(acc2[mi][2*nj+1], a2f[mi], b1f[2], b1f[3]);
                }
            }
        }
    }

    const int u = lane >> 2, qq = (lane & 3) * 2;
    const float k2 = 0.0078125f;
    const bool isv = (Vh != nullptr) && (bn >= 24);
#pragma unroll
    for (int mi = 0; mi < 4; mi++) {
        int r0 = bm * 128 + wm * 64 + mi * 16 + u;
        float sa0 = sA[r0], sa1 = sA[r0 + 8];
#pragma unroll
        for (int nt = 0; nt < 4; nt++) {
            int c0 = bn * 128 + wn * 32 + nt * 8 + qq;
            float sb0v = sB[c0], sb1v = sB[c0 + 1];
            float d0 = ((float)acc1[mi][nt][0] + (float)acc2[mi][nt][0] * k2) * sa0 * sb0v;
            float d1 = ((float)acc1[mi][nt][1] + (float)acc2[mi][nt][1] * k2) * sa0 * sb1v;
            float d2 = ((float)acc1[mi][nt][2] + (float)acc2[mi][nt][2] * k2) * sa1 * sb0v;
            float d3 = ((float)acc1[mi][nt][3] + (float)acc2[mi][nt][3] * k2) * sa1 * sb1v;
            if (isv) {
                int vc = c0 - 3072;
                *(uint32_t*)(Vh + (size_t)r0 * KVDIM + vc)       = pk2(d0, d1);
                *(uint32_t*)(Vh + (size_t)(r0 + 8) * KVDIM + vc) = pk2(d2, d3);
            } else {
                *(float2*)(C + (size_t)r0 * N + c0)       = make_float2(d0, d1);
                *(float2*)(C + (size_t)(r0 + 8) * N + c0) = make_float2(d2, d3);
            }
        }
    }
}

// ===========================================================================
// norm_rope_cvt: warp-per-head, Q and K only (V handled by gemm epilogue).
// grid (SEQ, 3): y=0,1 Q heads, y=2 K heads.
// ===========================================================================
__global__ __launch_bounds__(256)
void norm_rope_cvt(const float* __restrict__ qkv, __half* __restrict__ qo,
                   __half* __restrict__ ko,
                   const float* __restrict__ cs, const float* __restrict__ sn,
                   const float* __restrict__ qw, const float* __restrict__ kw)
{
    const int s = blockIdx.x, y = blockIdx.y;
    const int warp = threadIdx.x >> 5, lane = threadIdx.x & 31;

    const bool isq = y < 2;
    const int hh = isq ? (y * 8 + warp) : warp;
    const float* w = isq ? qw : kw;
    const float scale = isq ? (float)QSCALE : 1.0f;
    const int d0 = lane * 4;

    float4 x = *(const float4*)(qkv + (size_t)s * QKVN + (isq ? 0 : 2048) + hh * HD + d0);
    float ss = x.x * x.x + x.y * x.y + x.z * x.z + x.w * x.w;
#pragma unroll
    for (int o = 16; o; o >>= 1) ss += __shfl_xor_sync(0xffffffffu, ss, o);
    float r = rsqrtf(ss * (1.0f / 128.0f) + 1e-6f);

    float4 wv = *(const float4*)(w + d0);
    float xn0 = x.x * r * wv.x, xn1 = x.y * r * wv.y;
    float xn2 = x.z * r * wv.z, xn3 = x.w * r * wv.w;

    float p0 = __shfl_xor_sync(0xffffffffu, xn0, 16);
    float p1 = __shfl_xor_sync(0xffffffffu, xn1, 16);
    float p2 = __shfl_xor_sync(0xffffffffu, xn2, 16);
    float p3 = __shfl_xor_sync(0xffffffffu, xn3, 16);
    float sg = (lane < 16) ? -1.0f : 1.0f;

    float4 c4 = *(const float4*)(cs + s * HD + d0);
    float4 s4 = *(const float4*)(sn + s * HD + d0);
    float o0 = (xn0 * c4.x + sg * p0 * s4.x) * scale;
    float o1 = (xn1 * c4.y + sg * p1 * s4.y) * scale;
    float o2 = (xn2 * c4.z + sg * p2 * s4.z) * scale;
    float o3 = (xn3 * c4.w + sg * p3 * s4.w) * scale;

    uint2 pk; pk.x = pk2(o0, o1); pk.y = pk2(o2, o3);
    if (isq) *(uint2*)(qo + (size_t)s * QDIM + hh * HD + d0) = pk;
    else     *(uint2*)(ko + (size_t)s * KVDIM + hh * HD + d0) = pk;
}

// ===========================================================================
// fp16 flash attention, 128-row Q x 128-key KV tiles (unchanged from R14).
// ===========================================================================
__global__ __launch_bounds__(256)
void flash_f16()
{
    extern __shared__ uint8_t smf[];
    const uint32_t sQ = smem_u32(smf);          // 128 rows x 256B = 32KB
    const uint32_t sKV0 = sQ + 32768;           // 3 stages x 64KB (K32+V32)

    const int tid = threadIdx.x, lane = tid & 31, warp = tid >> 5;
    const int qb = gridDim.x - 1 - blockIdx.x;
    const int h = blockIdx.y, kvh = h >> 1;
    const int q2 = lane & 3, u = lane >> 2;
    const uint32_t ONES2 = 0x3C003C00u;

    const uint8_t* Kg0 = (const uint8_t*)(g_kh + (size_t)kvh * HD);
    const uint8_t* Vg0 = (const uint8_t*)(g_vh + (size_t)kvh * HD);
    const int njb = qb + 1;

    {
        const uint8_t* Qg = (const uint8_t*)(g_qh + ((size_t)(qb * 128) * NH + h) * HD);
#pragma unroll
        for (int j = 0; j < 8; j++) {
            int idx = tid + j * 256;
            int row = idx >> 4, g = idx & 15;
            cp16(sQ + row * 256 + ((g ^ (row & 7)) << 4),
                 Qg + (size_t)row * NH * HD * 2 + g * 16);
        }
        CP_COMMIT();
    }
#pragma unroll
    for (int pre = 0; pre < 2; pre++) {
        uint32_t st = sKV0 + pre * 65536;
        const uint8_t* Kg = Kg0 + (size_t)(pre * 128) * NKV * HD * 2;
        const uint8_t* Vg = Vg0 + (size_t)(pre * 128) * NKV * HD * 2;
#pragma unroll
        for (int j = 0; j < 8; j++) {
            int idx = tid + j * 256;
            int row = idx >> 4, g = idx & 15;
            uint32_t off = row * 256 + ((g ^ (row & 7)) << 4);
            size_t gsrc = (size_t)row * NKV * HD * 2 + g * 16;
            cp16(st + off, Kg + gsrc);
            cp16(st + 32768 + off, Vg + gsrc);
        }
        CP_COMMIT();
    }

    CP_WAIT2();
    __syncthreads();

    uint32_t qf[8][4];
    {
        int row = warp * 16 + (lane & 7) + ((lane >> 3) & 1) * 8;
        int go  = lane >> 4;
        uint32_t rb = sQ + row * 256;
        int rw = (row & 7);
#pragma unroll
        for (int ks = 0; ks < 8; ks++)
            ldsm4(qf[ks], rb + (((2 * ks + go) ^ rw) << 4));
    }

    float o[16][4];
#pragma unroll
    for (int i = 0; i < 16; i++)
#pragma unroll
        for (int r = 0; r < 4; r++) o[i][r] = 0.f;
    float m0 = -1e30f, m1 = -1e30f, l0 = 0.f, l1 = 0.f;

    const int kkey = lane & 7;
    const int kgo  = lane >> 3;
    const int vkey = (lane & 7) + ((lane >> 3) & 1) * 8;
    const int vgo  = lane >> 4;

    for (int jb = 0; jb < njb; jb++) {
        CP_WAIT1();
        __syncthreads();

        if (jb + 2 < njb) {
            uint32_t st = sKV0 + ((jb + 2) % 3) * 65536;
            const uint8_t* Kg = Kg0 + (size_t)((jb + 2) * 128) * NKV * HD * 2;
            const uint8_t* Vg = Vg0 + (size_t)((jb + 2) * 128) * NKV * HD * 2;
#pragma unroll
            for (int j = 0; j < 8; j++) {
                int idx = tid + j * 256;
                int row = idx >> 4, g = idx & 15;
                uint32_t off = row * 256 + ((g ^ (row & 7)) << 4);
                size_t gsrc = (size_t)row * NKV * HD * 2 + g * 16;
                cp16(st + off, Kg + gsrc);
                cp16(st + 32768 + off, Vg + gsrc);
            }
        }
        CP_COMMIT();

        const uint32_t sK = sKV0 + (jb % 3) * 65536, sV = sK + 32768;

        float s[16][4];
#pragma unroll
        for (int nt = 0; nt < 16; nt++)
#pragma unroll
            for (int r = 0; r < 4; r++) s[nt][r] = 0.f;

#pragma unroll
        for (int g2 = 0; g2 < 4; g2++) {
#pragma unroll
            for (int nt = 0; nt < 16; nt++) {
                int key = 8 * nt + kkey;
                uint32_t bf[4];
                ldsm4(bf, sK + key * 256 + (((4 * g2 + kgo) ^ (key & 7)) << 4));
                mma_f16(s[nt], qf[2 * g2],     bf[0], bf[1]);
                mma_f16(s[nt], qf[2 * g2 + 1], bf[2], bf[3]);
            }
        }

        if (jb == qb) {
            int r0g = qb * 128 + warp * 16 + u;
            int cb = jb * 128 + q2 * 2;
#pragma unroll
            for (int nt = 0; nt < 16; nt++) {
                int c = cb + nt * 8;
                if (c     > r0g)     s[nt][0] = -1e30f;
                if (c + 1 > r0g)     s[nt][1] = -1e30f;
                if (c     > r0g + 8) s[nt][2] = -1e30f;
                if (c + 1 > r0g + 8) s[nt][3] = -1e30f;
            }
        }

        float mx0 = -1e30f, mx1 = -1e30f;
#pragma unroll
        for (int nt = 0; nt < 16; nt++) {
            mx0 = fmaxf(mx0, fmaxf(s[nt][0], s[nt][1]));
            mx1 = fmaxf(mx1, fmaxf(s[nt][2], s[nt][3]));
        }
        mx0 = fmaxf(mx0, __shfl_xor_sync(0xffffffffu, mx0, 1));
        mx0 = fmaxf(mx0, __shfl_xor_sync(0xffffffffu, mx0, 2));
        mx1 = fmaxf(mx1, __shfl_xor_sync(0xffffffffu, mx1, 1));
        mx1 = fmaxf(mx1, __shfl_xor_sync(0xffffffffu, mx1, 2));
        float mn0 = fmaxf(m0, mx0), mn1 = fmaxf(m1, mx1);
        float cf0 = exp2s(m0 - mn0), cf1 = exp2s(m1 - mn1);
        m0 = mn0; m1 = mn1;

        uint32_t pf[8][4];
#pragma unroll
        for (int kt = 0; kt < 8; kt++) {
            pf[kt][0] = exp2h2(s[2*kt][0]   - mn0, s[2*kt][1]   - mn0);
            pf[kt][1] = exp2h2(s[2*kt][2]   - mn1, s[2*kt][3]   - mn1);
            pf[kt][2] = exp2h2(s[2*kt+1][0] - mn0, s[2*kt+1][1] - mn0);
            pf[kt][3] = exp2h2(s[2*kt+1][2] - mn1, s[2*kt+1][3] - mn1);
        }

        float rsd[4] = {0.f, 0.f, 0.f, 0.f};
#pragma unroll
        for (int kt = 0; kt < 8; kt++)
            mma_f16(rsd, pf[kt], ONES2, ONES2);

        l0 = l0 * cf0 + rsd[0];
        l1 = l1 * cf1 + rsd[2];
#pragma unroll
        for (int nt2 = 0; nt2 < 16; nt2++) {
            o[nt2][0] *= cf0; o[nt2][1] *= cf0;
            o[nt2][2] *= cf1; o[nt2][3] *= cf1;
        }

#pragma unroll
        for (int ks = 0; ks < 8; ks++) {
#pragma unroll
            for (int np = 0; np < 8; np++) {
                int key = 16 * ks + vkey;
                uint32_t vf[4];
                ldsm4t(vf, sV + key * 256 + (((2 * np + vgo) ^ (key & 7)) << 4));
                mma_f16(o[2 * np],     pf[ks], vf[0], vf[1]);
                mma_f16(o[2 * np + 1], pf[ks], vf[2], vf[3]);
            }
        }
    }

    float r0i = 1.f / l0, r1i = 1.f / l1;
    int grow = qb * 128 + warp * 16 + u;
#pragma unroll
    for (int nt2 = 0; nt2 < 16; nt2++) {
        int col = h * HD + nt2 * 8 + q2 * 2;
        *(float2*)(g_attn + (size_t)grow * QDIM + col) =
            make_float2(o[nt2][0] * r0i, o[nt2][1] * r0i);
        *(float2*)(g_attn + (size_t)(grow + 8) * QDIM + col) =
            make_float2(o[nt2][2] * r1i, o[nt2][3] * r1i);
    }
}

// ===========================================================================
extern "C" void kernel_launch(void* const* d_in, const int* in_sizes, int n_in,
                              void* d_out, int out_size)
{
    const float* hid  = (const float*)d_in[0];
    const float* cosp = (const float*)d_in[1];
    const float* sinp = (const float*)d_in[2];
    const float* wq   = (const float*)d_in[3];
    const float* wk   = (const float*)d_in[4];
    const float* wv   = (const float*)d_in[5];
    const float* wo   = (const float*)d_in[6];
    const float* qw   = (const float*)d_in[7];
    const float* kw   = (const float*)d_in[8];
    float* out = (float*)d_out;

    float *qkv, *ab;
    cudaGetSymbolAddress((void**)&qkv, g_qkv);
    cudaGetSymbolAddress((void**)&ab, g_attn);
    __half *qh, *kh, *vh;
    cudaGetSymbolAddress((void**)&qh, g_qh);
    cudaGetSymbolAddress((void**)&kh, g_kh);
    cudaGetSymbolAddress((void**)&vh, g_vh);
    uint8_t *pa, *pw, *pwo;
    cudaGetSymbolAddress((void**)&pa,  g_pa);
    cudaGetSymbolAddress((void**)&pw,  g_pw);
    cudaGetSymbolAddress((void**)&pwo, g_pwo);
    float *sa, *sw, *swo;
    cudaGetSymbolAddress((void**)&sa,  g_sa);
    cudaGetSymbolAddress((void**)&sw,  g_sw);
    cudaGetSymbolAddress((void**)&swo, g_swo);

    const int GEMM_SMEM  = 98304;
    const int FLASH_SMEM = 229376;   // Q 32KB + 3 x (K32+V32)
    cudaFuncSetAttribute(gemm_i8, cudaFuncAttributeMaxDynamicSharedMemorySize, GEMM_SMEM);
    cudaFuncSetAttribute(flash_f16, cudaFuncAttributeMaxDynamicSharedMemorySize, FLASH_SMEM);

    // launch 1: all packs (activations + weights)
    pack_all<<<1280, 256>>>(hid, wq, wk, wv, wo, pa, pw, pwo, sa, sw, swo);

    // launch 2: merged QKV projection; V columns written fp16 directly
    gemm_i8<<<dim3(QKVN / 128, SEQ / 128), 256, GEMM_SMEM>>>(pa, pw, sa, sw, qkv, QKVN, vh);

    // launch 3: Q/K norm + RoPE
    norm_rope_cvt<<<dim3(SEQ, 3), 256>>>(qkv, qh, kh, cosp, sinp, qw, kw);

    // launch 4: flash attention (ncu capture slot)
    flash_f16<<<dim3(SEQ / 128, NH), 256, FLASH_SMEM>>>();

    // launch 5-6: output projection
    pack_quant<<<SEQ / 8, 256>>>(ab, pa, sa);
    gemm_i8<<<dim3(HID / 128, SEQ / 128), 256, GEMM_SMEM>>>(pa, pwo, sa, swo, out, HID, nullptr);
}

// round 16
// speedup vs baseline: 9.7091x; 1.0252x over previous
#include <cuda_runtime.h>
#include <cuda_fp16.h>
#include <cstdint>

#define SEQ   4096
#define HID   2048
#define NH    16
#define NKV   8
#define HD    128
#define QDIM  (NH*HD)    // 2048
#define KVDIM (NKV*HD)   // 1024
#define KDIM  2048
#define KC    (KDIM/64)  // 32
#define QKVN  4096
#define QSCALE (0.08838834764831845f * 1.4426950408889634f)

// fp32 intermediates
__device__ float g_qkv[(size_t)SEQ * QKVN];   // V columns unused (fp16 direct)
__device__ float g_attn[(size_t)SEQ * QDIM];

// fp16 flash operands
__device__ __half g_qh[SEQ * QDIM];
__device__ __half g_kh[SEQ * KVDIM];
__device__ __half g_vh[SEQ * KVDIM];

// int8 2-term packed operands + per-row scales
__device__ uint8_t g_pa[(size_t)SEQ * KDIM * 2];
__device__ uint8_t g_pw[(size_t)QKVN * KDIM * 2];
__device__ uint8_t g_pwo[(size_t)HID * KDIM * 2];
__device__ float g_sa[SEQ];
__device__ float g_sw[QKVN], g_swo[HID];

__device__ __forceinline__ void mma_i8(int* d,
    const uint32_t* a, uint32_t b0, uint32_t b1)
{
    asm volatile(
        "mma.sync.aligned.m16n8k32.row.col.s32.s8.s8.s32 "
        "{%0,%1,%2,%3}, {%4,%5,%6,%7}, {%8,%9}, {%0,%1,%2,%3};\n"
        : "+r"(d[0]), "+r"(d[1]), "+r"(d[2]), "+r"(d[3])
        : "r"(a[0]), "r"(a[1]), "r"(a[2]), "r"(a[3]), "r"(b0), "r"(b1));
}
__device__ __forceinline__ void mma_f16(float* d,
    const uint32_t* a, uint32_t b0, uint32_t b1)
{
    asm volatile(
        "mma.sync.aligned.m16n8k16.row.col.f32.f16.f16.f32 "
        "{%0,%1,%2,%3}, {%4,%5,%6,%7}, {%8,%9}, {%0,%1,%2,%3};\n"
        : "+f"(d[0]), "+f"(d[1]), "+f"(d[2]), "+f"(d[3])
        : "r"(a[0]), "r"(a[1]), "r"(a[2]), "r"(a[3]), "r"(b0), "r"(b1));
}
__device__ __forceinline__ void ldsm4(uint32_t* r, uint32_t addr) {
    asm volatile("ldmatrix.sync.aligned.m8n8.x4.shared.b16 {%0,%1,%2,%3}, [%4];"
                 : "=r"(r[0]), "=r"(r[1]), "=r"(r[2]), "=r"(r[3]) : "r"(addr));
}
__device__ __forceinline__ void ldsm4t(uint32_t* r, uint32_t addr) {
    asm volatile("ldmatrix.sync.aligned.m8n8.x4.trans.shared.b16 {%0,%1,%2,%3}, [%4];"
                 : "=r"(r[0]), "=r"(r[1]), "=r"(r[2]), "=r"(r[3]) : "r"(addr));
}
__device__ __forceinline__ uint32_t smem_u32(const void* p) {
    uint32_t a;
    asm("{ .reg .u64 t; cvta.to.shared.u64 t, %1; cvt.u32.u64 %0, t; }" : "=r"(a) : "l"(p));
    return a;
}
__device__ __forceinline__ void cp16(uint32_t d, const void* g) {
    asm volatile("cp.async.cg.shared.global [%0], [%1], 16;" :: "r"(d), "l"(g));
}
#define CP_COMMIT() asm volatile("cp.async.commit_group;")
#define CP_WAIT2()  asm volatile("cp.async.wait_group 2;")
#define CP_WAIT1()  asm volatile("cp.async.wait_group 1;")

__device__ __forceinline__ uint32_t exp2h2(float a, float b) {
    __half2 h = __floats2half2_rn(a, b);
    uint32_t x = *(uint32_t*)&h, r;
    asm("ex2.approx.f16x2 %0, %1;" : "=r"(r) : "r"(x));
    return r;
}
__device__ __forceinline__ float exp2s(float x) {
    float r; asm("ex2.approx.f32 %0, %1;" : "=f"(r) : "f"(x)); return r;
}
__device__ __forceinline__ uint32_t pk2(float lo, float hi) {
    __half2 t = __floats2half2_rn(lo, hi);
    return *(uint32_t*)&t;
}

// ===========================================================================
// pack_row: fp32 row [KDIM] -> 2-term int8, tile-packed+swizzled (warp-wide).
// ===========================================================================
__device__ __forceinline__ void pack_row(const float* __restrict__ src,
                                         uint8_t* __restrict__ dst,
                                         float* __restrict__ scl,
                                         int row, int lane)
{
    const float* s = src + (size_t)row * KDIM;

    float4 v[16];
    float mx = 0.f;
#pragma unroll
    for (int j = 0; j < 16; j++) {
        v[j] = *(const float4*)(s + lane * 4 + j * 128);
        mx = fmaxf(mx, fmaxf(fmaxf(fabsf(v[j].x), fabsf(v[j].y)),
                             fmaxf(fabsf(v[j].z), fabsf(v[j].w))));
    }
#pragma unroll
    for (int o = 16; o; o >>= 1) mx = fmaxf(mx, __shfl_xor_sync(0xffffffffu, mx, o));

    const float s1   = mx * (1.f / 127.f);
    const float inv1 = mx > 0.f ? 127.f / mx : 0.f;
    const float inv2 = inv1 * 128.f;
    if (lane == 0) scl[row] = s1;

    const int rt = row >> 7, rr = row & 127, sw = rr & 7;
    uint8_t* tbase0 = dst + ((size_t)rt * KC) * 16384 + rr * 128;

#pragma unroll
    for (int j = 0; j < 16; j++) {
        int k = lane * 4 + j * 128;
        int c = k >> 6, w16 = (k >> 4) & 3, bin = k & 15;
        float4 x = v[j];
        int q0 = __float2int_rn(x.x * inv1), q1 = __float2int_rn(x.y * inv1);
        int q2 = __float2int_rn(x.z * inv1), q3 = __float2int_rn(x.w * inv1);
        int r0 = __float2int_rn((x.x - q0 * s1) * inv2);
        int r1 = __float2int_rn((x.y - q1 * s1) * inv2);
        int r2 = __float2int_rn((x.z - q2 * s1) * inv2);
        int r3 = __float2int_rn((x.w - q3 * s1) * inv2);
        uint8_t* tb = tbase0 + c * 16384;
        *(char4*)(tb + (((w16     ^ sw) << 4) + bin)) =
            make_char4((char)q0, (char)q1, (char)q2, (char)q3);
        *(char4*)(tb + ((((w16+4) ^ sw) << 4) + bin)) =
            make_char4((char)r0, (char)r1, (char)r2, (char)r3);
    }
}

__global__ __launch_bounds__(256)
void pack_quant(const float* __restrict__ src, uint8_t* __restrict__ dst,
                float* __restrict__ scl)
{
    const int warp = threadIdx.x >> 5, lane = threadIdx.x & 31;
    pack_row(src, dst, scl, blockIdx.x * 8 + warp, lane);
}

__global__ __launch_bounds__(256)
void pack_all(const float* __restrict__ hid,
              const float* __restrict__ wq, const float* __restrict__ wk,
              const float* __restrict__ wv, const float* __restrict__ wo,
              uint8_t* __restrict__ pa, uint8_t* __restrict__ pw,
              uint8_t* __restrict__ pwo,
              float* __restrict__ sa, float* __restrict__ sw,
              float* __restrict__ swo)
{
    const int warp = threadIdx.x >> 5, lane = threadIdx.x & 31;
    const int gr = blockIdx.x * 8 + warp;

    const float* src; uint8_t* dst; float* scl; int row;
    if (gr < 4096)      { src = hid; dst = pa;                            scl = sa;        row = gr; }
    else if (gr < 6144) { src = wq;  dst = pw;                            scl = sw;        row = gr - 4096; }
    else if (gr < 7168) { src = wk;  dst = pw + (size_t)2048 * KDIM * 2;  scl = sw + 2048; row = gr - 6144; }
    else if (gr < 8192) { src = wv;  dst = pw + (size_t)3072 * KDIM * 2;  scl = sw + 3072; row = gr - 7168; }
    else                { src = wo;  dst = pwo;                           scl = swo;       row = gr - 8192; }
    pack_row(src, dst, scl, row, lane);
}

// ===========================================================================
// gemm_i8 (unchanged, passing): 3-term int8 mma, 128x128 tile, 3-stage.
// If Vh != nullptr, CTAs with bn >= 24 write fp16 V directly.
// ===========================================================================
__global__ __launch_bounds__(256)
void gemm_i8(const uint8_t* __restrict__ Ap, const uint8_t* __restrict__ Bp,
             const float* __restrict__ sA, const float* __restrict__ sB,
             float* __restrict__ C, int N, __half* __restrict__ Vh)
{
    extern __shared__ uint8_t smi[];
    const uint32_t sb0 = smem_u32(smi);
    const int tid = threadIdx.x, lane = tid & 31, warp = tid >> 5;
    const int wm = warp >> 2, wn = warp & 3;
    const int bn = blockIdx.x, bm = blockIdx.y;

    const uint8_t* Asrc = Ap + (size_t)bm * KC * 16384 + tid * 16;
    const uint8_t* Bsrc = Bp + (size_t)bn * KC * 16384 + tid * 16;

    int acc1[4][4][4] = {}, acc2[4][4][4] = {};

    const int arow = wm * 64 + (lane & 7) + ((lane >> 3) & 1) * 8;
    const int akh  = lane >> 4;
    const int aw   = arow & 7;
    const int brow = wn * 32 + (lane & 7) + (lane >> 4) * 8;
    const int bkh  = (lane >> 3) & 1;
    const int bw   = brow & 7;

#pragma unroll
    for (int pre = 0; pre < 2; pre++) {
        uint32_t d = sb0 + pre * 32768 + tid * 16;
#pragma unroll
        for (int i = 0; i < 4; i++) cp16(d + i * 4096,         Asrc + (size_t)pre * 16384 + i * 4096);
#pragma unroll
        for (int i = 0; i < 4; i++) cp16(d + 16384 + i * 4096, Bsrc + (size_t)pre * 16384 + i * 4096);
        CP_COMMIT();
    }

    for (int kc = 0; kc < KC; kc++) {
        CP_WAIT1();
        __syncthreads();
        if (kc + 2 < KC) {
            int st2 = (kc + 2) % 3;
            uint32_t d = sb0 + st2 * 32768 + tid * 16;
#pragma unroll
            for (int i = 0; i < 4; i++) cp16(d + i * 4096,         Asrc + (size_t)(kc + 2) * 16384 + i * 4096);
#pragma unroll
            for (int i = 0; i < 4; i++) cp16(d + 16384 + i * 4096, Bsrc + (size_t)(kc + 2) * 16384 + i * 4096);
        }
        CP_COMMIT();

        const uint32_t stA = sb0 + (kc % 3) * 32768, stB = stA + 16384;

#pragma unroll
        for (int s = 0; s < 2; s++) {
            uint32_t a1f[4][4], a2f[4][4];
            const int ga = 2 * s + akh;
#pragma unroll
            for (int mi = 0; mi < 4; mi++) {
                uint32_t ad = stA + (uint32_t)(arow + mi * 16) * 128;
                ldsm4(a1f[mi], ad + (uint32_t)(((ga     ^ aw) << 4)));
                ldsm4(a2f[mi], ad + (uint32_t)((((ga+4) ^ aw) << 4)));
            }
            const int gb = 2 * s + bkh;
#pragma unroll
            for (int nj = 0; nj < 2; nj++) {
                uint32_t bd = stB + (uint32_t)(brow + nj * 16) * 128;
                uint32_t b1f[4], b2f[4];
                ldsm4(b1f, bd + (uint32_t)(((gb     ^ bw) << 4)));
                ldsm4(b2f, bd + (uint32_t)((((gb+4) ^ bw) << 4)));
#pragma unroll
                for (int mi = 0; mi < 4; mi++) {
                    mma_i8(acc1[mi][2*nj],   a1f[mi], b1f[0], b1f[1]);
                    mma_i8(acc1[mi][2*nj+1], a1f[mi], b1f[2], b1f[3]);
                    mma_i8(acc2[mi][2*nj],   a1f[mi], b2f[0], b2f[1]);
                    mma_i8(acc2[mi][2*nj+1], a1f[mi], b2f[2], b2f[3]);
                    mma_i8(acc2[mi][2*nj],   a2f[mi], b1f[0], b1f[1]);
                    mma_i8(acc2[mi][2*nj+1], a2f[mi], b1f[2], b1f[3]);
                }
            }
        }
    }

    const int u = lane >> 2, qq = (lane & 3) * 2;
    const float k2 = 0.0078125f;
    const bool isv = (Vh != nullptr) && (bn >= 24);
#pragma unroll
    for (int mi = 0; mi < 4; mi++) {
        int r0 = bm * 128 + wm * 64 + mi * 16 + u;
        float sa0 = sA[r0], sa1 = sA[r0 + 8];
#pragma unroll
        for (int nt = 0; nt < 4; nt++) {
            int c0 = bn * 128 + wn * 32 + nt * 8 + qq;
            float sb0v = sB[c0], sb1v = sB[c0 + 1];
            float d0 = ((float)acc1[mi][nt][0] + (float)acc2[mi][nt][0] * k2) * sa0 * sb0v;
            float d1 = ((float)acc1[mi][nt][1] + (float)acc2[mi][nt][1] * k2) * sa0 * sb1v;
            float d2 = ((float)acc1[mi][nt][2] + (float)acc2[mi][nt][2] * k2) * sa1 * sb0v;
            float d3 = ((float)acc1[mi][nt][3] + (float)acc2[mi][nt][3] * k2) * sa1 * sb1v;
            if (isv) {
                int vc = c0 - 3072;
                *(uint32_t*)(Vh + (size_t)r0 * KVDIM + vc)       = pk2(d0, d1);
                *(uint32_t*)(Vh + (size_t)(r0 + 8) * KVDIM + vc) = pk2(d2, d3);
            } else {
                *(float2*)(C + (size_t)r0 * N + c0)       = make_float2(d0, d1);
                *(float2*)(C + (size_t)(r0 + 8) * N + c0) = make_float2(d2, d3);
            }
        }
    }
}

// ===========================================================================
// norm_rope_cvt: warp-per-head, Q and K only (unchanged, passing).
// ===========================================================================
__global__ __launch_bounds__(256)
void norm_rope_cvt(const float* __restrict__ qkv, __half* __restrict__ qo,
                   __half* __restrict__ ko,
                   const float* __restrict__ cs, const float* __restrict__ sn,
                   const float* __restrict__ qw, const float* __restrict__ kw)
{
    const int s = blockIdx.x, y = blockIdx.y;
    const int warp = threadIdx.x >> 5, lane = threadIdx.x & 31;

    const bool isq = y < 2;
    const int hh = isq ? (y * 8 + warp) : warp;
    const float* w = isq ? qw : kw;
    const float scale = isq ? (float)QSCALE : 1.0f;
    const int d0 = lane * 4;

    float4 x = *(const float4*)(qkv + (size_t)s * QKVN + (isq ? 0 : 2048) + hh * HD + d0);
    float ss = x.x * x.x + x.y * x.y + x.z * x.z + x.w * x.w;
#pragma unroll
    for (int o = 16; o; o >>= 1) ss += __shfl_xor_sync(0xffffffffu, ss, o);
    float r = rsqrtf(ss * (1.0f / 128.0f) + 1e-6f);

    float4 wv = *(const float4*)(w + d0);
    float xn0 = x.x * r * wv.x, xn1 = x.y * r * wv.y;
    float xn2 = x.z * r * wv.z, xn3 = x.w * r * wv.w;

    float p0 = __shfl_xor_sync(0xffffffffu, xn0, 16);
    float p1 = __shfl_xor_sync(0xffffffffu, xn1, 16);
    float p2 = __shfl_xor_sync(0xffffffffu, xn2, 16);
    float p3 = __shfl_xor_sync(0xffffffffu, xn3, 16);
    float sg = (lane < 16) ? -1.0f : 1.0f;

    float4 c4 = *(const float4*)(cs + s * HD + d0);
    float4 s4 = *(const float4*)(sn + s * HD + d0);
    float o0 = (xn0 * c4.x + sg * p0 * s4.x) * scale;
    float o1 = (xn1 * c4.y + sg * p1 * s4.y) * scale;
    float o2 = (xn2 * c4.z + sg * p2 * s4.z) * scale;
    float o3 = (xn3 * c4.w + sg * p3 * s4.w) * scale;

    uint2 pk; pk.x = pk2(o0, o1); pk.y = pk2(o2, o3);
    if (isq) *(uint2*)(qo + (size_t)s * QDIM + hh * HD + d0) = pk;
    else     *(uint2*)(ko + (size_t)s * KVDIM + hh * HD + d0) = pk;
}

// ===========================================================================
// fp16 flash attention: 64-row Q tiles, 4 warps (128 thr), 64-key KV tiles,
// 3-stage pipeline, 1 sync/iter, distance-2 prefetch.
// smem = Q 16KB + 3 x 32KB = 112KB -> TWO CTAs PER SM (latency hiding).
// ===========================================================================
__global__ __launch_bounds__(128, 2)
void flash_f16()
{
    extern __shared__ uint8_t smf[];
    const uint32_t sQ = smem_u32(smf);          // 64 rows x 256B = 16KB
    const uint32_t sKV0 = sQ + 16384;           // 3 stages x 32KB (K16+V16)

    const int tid = threadIdx.x, lane = tid & 31, warp = tid >> 5;
    const int qb = gridDim.x - 1 - blockIdx.x;
    const int h = blockIdx.y, kvh = h >> 1;
    const int q2 = lane & 3, u = lane >> 2;
    const uint32_t ONES2 = 0x3C003C00u;

    const uint8_t* Kg0 = (const uint8_t*)(g_kh + (size_t)kvh * HD);
    const uint8_t* Vg0 = (const uint8_t*)(g_vh + (size_t)kvh * HD);
    const int njb = qb + 1;

    {
        const uint8_t* Qg = (const uint8_t*)(g_qh + ((size_t)(qb * 64) * NH + h) * HD);
#pragma unroll
        for (int j = 0; j < 8; j++) {
            int idx = tid + j * 128;
            int row = idx >> 4, g = idx & 15;
            cp16(sQ + row * 256 + ((g ^ (row & 7)) << 4),
                 Qg + (size_t)row * NH * HD * 2 + g * 16);
        }
        CP_COMMIT();
    }
#pragma unroll
    for (int pre = 0; pre < 2; pre++) {   // tiles 0,1 (tile 1 in-bounds for all qb)
        uint32_t st = sKV0 + pre * 32768;
        const uint8_t* Kg = Kg0 + (size_t)(pre * 64) * NKV * HD * 2;
        const uint8_t* Vg = Vg0 + (size_t)(pre * 64) * NKV * HD * 2;
#pragma unroll
        for (int j = 0; j < 8; j++) {
            int idx = tid + j * 128;
            int row = idx >> 4, g = idx & 15;
            uint32_t off = row * 256 + ((g ^ (row & 7)) << 4);
            size_t gsrc = (size_t)row * NKV * HD * 2 + g * 16;
            cp16(st + off, Kg + gsrc);
            cp16(st + 16384 + off, Vg + gsrc);
        }
        CP_COMMIT();
    }

    CP_WAIT2();
    __syncthreads();

    uint32_t qf[8][4];
    {
        int row = warp * 16 + (lane & 7) + ((lane >> 3) & 1) * 8;
        int go  = lane >> 4;
        uint32_t rb = sQ + row * 256;
        int rw = (row & 7);
#pragma unroll
        for (int ks = 0; ks < 8; ks++)
            ldsm4(qf[ks], rb + (((2 * ks + go) ^ rw) << 4));
    }

    float o[16][4];
#pragma unroll
    for (int i = 0; i < 16; i++)
#pragma unroll
        for (int r = 0; r < 4; r++) o[i][r] = 0.f;
    float m0 = -1e30f, m1 = -1e30f, l0 = 0.f, l1 = 0.f;

    const int kkey = lane & 7;
    const int kgo  = lane >> 3;
    const int vkey = (lane & 7) + ((lane >> 3) & 1) * 8;
    const int vgo  = lane >> 4;

    for (int jb = 0; jb < njb; jb++) {
        CP_WAIT1();
        __syncthreads();

        if (jb + 2 < njb) {
            uint32_t st = sKV0 + ((jb + 2) % 3) * 32768;
            const uint8_t* Kg = Kg0 + (size_t)((jb + 2) * 64) * NKV * HD * 2;
            const uint8_t* Vg = Vg0 + (size_t)((jb + 2) * 64) * NKV * HD * 2;
#pragma unroll
            for (int j = 0; j < 8; j++) {
                int idx = tid + j * 128;
                int row = idx >> 4, g = idx & 15;
                uint32_t off = row * 256 + ((g ^ (row & 7)) << 4);
                size_t gsrc = (size_t)row * NKV * HD * 2 + g * 16;
                cp16(st + off, Kg + gsrc);
                cp16(st + 16384 + off, Vg + gsrc);
            }
        }
        CP_COMMIT();

        const uint32_t sK = sKV0 + (jb % 3) * 32768, sV = sK + 16384;

        // S = Q K^T over 64 keys
        float s[8][4];
#pragma unroll
        for (int nt = 0; nt < 8; nt++)
#pragma unroll
            for (int r = 0; r < 4; r++) s[nt][r] = 0.f;

#pragma unroll
        for (int g2 = 0; g2 < 4; g2++) {
#pragma unroll
            for (int nt = 0; nt < 8; nt++) {
                int key = 8 * nt + kkey;
                uint32_t bf[4];
                ldsm4(bf, sK + key * 256 + (((4 * g2 + kgo) ^ (key & 7)) << 4));
                mma_f16(s[nt], qf[2 * g2],     bf[0], bf[1]);
                mma_f16(s[nt], qf[2 * g2 + 1], bf[2], bf[3]);
            }
        }

        if (jb == qb) {   // diagonal tile
            int r0g = qb * 64 + warp * 16 + u;
            int cb = jb * 64 + q2 * 2;
#pragma unroll
            for (int nt = 0; nt < 8; nt++) {
                int c = cb + nt * 8;
                if (c     > r0g)     s[nt][0] = -1e30f;
                if (c + 1 > r0g)     s[nt][1] = -1e30f;
                if (c     > r0g + 8) s[nt][2] = -1e30f;
                if (c + 1 > r0g + 8) s[nt][3] = -1e30f;
            }
        }

        // online softmax (base-2)
        float mx0 = -1e30f, mx1 = -1e30f;
#pragma unroll
        for (int nt = 0; nt < 8; nt++) {
            mx0 = fmaxf(mx0, fmaxf(s[nt][0], s[nt][1]));
            mx1 = fmaxf(mx1, fmaxf(s[nt][2], s[nt][3]));
        }
        mx0 = fmaxf(mx0, __shfl_xor_sync(0xffffffffu, mx0, 1));
        mx0 = fmaxf(mx0, __shfl_xor_sync(0xffffffffu, mx0, 2));
        mx1 = fmaxf(mx1, __shfl_xor_sync(0xffffffffu, mx1, 1));
        mx1 = fmaxf(mx1, __shfl_xor_sync(0xffffffffu, mx1, 2));
        float mn0 = fmaxf(m0, mx0), mn1 = fmaxf(m1, mx1);
        float cf0 = exp2s(m0 - mn0), cf1 = exp2s(m1 - mn1);
        m0 = mn0; m1 = mn1;

        uint32_t pf[4][4];
#pragma unroll
        for (int kt = 0; kt < 4; kt++) {
            pf[kt][0] = exp2h2(s[2*kt][0]   - mn0, s[2*kt][1]   - mn0);
            pf[kt][1] = exp2h2(s[2*kt][2]   - mn1, s[2*kt][3]   - mn1);
            pf[kt][2] = exp2h2(s[2*kt+1][0] - mn0, s[2*kt+1][1] - mn0);
            pf[kt][3] = exp2h2(s[2*kt+1][2] - mn1, s[2*kt+1][3] - mn1);
        }

        float rsd[4] = {0.f, 0.f, 0.f, 0.f};
#pragma unroll
        for (int kt = 0; kt < 4; kt++)
            mma_f16(rsd, pf[kt], ONES2, ONES2);

        l0 = l0 * cf0 + rsd[0];
        l1 = l1 * cf1 + rsd[2];
#pragma unroll
        for (int nt2 = 0; nt2 < 16; nt2++) {
            o[nt2][0] *= cf0; o[nt2][1] *= cf0;
            o[nt2][2] *= cf1; o[nt2][3] *= cf1;
        }

        // O += P V over 64 keys
#pragma unroll
        for (int ks = 0; ks < 4; ks++) {
#pragma unroll
            for (int np = 0; np < 8; np++) {
                int key = 16 * ks + vkey;
                uint32_t vf[4];
                ldsm4t(vf, sV + key * 256 + (((2 * np + vgo) ^ (key & 7)) << 4));
                mma_f16(o[2 * np],     pf[ks], vf[0], vf[1]);
                mma_f16(o[2 * np + 1], pf[ks], vf[2], vf[3]);
            }
        }
    }

    float r0i = 1.f / l0, r1i = 1.f / l1;
    int grow = qb * 64 + warp * 16 + u;
#pragma unroll
    for (int nt2 = 0; nt2 < 16; nt2++) {
        int col = h * HD + nt2 * 8 + q2 * 2;
        *(float2*)(g_attn + (size_t)grow * QDIM + col) =
            make_float2(o[nt2][0] * r0i, o[nt2][1] * r0i);
        *(float2*)(g_attn + (size_t)(grow + 8) * QDIM + col) =
            make_float2(o[nt2][2] * r1i, o[nt2][3] * r1i);
    }
}

// ===========================================================================
extern "C" void kernel_launch(void* const* d_in, const int* in_sizes, int n_in,
                              void* d_out, int out_size)
{
    const float* hid  = (const float*)d_in[0];
    const float* cosp = (const float*)d_in[1];
    const float* sinp = (const float*)d_in[2];
    const float* wq   = (const float*)d_in[3];
    const float* wk   = (const float*)d_in[4];
    const float* wv   = (const float*)d_in[5];
    const float* wo   = (const float*)d_in[6];
    const float* qw   = (const float*)d_in[7];
    const float* kw   = (const float*)d_in[8];
    float* out = (float*)d_out;

    float *qkv, *ab;
    cudaGetSymbolAddress((void**)&qkv, g_qkv);
    cudaGetSymbolAddress((void**)&ab, g_attn);
    __half *qh, *kh, *vh;
    cudaGetSymbolAddress((void**)&qh, g_qh);
    cudaGetSymbolAddress((void**)&kh, g_kh);
    cudaGetSymbolAddress((void**)&vh, g_vh);
    uint8_t *pa, *pw, *pwo;
    cudaGetSymbolAddress((void**)&pa,  g_pa);
    cudaGetSymbolAddress((void**)&pw,  g_pw);
    cudaGetSymbolAddress((void**)&pwo, g_pwo);
    float *sa, *sw, *swo;
    cudaGetSymbolAddress((void**)&sa,  g_sa);
    cudaGetSymbolAddress((void**)&sw,  g_sw);
    cudaGetSymbolAddress((void**)&swo, g_swo);

    const int GEMM_SMEM  = 98304;
    const int FLASH_SMEM = 114688;   // Q 16KB + 3 x 32KB -> 2 CTAs/SM
    cudaFuncSetAttribute(gemm_i8, cudaFuncAttributeMaxDynamicSharedMemorySize, GEMM_SMEM);
    cudaFuncSetAttribute(flash_f16, cudaFuncAttributeMaxDynamicSharedMemorySize, FLASH_SMEM);

    // launch 1: all packs
    pack_all<<<1280, 256>>>(hid, wq, wk, wv, wo, pa, pw, pwo, sa, sw, swo);

    // launch 2: merged QKV projection (V written fp16 directly)
    gemm_i8<<<dim3(QKVN / 128, SEQ / 128), 256, GEMM_SMEM>>>(pa, pw, sa, sw, qkv, QKVN, vh);

    // launch 3: Q/K norm + RoPE
    norm_rope_cvt<<<dim3(SEQ, 3), 256>>>(qkv, qh, kh, cosp, sinp, qw, kw);

    // launch 4: flash attention (2 CTAs/SM)
    flash_f16<<<dim3(SEQ / 64, NH), 128, FLASH_SMEM>>>();

    // launch 5-6: output projection
    pack_quant<<<SEQ / 8, 256>>>(ab, pa, sa);
    gemm_i8<<<dim3(HID / 128, SEQ / 128), 256, GEMM_SMEM>>>(pa, pwo, sa, swo, out, HID, nullptr);
}